// round 2
// baseline (speedup 1.0000x reference)
#include <cuda_runtime.h>
#include <cstdint>

// ---------------- problem dims (compile-time) ----------------
#define BSZ   2
#define QL    1024
#define HID   4096
#define NH    32
#define NKV   8
#define HD    128
#define NBLK  512      // total storage blocks
#define BLKSZ 16       // rows per storage block
#define SEQ   4096     // CTX_BLOCKS * BLOCK
#define MROWS (BSZ*QL) // 2048

// ---------------- device scratch (no cudaMalloc allowed) ----------------
__device__ float g_qraw[(size_t)MROWS * NH * HD];    // 2048 x 4096
__device__ float g_kraw[(size_t)MROWS * NKV * HD];   // 2048 x 1024
__device__ float g_vraw[(size_t)MROWS * NKV * HD];   // 2048 x 1024
__device__ float g_q   [(size_t)BSZ * NH * QL * HD]; // rope'd Q, [b,h,t,d]
__device__ float g_kst [(size_t)NBLK * NKV * BLKSZ * HD]; // writable k_storage copy
__device__ float g_vst [(size_t)NBLK * NKV * BLKSZ * HD];
__device__ float g_attn[(size_t)MROWS * NH * HD];    // attention out, [b,t,h,d] = 2048 x 4096

// ---------------- SGEMM: C[M,N] = A[M,K] * B[N,K]^T (both row-major) ----------------
__global__ __launch_bounds__(256) void sgemm_nt(const float* __restrict__ A,
                                                const float* __restrict__ B,
                                                float* __restrict__ C,
                                                int M, int N, int K)
{
    __shared__ float As[16][128];
    __shared__ float Bs[16][128];
    const int tid = threadIdx.x;
    const int bm = blockIdx.y * 128;
    const int bn = blockIdx.x * 128;
    const int ty = tid >> 4, tx = tid & 15;

    float acc[8][8];
#pragma unroll
    for (int i = 0; i < 8; i++)
#pragma unroll
        for (int j = 0; j < 8; j++) acc[i][j] = 0.f;

    const float* Ab = A + (size_t)bm * K;
    const float* Bb = B + (size_t)bn * K;

    for (int k0 = 0; k0 < K; k0 += 16) {
#pragma unroll
        for (int p = 0; p < 2; p++) {
            int idx = tid + p * 256;       // 0..511
            int r   = idx >> 2;            // 0..127
            int kq  = (idx & 3) << 2;      // 0,4,8,12
            float4 a = *(const float4*)(Ab + (size_t)r * K + k0 + kq);
            As[kq + 0][r] = a.x; As[kq + 1][r] = a.y;
            As[kq + 2][r] = a.z; As[kq + 3][r] = a.w;
            float4 b = *(const float4*)(Bb + (size_t)r * K + k0 + kq);
            Bs[kq + 0][r] = b.x; Bs[kq + 1][r] = b.y;
            Bs[kq + 2][r] = b.z; Bs[kq + 3][r] = b.w;
        }
        __syncthreads();
#pragma unroll
        for (int kk = 0; kk < 16; kk++) {
            float ra[8], rb[8];
            *(float4*)&ra[0] = *(const float4*)&As[kk][ty * 8];
            *(float4*)&ra[4] = *(const float4*)&As[kk][ty * 8 + 4];
            *(float4*)&rb[0] = *(const float4*)&Bs[kk][tx * 8];
            *(float4*)&rb[4] = *(const float4*)&Bs[kk][tx * 8 + 4];
#pragma unroll
            for (int i = 0; i < 8; i++)
#pragma unroll
                for (int j = 0; j < 8; j++)
                    acc[i][j] = fmaf(ra[i], rb[j], acc[i][j]);
        }
        __syncthreads();
    }

    float* Cb = C + (size_t)(bm + ty * 8) * N + bn + tx * 8;
#pragma unroll
    for (int i = 0; i < 8; i++) {
        *(float4*)(Cb + (size_t)i * N)     = make_float4(acc[i][0], acc[i][1], acc[i][2], acc[i][3]);
        *(float4*)(Cb + (size_t)i * N + 4) = make_float4(acc[i][4], acc[i][5], acc[i][6], acc[i][7]);
    }
}

// ---------------- RoPE + cache scatter ----------------
// rotate_half: out[d]   = x[d]*cos[d]   - x[d+64]*sin[d]     (d < 64)
//              out[d+64]= x[d+64]*cos[d+64] + x[d]*sin[d+64]
__global__ __launch_bounds__(256) void rope_scatter(const float* __restrict__ Qr,
                                                    const float* __restrict__ Kr,
                                                    const float* __restrict__ Vr,
                                                    const float* __restrict__ cosp,
                                                    const float* __restrict__ sinp,
                                                    const int* __restrict__ ctx_ptrs,
                                                    float* __restrict__ gq,
                                                    float* __restrict__ gk,
                                                    float* __restrict__ gv)
{
    const int row = blockIdx.x;          // 0..2047
    const int b = row >> 10, t = row & 1023;
    const int tid = threadIdx.x;
    const float* crow = cosp + (size_t)t * HD;
    const float* srow = sinp + (size_t)t * HD;

    // Q heads
    for (int idx = tid; idx < NH * 64; idx += 256) {
        int h = idx >> 6, d = idx & 63;
        float x0 = Qr[(size_t)row * (NH * HD) + h * HD + d];
        float x1 = Qr[(size_t)row * (NH * HD) + h * HD + d + 64];
        float o0 = x0 * crow[d]      - x1 * srow[d];
        float o1 = x1 * crow[d + 64] + x0 * srow[d + 64];
        size_t base = ((size_t)(b * NH + h) * QL + t) * HD;
        gq[base + d]      = o0;
        gq[base + d + 64] = o1;
    }

    const int blk  = ctx_ptrs[b * (QL / BLKSZ) + (t >> 4)];
    const int rrow = t & 15;

    // K heads (rope) -> storage
    for (int idx = tid; idx < NKV * 64; idx += 256) {
        int h = idx >> 6, d = idx & 63;
        float x0 = Kr[(size_t)row * (NKV * HD) + h * HD + d];
        float x1 = Kr[(size_t)row * (NKV * HD) + h * HD + d + 64];
        float o0 = x0 * crow[d]      - x1 * srow[d];
        float o1 = x1 * crow[d + 64] + x0 * srow[d + 64];
        size_t base = (((size_t)blk * NKV + h) * BLKSZ + rrow) * HD;
        gk[base + d]      = o0;
        gk[base + d + 64] = o1;
    }

    // V heads (no rope) -> storage
    for (int idx = tid; idx < NKV * HD; idx += 256) {
        int h = idx >> 7, d = idx & 127;
        gv[(((size_t)blk * NKV + h) * BLKSZ + rrow) * HD + d] =
            Vr[(size_t)row * (NKV * HD) + h * HD + d];
    }
}

// ---------------- flash attention (fp32, online softmax) ----------------
// grid: (qtile 0..15, head 0..31, batch 0..1); block 256 threads (16x16)
// thread (ty,tx): S micro-tile q in {ty+16i}, s in {tx+16j};
//                 O accum   q in {ty+16i}, d in {4tx..4tx+3, 64+4tx..}
#define QPAD 132
#define PPAD 68
#define ATT_SMEM ((2 * 64 * QPAD + 64 * PPAD) * (int)sizeof(float))

__global__ __launch_bounds__(256) void attn_kernel(const float* __restrict__ gq,
                                                   const float* __restrict__ gk,
                                                   const float* __restrict__ gv,
                                                   const int* __restrict__ kvlut,
                                                   const int* __restrict__ prefix_ptr,
                                                   float* __restrict__ gout)
{
    extern __shared__ float sm[];
    float* Qs  = sm;                 // 64 x 132
    float* KVs = sm + 64 * QPAD;     // 64 x 132 (K, then reused for V)
    float* Ps  = sm + 2 * 64 * QPAD; // 64 x 68, layout [s][q]

    const int qtile = blockIdx.x, h = blockIdx.y, b = blockIdx.z;
    const int kvh = h >> 2;          // group size 4
    const int prefix = prefix_ptr ? *prefix_ptr : 3072;
    const int tid = threadIdx.x;
    const int ty = tid >> 4, tx = tid & 15;
    const int q0 = qtile * 64;
    const int* lut = kvlut + b * (SEQ / BLKSZ);

    // load Q tile
    const float* qbase = gq + ((size_t)(b * NH + h) * QL + q0) * HD;
    for (int i = tid; i < 64 * 32; i += 256) {
        int r = i >> 5, c4 = (i & 31) << 2;
        *(float4*)&Qs[r * QPAD + c4] = *(const float4*)(qbase + (size_t)r * HD + c4);
    }

    float m[4], l[4], O[4][2][4];
    int qpos[4];
#pragma unroll
    for (int i = 0; i < 4; i++) {
        m[i] = -1e30f; l[i] = 0.f;
        qpos[i] = prefix + q0 + ty + 16 * i;
#pragma unroll
        for (int u = 0; u < 2; u++)
#pragma unroll
            for (int e = 0; e < 4; e++) O[i][u][e] = 0.f;
    }

    const int kv_end = prefix + q0 + 64; // exclusive bound on needed kv positions
    const float scale = 0.08838834764831845f; // 1/sqrt(128)

    for (int s0 = 0; s0 < kv_end; s0 += 64) {
        __syncthreads(); // protect previous-iter V/P readers before overwrite

        // load K tile (gather via LUT)
        for (int i = tid; i < 64 * 32; i += 256) {
            int r = i >> 5, c4 = (i & 31) << 2;
            int s = s0 + r;
            int blk = lut[s >> 4];
            const float* src = gk + (((size_t)blk * NKV + kvh) * BLKSZ + (s & 15)) * HD;
            *(float4*)&KVs[r * QPAD + c4] = *(const float4*)(src + c4);
        }
        __syncthreads();

        // S = Q K^T (4x4 micro-tile per thread)
        float Sv[4][4];
#pragma unroll
        for (int i = 0; i < 4; i++)
#pragma unroll
            for (int j = 0; j < 4; j++) Sv[i][j] = 0.f;

#pragma unroll 4
        for (int d = 0; d < HD; d += 4) {
            float4 qa[4], kb[4];
#pragma unroll
            for (int i = 0; i < 4; i++)
                qa[i] = *(const float4*)&Qs[(ty + 16 * i) * QPAD + d];
#pragma unroll
            for (int j = 0; j < 4; j++)
                kb[j] = *(const float4*)&KVs[(tx + 16 * j) * QPAD + d];
#pragma unroll
            for (int i = 0; i < 4; i++)
#pragma unroll
                for (int j = 0; j < 4; j++) {
                    Sv[i][j] = fmaf(qa[i].x, kb[j].x, Sv[i][j]);
                    Sv[i][j] = fmaf(qa[i].y, kb[j].y, Sv[i][j]);
                    Sv[i][j] = fmaf(qa[i].z, kb[j].z, Sv[i][j]);
                    Sv[i][j] = fmaf(qa[i].w, kb[j].w, Sv[i][j]);
                }
        }

        // mask + online softmax per q-row group
#pragma unroll
        for (int i = 0; i < 4; i++) {
            float rmax = -1e30f;
#pragma unroll
            for (int j = 0; j < 4; j++) {
                int spos = s0 + tx + 16 * j;
                float v = (spos <= qpos[i]) ? Sv[i][j] * scale : -1e30f;
                Sv[i][j] = v;
                rmax = fmaxf(rmax, v);
            }
#pragma unroll
            for (int o = 1; o < 16; o <<= 1)
                rmax = fmaxf(rmax, __shfl_xor_sync(0xffffffffu, rmax, o));
            float mn = fmaxf(m[i], rmax);
            float f  = __expf(m[i] - mn);
            float sum = 0.f;
#pragma unroll
            for (int j = 0; j < 4; j++) {
                float p = __expf(Sv[i][j] - mn);
                Sv[i][j] = p;
                sum += p;
            }
#pragma unroll
            for (int o = 1; o < 16; o <<= 1)
                sum += __shfl_xor_sync(0xffffffffu, sum, o);
            m[i] = mn;
            l[i] = l[i] * f + sum;
#pragma unroll
            for (int u = 0; u < 2; u++)
#pragma unroll
                for (int e = 0; e < 4; e++) O[i][u][e] *= f;
#pragma unroll
            for (int j = 0; j < 4; j++)
                Ps[(tx + 16 * j) * PPAD + ty + 16 * i] = Sv[i][j];
        }
        __syncthreads();

        // load V tile into same smem
        for (int i = tid; i < 64 * 32; i += 256) {
            int r = i >> 5, c4 = (i & 31) << 2;
            int s = s0 + r;
            int blk = lut[s >> 4];
            const float* src = gv + (((size_t)blk * NKV + kvh) * BLKSZ + (s & 15)) * HD;
            *(float4*)&KVs[r * QPAD + c4] = *(const float4*)(src + c4);
        }
        __syncthreads();

        // O += P V
#pragma unroll 2
        for (int s = 0; s < 64; s++) {
            float4 v0 = *(const float4*)&KVs[s * QPAD + tx * 4];
            float4 v1 = *(const float4*)&KVs[s * QPAD + 64 + tx * 4];
#pragma unroll
            for (int i = 0; i < 4; i++) {
                float p = Ps[s * PPAD + ty + 16 * i];
                O[i][0][0] = fmaf(p, v0.x, O[i][0][0]);
                O[i][0][1] = fmaf(p, v0.y, O[i][0][1]);
                O[i][0][2] = fmaf(p, v0.z, O[i][0][2]);
                O[i][0][3] = fmaf(p, v0.w, O[i][0][3]);
                O[i][1][0] = fmaf(p, v1.x, O[i][1][0]);
                O[i][1][1] = fmaf(p, v1.y, O[i][1][1]);
                O[i][1][2] = fmaf(p, v1.z, O[i][1][2]);
                O[i][1][3] = fmaf(p, v1.w, O[i][1][3]);
            }
        }
    }

    // normalize + write [b, t, h, d]
#pragma unroll
    for (int i = 0; i < 4; i++) {
        float inv = 1.f / l[i];
        int q = q0 + ty + 16 * i;
        float* dst = gout + ((size_t)(b * QL + q)) * (NH * HD) + h * HD;
        *(float4*)(dst + tx * 4) =
            make_float4(O[i][0][0] * inv, O[i][0][1] * inv, O[i][0][2] * inv, O[i][0][3] * inv);
        *(float4*)(dst + 64 + tx * 4) =
            make_float4(O[i][1][0] * inv, O[i][1][1] * inv, O[i][1][2] * inv, O[i][1][3] * inv);
    }
}

// ---------------- launcher ----------------
extern "C" void kernel_launch(void* const* d_in, const int* in_sizes, int n_in,
                              void* d_out, int out_size)
{
    const float* hidden = (const float*)d_in[0];
    const float* Wq     = (const float*)d_in[1];
    const float* Wk     = (const float*)d_in[2];
    const float* Wv     = (const float*)d_in[3];
    const float* Wo     = (const float*)d_in[4];
    const float* cosp   = (const float*)d_in[5];
    const float* sinp   = (const float*)d_in[6];
    const float* kstore = (const float*)d_in[7];
    const float* vstore = (const float*)d_in[8];
    const int*   kvlut  = (const int*)d_in[9];
    const int*   ctxptr = (const int*)d_in[10];
    const int*   prefix = (n_in >= 12) ? (const int*)d_in[11] : nullptr;
    float* out = (float*)d_out;

    float *qraw, *kraw, *vraw, *qrope, *kst, *vst, *attn;
    cudaGetSymbolAddress((void**)&qraw,  g_qraw);
    cudaGetSymbolAddress((void**)&kraw,  g_kraw);
    cudaGetSymbolAddress((void**)&vraw,  g_vraw);
    cudaGetSymbolAddress((void**)&qrope, g_q);
    cudaGetSymbolAddress((void**)&kst,   g_kst);
    cudaGetSymbolAddress((void**)&vst,   g_vst);
    cudaGetSymbolAddress((void**)&attn,  g_attn);

    const size_t kvbytes = (size_t)NBLK * NKV * BLKSZ * HD * sizeof(float);
    cudaMemcpyAsync(kst, kstore, kvbytes, cudaMemcpyDeviceToDevice, 0);
    cudaMemcpyAsync(vst, vstore, kvbytes, cudaMemcpyDeviceToDevice, 0);

    // QKV projections
    sgemm_nt<<<dim3((NH * HD) / 128,  MROWS / 128), 256>>>(hidden, Wq, qraw, MROWS, NH * HD,  HID);
    sgemm_nt<<<dim3((NKV * HD) / 128, MROWS / 128), 256>>>(hidden, Wk, kraw, MROWS, NKV * HD, HID);
    sgemm_nt<<<dim3((NKV * HD) / 128, MROWS / 128), 256>>>(hidden, Wv, vraw, MROWS, NKV * HD, HID);

    // RoPE + cache scatter
    rope_scatter<<<MROWS, 256>>>(qraw, kraw, vraw, cosp, sinp, ctxptr, qrope, kst, vst);

    // flash attention
    cudaFuncSetAttribute(attn_kernel, cudaFuncAttributeMaxDynamicSharedMemorySize, ATT_SMEM);
    attn_kernel<<<dim3(QL / 64, NH, BSZ), 256, ATT_SMEM>>>(qrope, kst, vst, kvlut, prefix, attn);

    // output projection -> d_out
    sgemm_nt<<<dim3(HID / 128, MROWS / 128), 256>>>(attn, Wo, out, MROWS, HID, HID);
}

// round 4
// speedup vs baseline: 1.5313x; 1.5313x over previous
#include <cuda_runtime.h>
#include <cuda_bf16.h>
#include <cstdint>

// ---------------- problem dims ----------------
#define BSZ   2
#define QL    1024
#define HID   4096
#define NH    32
#define NKV   8
#define HD    128
#define NBLK  512
#define BLKSZ 16
#define SEQ   4096
#define MROWS (BSZ*QL)                 // 2048
#define WROWS (NH*HD + 2*NKV*HD + HID) // 10240
#define WOFF_Q 0
#define WOFF_K ((size_t)(NH*HD) * HID)
#define WOFF_V ((size_t)(NH*HD + NKV*HD) * HID)
#define WOFF_O ((size_t)(NH*HD + 2*NKV*HD) * HID)

// ---------------- device scratch ----------------
__device__ float g_qraw[(size_t)MROWS * NH * HD];
__device__ float g_kraw[(size_t)MROWS * NKV * HD];
__device__ float g_vraw[(size_t)MROWS * NKV * HD];
__device__ float g_q   [(size_t)BSZ * NH * QL * HD];
__device__ float g_kst [(size_t)NBLK * NKV * BLKSZ * HD];
__device__ float g_vst [(size_t)NBLK * NKV * BLKSZ * HD];
__device__ float g_attn[(size_t)MROWS * NH * HD];
__device__ __nv_bfloat16 g_xhi[(size_t)MROWS * HID];
__device__ __nv_bfloat16 g_xlo[(size_t)MROWS * HID];
__device__ __nv_bfloat16 g_whi[(size_t)WROWS * HID];
__device__ __nv_bfloat16 g_wlo[(size_t)WROWS * HID];

// ---------------- helpers ----------------
__device__ __forceinline__ uint32_t smem_u32(const void* p) {
    uint32_t a;
    asm("{ .reg .u64 t; cvta.to.shared.u64 t, %1; cvt.u32.u64 %0, t; }" : "=r"(a) : "l"(p));
    return a;
}
__device__ __forceinline__ void ldsm4(uint32_t* r, uint32_t addr) {
    asm volatile("ldmatrix.sync.aligned.m8n8.x4.shared.b16 {%0,%1,%2,%3}, [%4];"
                 : "=r"(r[0]), "=r"(r[1]), "=r"(r[2]), "=r"(r[3]) : "r"(addr));
}
__device__ __forceinline__ void mma_bf16(float* c, const uint32_t* a, uint32_t b0, uint32_t b1) {
    asm volatile("mma.sync.aligned.m16n8k16.row.col.f32.bf16.bf16.f32 "
                 "{%0,%1,%2,%3}, {%4,%5,%6,%7}, {%8,%9}, {%0,%1,%2,%3};"
                 : "+f"(c[0]), "+f"(c[1]), "+f"(c[2]), "+f"(c[3])
                 : "r"(a[0]), "r"(a[1]), "r"(a[2]), "r"(a[3]), "r"(b0), "r"(b1));
}

// ---------------- fp32 -> bf16 hi/lo split ----------------
__global__ __launch_bounds__(256) void split2(const float* __restrict__ x,
                                              __nv_bfloat16* __restrict__ hi,
                                              __nv_bfloat16* __restrict__ lo, int n4)
{
    int i = blockIdx.x * 256 + threadIdx.x;
    if (i >= n4) return;
    float4 v = *(const float4*)(x + (size_t)i * 4);
    __nv_bfloat16 h0 = __float2bfloat16(v.x), h1 = __float2bfloat16(v.y);
    __nv_bfloat16 h2 = __float2bfloat16(v.z), h3 = __float2bfloat16(v.w);
    __nv_bfloat16 l0 = __float2bfloat16(v.x - __bfloat162float(h0));
    __nv_bfloat16 l1 = __float2bfloat16(v.y - __bfloat162float(h1));
    __nv_bfloat16 l2 = __float2bfloat16(v.z - __bfloat162float(h2));
    __nv_bfloat16 l3 = __float2bfloat16(v.w - __bfloat162float(h3));
    __nv_bfloat162* hp = (__nv_bfloat162*)(hi + (size_t)i * 4);
    __nv_bfloat162* lp = (__nv_bfloat162*)(lo + (size_t)i * 4);
    hp[0] = __nv_bfloat162(h0, h1); hp[1] = __nv_bfloat162(h2, h3);
    lp[0] = __nv_bfloat162(l0, l1); lp[1] = __nv_bfloat162(l2, l3);
}

// ---------------- mma.sync bf16 3-term split GEMM ----------------
// C[M,N] = A[M,K]*B[N,K]^T, fp32 acc. Tile 128x128x32, 8 warps (4M x 2N),
// warp tile 32x64 via m16n8k16. Smem swizzle: 16B chunk index ^= (row>>1)&3,
// conflict-free for both float4 stores and ldmatrix reads.
__global__ __launch_bounds__(256) void gemm_mma_split(
    const __nv_bfloat16* __restrict__ Ahi, const __nv_bfloat16* __restrict__ Alo,
    const __nv_bfloat16* __restrict__ Bhi, const __nv_bfloat16* __restrict__ Blo,
    float* __restrict__ C, int M, int N, int K)
{
    __shared__ __nv_bfloat16 sAh[128 * 32], sAl[128 * 32];
    __shared__ __nv_bfloat16 sBh[128 * 32], sBl[128 * 32];

    const int tid  = threadIdx.x;
    const int warp = tid >> 5, lane = tid & 31;
    const int wm = warp & 3, wn = warp >> 2;   // 4 warps in M, 2 in N
    const int bm = blockIdx.y * 128, bn = blockIdx.x * 128;

    const uint32_t aHi = smem_u32(sAh), aLo = smem_u32(sAl);
    const uint32_t bHi = smem_u32(sBh), bLo = smem_u32(sBl);

    float acc[2][8][4];
#pragma unroll
    for (int i = 0; i < 2; i++)
#pragma unroll
        for (int j = 0; j < 8; j++)
#pragma unroll
            for (int e = 0; e < 4; e++) acc[i][j][e] = 0.f;

    const __nv_bfloat16* gAh = Ahi + (size_t)bm * K;
    const __nv_bfloat16* gAl = Alo + (size_t)bm * K;
    const __nv_bfloat16* gBh = Bhi + (size_t)bn * K;
    const __nv_bfloat16* gBl = Blo + (size_t)bn * K;

    for (int k0 = 0; k0 < K; k0 += 32) {
#pragma unroll
        for (int p = 0; p < 2; p++) {
            int c   = tid + p * 256;        // 0..511
            int row = c >> 2, kc = c & 3;
            int phys = (kc + (row >> 1)) & 3;
            uint32_t soff = (uint32_t)(row * 32 + phys * 8);
            size_t goff = (size_t)row * K + k0 + kc * 8;
            *(uint4*)&sAh[soff] = *(const uint4*)(gAh + goff);
            *(uint4*)&sAl[soff] = *(const uint4*)(gAl + goff);
            *(uint4*)&sBh[soff] = *(const uint4*)(gBh + goff);
            *(uint4*)&sBl[soff] = *(const uint4*)(gBl + goff);
        }
        __syncthreads();

#pragma unroll
        for (int ks = 0; ks < 2; ks++) {
            uint32_t ah[2][4], al[2][4];
            {
                int r  = wm * 32 + (lane & 15);
                int cd = ks * 2 + (lane >> 4);
#pragma unroll
                for (int mt = 0; mt < 2; mt++) {
                    int row  = r + mt * 16;
                    int phys = (cd + (row >> 1)) & 3;
                    uint32_t off = (uint32_t)(row * 32 + phys * 8) * 2;
                    ldsm4(ah[mt], aHi + off);
                    ldsm4(al[mt], aLo + off);
                }
            }
#pragma unroll
            for (int nt4 = 0; nt4 < 4; nt4++) {
                int n    = wn * 64 + nt4 * 16 + (lane & 7) + ((lane >> 4) << 3);
                int cd   = ks * 2 + ((lane >> 3) & 1);
                int phys = (cd + (n >> 1)) & 3;
                uint32_t off = (uint32_t)(n * 32 + phys * 8) * 2;
                uint32_t bh[4], bl[4];
                ldsm4(bh, bHi + off);
                ldsm4(bl, bLo + off);
#pragma unroll
                for (int mt = 0; mt < 2; mt++) {
#pragma unroll
                    for (int p = 0; p < 2; p++) {
                        float* cc = acc[mt][nt4 * 2 + p];
                        mma_bf16(cc, ah[mt], bh[2 * p], bh[2 * p + 1]);
                        mma_bf16(cc, ah[mt], bl[2 * p], bl[2 * p + 1]);
                        mma_bf16(cc, al[mt], bh[2 * p], bh[2 * p + 1]);
                    }
                }
            }
        }
        __syncthreads();
    }

    // epilogue
#pragma unroll
    for (int mt = 0; mt < 2; mt++) {
#pragma unroll
        for (int nt = 0; nt < 8; nt++) {
            int row = bm + wm * 32 + mt * 16 + (lane >> 2);
            int col = bn + wn * 64 + nt * 8 + (lane & 3) * 2;
            float* cc = acc[mt][nt];
            *(float2*)&C[(size_t)row * N + col]       = make_float2(cc[0], cc[1]);
            *(float2*)&C[(size_t)(row + 8) * N + col] = make_float2(cc[2], cc[3]);
        }
    }
}

// ---------------- RoPE + cache scatter ----------------
__global__ __launch_bounds__(256) void rope_scatter(const float* __restrict__ Qr,
                                                    const float* __restrict__ Kr,
                                                    const float* __restrict__ Vr,
                                                    const float* __restrict__ cosp,
                                                    const float* __restrict__ sinp,
                                                    const int* __restrict__ ctx_ptrs,
                                                    float* __restrict__ gq,
                                                    float* __restrict__ gk,
                                                    float* __restrict__ gv)
{
    const int row = blockIdx.x;
    const int b = row >> 10, t = row & 1023;
    const int tid = threadIdx.x;
    const float* crow = cosp + (size_t)t * HD;
    const float* srow = sinp + (size_t)t * HD;

    for (int idx = tid; idx < NH * 64; idx += 256) {
        int h = idx >> 6, d = idx & 63;
        float x0 = Qr[(size_t)row * (NH * HD) + h * HD + d];
        float x1 = Qr[(size_t)row * (NH * HD) + h * HD + d + 64];
        float o0 = x0 * crow[d]      - x1 * srow[d];
        float o1 = x1 * crow[d + 64] + x0 * srow[d + 64];
        size_t base = ((size_t)(b * NH + h) * QL + t) * HD;
        gq[base + d] = o0; gq[base + d + 64] = o1;
    }
    const int blk  = ctx_ptrs[b * (QL / BLKSZ) + (t >> 4)];
    const int rrow = t & 15;
    for (int idx = tid; idx < NKV * 64; idx += 256) {
        int h = idx >> 6, d = idx & 63;
        float x0 = Kr[(size_t)row * (NKV * HD) + h * HD + d];
        float x1 = Kr[(size_t)row * (NKV * HD) + h * HD + d + 64];
        float o0 = x0 * crow[d]      - x1 * srow[d];
        float o1 = x1 * crow[d + 64] + x0 * srow[d + 64];
        size_t base = (((size_t)blk * NKV + h) * BLKSZ + rrow) * HD;
        gk[base + d] = o0; gk[base + d + 64] = o1;
    }
    for (int idx = tid; idx < NKV * HD; idx += 256) {
        int h = idx >> 7, d = idx & 127;
        gv[(((size_t)blk * NKV + h) * BLKSZ + rrow) * HD + d] =
            Vr[(size_t)row * (NKV * HD) + h * HD + d];
    }
}

// ---------------- flash attention (fp32, online softmax) ----------------
#define QPAD 132
#define PPAD 68
#define ATT_SMEM ((2 * 64 * QPAD + 64 * PPAD) * (int)sizeof(float))

__global__ __launch_bounds__(256) void attn_kernel(const float* __restrict__ gq,
                                                   const float* __restrict__ gk,
                                                   const float* __restrict__ gv,
                                                   const int* __restrict__ kvlut,
                                                   const int* __restrict__ prefix_ptr,
                                                   float* __restrict__ gout)
{
    extern __shared__ float sm[];
    float* Qs  = sm;
    float* KVs = sm + 64 * QPAD;
    float* Ps  = sm + 2 * 64 * QPAD;

    const int qtile = blockIdx.x, h = blockIdx.y, b = blockIdx.z;
    const int kvh = h >> 2;
    const int prefix = prefix_ptr ? *prefix_ptr : 3072;
    const int tid = threadIdx.x;
    const int ty = tid >> 4, tx = tid & 15;
    const int q0 = qtile * 64;
    const int* lut = kvlut + b * (SEQ / BLKSZ);

    const float* qbase = gq + ((size_t)(b * NH + h) * QL + q0) * HD;
    for (int i = tid; i < 64 * 32; i += 256) {
        int r = i >> 5, c4 = (i & 31) << 2;
        *(float4*)&Qs[r * QPAD + c4] = *(const float4*)(qbase + (size_t)r * HD + c4);
    }

    float m[4], l[4], O[4][2][4];
    int qpos[4];
#pragma unroll
    for (int i = 0; i < 4; i++) {
        m[i] = -1e30f; l[i] = 0.f;
        qpos[i] = prefix + q0 + ty + 16 * i;
#pragma unroll
        for (int u = 0; u < 2; u++)
#pragma unroll
            for (int e = 0; e < 4; e++) O[i][u][e] = 0.f;
    }

    const int kv_end = prefix + q0 + 64;
    const float scale = 0.08838834764831845f;

    for (int s0 = 0; s0 < kv_end; s0 += 64) {
        __syncthreads();
        for (int i = tid; i < 64 * 32; i += 256) {
            int r = i >> 5, c4 = (i & 31) << 2;
            int s = s0 + r;
            int blk = lut[s >> 4];
            const float* src = gk + (((size_t)blk * NKV + kvh) * BLKSZ + (s & 15)) * HD;
            *(float4*)&KVs[r * QPAD + c4] = *(const float4*)(src + c4);
        }
        __syncthreads();

        float Sv[4][4];
#pragma unroll
        for (int i = 0; i < 4; i++)
#pragma unroll
            for (int j = 0; j < 4; j++) Sv[i][j] = 0.f;

#pragma unroll 4
        for (int d = 0; d < HD; d += 4) {
            float4 qa[4], kb[4];
#pragma unroll
            for (int i = 0; i < 4; i++)
                qa[i] = *(const float4*)&Qs[(ty + 16 * i) * QPAD + d];
#pragma unroll
            for (int j = 0; j < 4; j++)
                kb[j] = *(const float4*)&KVs[(tx + 16 * j) * QPAD + d];
#pragma unroll
            for (int i = 0; i < 4; i++)
#pragma unroll
                for (int j = 0; j < 4; j++) {
                    Sv[i][j] = fmaf(qa[i].x, kb[j].x, Sv[i][j]);
                    Sv[i][j] = fmaf(qa[i].y, kb[j].y, Sv[i][j]);
                    Sv[i][j] = fmaf(qa[i].z, kb[j].z, Sv[i][j]);
                    Sv[i][j] = fmaf(qa[i].w, kb[j].w, Sv[i][j]);
                }
        }

#pragma unroll
        for (int i = 0; i < 4; i++) {
            float rmax = -1e30f;
#pragma unroll
            for (int j = 0; j < 4; j++) {
                int spos = s0 + tx + 16 * j;
                float v = (spos <= qpos[i]) ? Sv[i][j] * scale : -1e30f;
                Sv[i][j] = v;
                rmax = fmaxf(rmax, v);
            }
#pragma unroll
            for (int o = 1; o < 16; o <<= 1)
                rmax = fmaxf(rmax, __shfl_xor_sync(0xffffffffu, rmax, o));
            float mn = fmaxf(m[i], rmax);
            float f  = __expf(m[i] - mn);
            float sum = 0.f;
#pragma unroll
            for (int j = 0; j < 4; j++) {
                float p = __expf(Sv[i][j] - mn);
                Sv[i][j] = p;
                sum += p;
            }
#pragma unroll
            for (int o = 1; o < 16; o <<= 1)
                sum += __shfl_xor_sync(0xffffffffu, sum, o);
            m[i] = mn;
            l[i] = l[i] * f + sum;
#pragma unroll
            for (int u = 0; u < 2; u++)
#pragma unroll
                for (int e = 0; e < 4; e++) O[i][u][e] *= f;
#pragma unroll
            for (int j = 0; j < 4; j++)
                Ps[(tx + 16 * j) * PPAD + ty + 16 * i] = Sv[i][j];
        }
        __syncthreads();

        for (int i = tid; i < 64 * 32; i += 256) {
            int r = i >> 5, c4 = (i & 31) << 2;
            int s = s0 + r;
            int blk = lut[s >> 4];
            const float* src = gv + (((size_t)blk * NKV + kvh) * BLKSZ + (s & 15)) * HD;
            *(float4*)&KVs[r * QPAD + c4] = *(const float4*)(src + c4);
        }
        __syncthreads();

#pragma unroll 2
        for (int s = 0; s < 64; s++) {
            float4 v0 = *(const float4*)&KVs[s * QPAD + tx * 4];
            float4 v1 = *(const float4*)&KVs[s * QPAD + 64 + tx * 4];
#pragma unroll
            for (int i = 0; i < 4; i++) {
                float p = Ps[s * PPAD + ty + 16 * i];
                O[i][0][0] = fmaf(p, v0.x, O[i][0][0]);
                O[i][0][1] = fmaf(p, v0.y, O[i][0][1]);
                O[i][0][2] = fmaf(p, v0.z, O[i][0][2]);
                O[i][0][3] = fmaf(p, v0.w, O[i][0][3]);
                O[i][1][0] = fmaf(p, v1.x, O[i][1][0]);
                O[i][1][1] = fmaf(p, v1.y, O[i][1][1]);
                O[i][1][2] = fmaf(p, v1.z, O[i][1][2]);
                O[i][1][3] = fmaf(p, v1.w, O[i][1][3]);
            }
        }
    }

#pragma unroll
    for (int i = 0; i < 4; i++) {
        float inv = 1.f / l[i];
        int q = q0 + ty + 16 * i;
        float* dst = gout + ((size_t)(b * QL + q)) * (NH * HD) + h * HD;
        *(float4*)(dst + tx * 4) =
            make_float4(O[i][0][0] * inv, O[i][0][1] * inv, O[i][0][2] * inv, O[i][0][3] * inv);
        *(float4*)(dst + 64 + tx * 4) =
            make_float4(O[i][1][0] * inv, O[i][1][1] * inv, O[i][1][2] * inv, O[i][1][3] * inv);
    }
}

// ---------------- launcher ----------------
extern "C" void kernel_launch(void* const* d_in, const int* in_sizes, int n_in,
                              void* d_out, int out_size)
{
    const float* hidden = (const float*)d_in[0];
    const float* Wq     = (const float*)d_in[1];
    const float* Wk     = (const float*)d_in[2];
    const float* Wv     = (const float*)d_in[3];
    const float* Wo     = (const float*)d_in[4];
    const float* cosp   = (const float*)d_in[5];
    const float* sinp   = (const float*)d_in[6];
    const float* kstore = (const float*)d_in[7];
    const float* vstore = (const float*)d_in[8];
    const int*   kvlut  = (const int*)d_in[9];
    const int*   ctxptr = (const int*)d_in[10];
    const int*   prefix = (n_in >= 12) ? (const int*)d_in[11] : nullptr;
    float* out = (float*)d_out;

    float *qraw, *kraw, *vraw, *qrope, *kst, *vst, *attn;
    __nv_bfloat16 *xhi, *xlo, *whi, *wlo;
    cudaGetSymbolAddress((void**)&qraw,  g_qraw);
    cudaGetSymbolAddress((void**)&kraw,  g_kraw);
    cudaGetSymbolAddress((void**)&vraw,  g_vraw);
    cudaGetSymbolAddress((void**)&qrope, g_q);
    cudaGetSymbolAddress((void**)&kst,   g_kst);
    cudaGetSymbolAddress((void**)&vst,   g_vst);
    cudaGetSymbolAddress((void**)&attn,  g_attn);
    cudaGetSymbolAddress((void**)&xhi,   g_xhi);
    cudaGetSymbolAddress((void**)&xlo,   g_xlo);
    cudaGetSymbolAddress((void**)&whi,   g_whi);
    cudaGetSymbolAddress((void**)&wlo,   g_wlo);

    const size_t kvbytes = (size_t)NBLK * NKV * BLKSZ * HD * sizeof(float);
    cudaMemcpyAsync(kst, kstore, kvbytes, cudaMemcpyDeviceToDevice, 0);
    cudaMemcpyAsync(vst, vstore, kvbytes, cudaMemcpyDeviceToDevice, 0);

    cudaFuncSetAttribute(attn_kernel, cudaFuncAttributeMaxDynamicSharedMemorySize, ATT_SMEM);

    // hi/lo splits
    {
        int n4;
        n4 = MROWS * HID / 4;
        split2<<<(n4 + 255) / 256, 256>>>(hidden, xhi, xlo, n4);
        n4 = (NH * HD) * HID / 4;
        split2<<<(n4 + 255) / 256, 256>>>(Wq, whi + WOFF_Q, wlo + WOFF_Q, n4);
        n4 = (NKV * HD) * HID / 4;
        split2<<<(n4 + 255) / 256, 256>>>(Wk, whi + WOFF_K, wlo + WOFF_K, n4);
        split2<<<(n4 + 255) / 256, 256>>>(Wv, whi + WOFF_V, wlo + WOFF_V, n4);
        n4 = HID * HID / 4;
        split2<<<(n4 + 255) / 256, 256>>>(Wo, whi + WOFF_O, wlo + WOFF_O, n4);
    }

    // projections via mma.sync bf16-split
    gemm_mma_split<<<dim3((NH * HD) / 128,  MROWS / 128), 256>>>(
        xhi, xlo, whi + WOFF_Q, wlo + WOFF_Q, qraw, MROWS, NH * HD, HID);
    gemm_mma_split<<<dim3((NKV * HD) / 128, MROWS / 128), 256>>>(
        xhi, xlo, whi + WOFF_K, wlo + WOFF_K, kraw, MROWS, NKV * HD, HID);
    gemm_mma_split<<<dim3((NKV * HD) / 128, MROWS / 128), 256>>>(
        xhi, xlo, whi + WOFF_V, wlo + WOFF_V, vraw, MROWS, NKV * HD, HID);

    rope_scatter<<<MROWS, 256>>>(qraw, kraw, vraw, cosp, sinp, ctxptr, qrope, kst, vst);

    attn_kernel<<<dim3(QL / 64, NH, BSZ), 256, ATT_SMEM>>>(qrope, kst, vst, kvlut, prefix, attn);

    // O projection
    {
        int n4 = MROWS * HID / 4;
        split2<<<(n4 + 255) / 256, 256>>>(attn, xhi, xlo, n4);
    }
    gemm_mma_split<<<dim3(HID / 128, MROWS / 128), 256>>>(
        xhi, xlo, whi + WOFF_O, wlo + WOFF_O, out, MROWS, HID, HID);
}

// round 5
// speedup vs baseline: 2.6729x; 1.7455x over previous
#include <cuda_runtime.h>
#include <cuda_bf16.h>
#include <cstdint>

// ---------------- problem dims ----------------
#define BSZ   2
#define QL    1024
#define HID   4096
#define NH    32
#define NKV   8
#define HD    128
#define NBLK  512
#define BLKSZ 16
#define SEQ   4096
#define MROWS (BSZ*QL)                 // 2048
#define WROWS (NH*HD + 2*NKV*HD + HID) // 10240
#define WOFF_Q 0
#define WOFF_K ((size_t)(NH*HD) * HID)
#define WOFF_V ((size_t)(NH*HD + NKV*HD) * HID)
#define WOFF_O ((size_t)(NH*HD + 2*NKV*HD) * HID)

// q pre-scale: (1/sqrt(128)) * log2(e)  -> softmax in exp2 domain
#define ASCALE ((float)(0.08838834764831845 * 1.4426950408889634))

// ---------------- device scratch ----------------
__device__ float g_qraw[(size_t)MROWS * NH * HD];
__device__ float g_kraw[(size_t)MROWS * NKV * HD];
__device__ float g_vraw[(size_t)MROWS * NKV * HD];
__device__ __nv_bfloat16 g_xhi[(size_t)MROWS * HID];
__device__ __nv_bfloat16 g_xlo[(size_t)MROWS * HID];
__device__ __nv_bfloat16 g_whi[(size_t)WROWS * HID];
__device__ __nv_bfloat16 g_wlo[(size_t)WROWS * HID];
__device__ __nv_bfloat16 g_qhi[(size_t)BSZ * NH * QL * HD];
__device__ __nv_bfloat16 g_qlo[(size_t)BSZ * NH * QL * HD];
__device__ __nv_bfloat16 g_khi[(size_t)NBLK * NKV * BLKSZ * HD];
__device__ __nv_bfloat16 g_klo[(size_t)NBLK * NKV * BLKSZ * HD];
__device__ __nv_bfloat16 g_vhi[(size_t)NBLK * NKV * BLKSZ * HD];
__device__ __nv_bfloat16 g_vlo[(size_t)NBLK * NKV * BLKSZ * HD];

// ---------------- helpers ----------------
__device__ __forceinline__ uint32_t smem_u32(const void* p) {
    uint32_t a;
    asm("{ .reg .u64 t; cvta.to.shared.u64 t, %1; cvt.u32.u64 %0, t; }" : "=r"(a) : "l"(p));
    return a;
}
__device__ __forceinline__ void ldsm4(uint32_t* r, uint32_t addr) {
    asm volatile("ldmatrix.sync.aligned.m8n8.x4.shared.b16 {%0,%1,%2,%3}, [%4];"
                 : "=r"(r[0]), "=r"(r[1]), "=r"(r[2]), "=r"(r[3]) : "r"(addr));
}
__device__ __forceinline__ void ldsm4t(uint32_t* r, uint32_t addr) {
    asm volatile("ldmatrix.sync.aligned.m8n8.x4.trans.shared.b16 {%0,%1,%2,%3}, [%4];"
                 : "=r"(r[0]), "=r"(r[1]), "=r"(r[2]), "=r"(r[3]) : "r"(addr));
}
__device__ __forceinline__ void mma_bf16(float* c, const uint32_t* a, uint32_t b0, uint32_t b1) {
    asm volatile("mma.sync.aligned.m16n8k16.row.col.f32.bf16.bf16.f32 "
                 "{%0,%1,%2,%3}, {%4,%5,%6,%7}, {%8,%9}, {%0,%1,%2,%3};"
                 : "+f"(c[0]), "+f"(c[1]), "+f"(c[2]), "+f"(c[3])
                 : "r"(a[0]), "r"(a[1]), "r"(a[2]), "r"(a[3]), "r"(b0), "r"(b1));
}
__device__ __forceinline__ float ex2f(float x) {
    float y; asm("ex2.approx.ftz.f32 %0, %1;" : "=f"(y) : "f"(x)); return y;
}
__device__ __forceinline__ uint32_t packbf2(float a, float b) {
    __nv_bfloat162 t = __floats2bfloat162_rn(a, b);
    return *(uint32_t*)&t;
}

// ---------------- fp32 -> bf16 hi/lo split ----------------
__global__ __launch_bounds__(256) void split2(const float* __restrict__ x,
                                              __nv_bfloat16* __restrict__ hi,
                                              __nv_bfloat16* __restrict__ lo, int n4)
{
    int i = blockIdx.x * 256 + threadIdx.x;
    if (i >= n4) return;
    float4 v = *(const float4*)(x + (size_t)i * 4);
    __nv_bfloat16 h0 = __float2bfloat16(v.x), h1 = __float2bfloat16(v.y);
    __nv_bfloat16 h2 = __float2bfloat16(v.z), h3 = __float2bfloat16(v.w);
    __nv_bfloat16 l0 = __float2bfloat16(v.x - __bfloat162float(h0));
    __nv_bfloat16 l1 = __float2bfloat16(v.y - __bfloat162float(h1));
    __nv_bfloat16 l2 = __float2bfloat16(v.z - __bfloat162float(h2));
    __nv_bfloat16 l3 = __float2bfloat16(v.w - __bfloat162float(h3));
    __nv_bfloat162* hp = (__nv_bfloat162*)(hi + (size_t)i * 4);
    __nv_bfloat162* lp = (__nv_bfloat162*)(lo + (size_t)i * 4);
    hp[0] = __nv_bfloat162(h0, h1); hp[1] = __nv_bfloat162(h2, h3);
    lp[0] = __nv_bfloat162(l0, l1); lp[1] = __nv_bfloat162(l2, l3);
}

// ---------------- mma.sync bf16 3-term split GEMM (unchanged from R4) ----------------
__global__ __launch_bounds__(256) void gemm_mma_split(
    const __nv_bfloat16* __restrict__ Ahi, const __nv_bfloat16* __restrict__ Alo,
    const __nv_bfloat16* __restrict__ Bhi, const __nv_bfloat16* __restrict__ Blo,
    float* __restrict__ C, int M, int N, int K)
{
    __shared__ __nv_bfloat16 sAh[128 * 32], sAl[128 * 32];
    __shared__ __nv_bfloat16 sBh[128 * 32], sBl[128 * 32];

    const int tid  = threadIdx.x;
    const int warp = tid >> 5, lane = tid & 31;
    const int wm = warp & 3, wn = warp >> 2;
    const int bm = blockIdx.y * 128, bn = blockIdx.x * 128;

    const uint32_t aHi = smem_u32(sAh), aLo = smem_u32(sAl);
    const uint32_t bHi = smem_u32(sBh), bLo = smem_u32(sBl);

    float acc[2][8][4];
#pragma unroll
    for (int i = 0; i < 2; i++)
#pragma unroll
        for (int j = 0; j < 8; j++)
#pragma unroll
            for (int e = 0; e < 4; e++) acc[i][j][e] = 0.f;

    const __nv_bfloat16* gAh = Ahi + (size_t)bm * K;
    const __nv_bfloat16* gAl = Alo + (size_t)bm * K;
    const __nv_bfloat16* gBh = Bhi + (size_t)bn * K;
    const __nv_bfloat16* gBl = Blo + (size_t)bn * K;

    for (int k0 = 0; k0 < K; k0 += 32) {
#pragma unroll
        for (int p = 0; p < 2; p++) {
            int c   = tid + p * 256;
            int row = c >> 2, kc = c & 3;
            int phys = (kc + (row >> 1)) & 3;
            uint32_t soff = (uint32_t)(row * 32 + phys * 8);
            size_t goff = (size_t)row * K + k0 + kc * 8;
            *(uint4*)&sAh[soff] = *(const uint4*)(gAh + goff);
            *(uint4*)&sAl[soff] = *(const uint4*)(gAl + goff);
            *(uint4*)&sBh[soff] = *(const uint4*)(gBh + goff);
            *(uint4*)&sBl[soff] = *(const uint4*)(gBl + goff);
        }
        __syncthreads();

#pragma unroll
        for (int ks = 0; ks < 2; ks++) {
            uint32_t ah[2][4], al[2][4];
            {
                int r  = wm * 32 + (lane & 15);
                int cd = ks * 2 + (lane >> 4);
#pragma unroll
                for (int mt = 0; mt < 2; mt++) {
                    int row  = r + mt * 16;
                    int phys = (cd + (row >> 1)) & 3;
                    uint32_t off = (uint32_t)(row * 32 + phys * 8) * 2;
                    ldsm4(ah[mt], aHi + off);
                    ldsm4(al[mt], aLo + off);
                }
            }
#pragma unroll
            for (int nt4 = 0; nt4 < 4; nt4++) {
                int n    = wn * 64 + nt4 * 16 + (lane & 7) + ((lane >> 4) << 3);
                int cd   = ks * 2 + ((lane >> 3) & 1);
                int phys = (cd + (n >> 1)) & 3;
                uint32_t off = (uint32_t)(n * 32 + phys * 8) * 2;
                uint32_t bh[4], bl[4];
                ldsm4(bh, bHi + off);
                ldsm4(bl, bLo + off);
#pragma unroll
                for (int mt = 0; mt < 2; mt++) {
#pragma unroll
                    for (int p = 0; p < 2; p++) {
                        float* cc = acc[mt][nt4 * 2 + p];
                        mma_bf16(cc, ah[mt], bh[2 * p], bh[2 * p + 1]);
                        mma_bf16(cc, ah[mt], bl[2 * p], bl[2 * p + 1]);
                        mma_bf16(cc, al[mt], bh[2 * p], bh[2 * p + 1]);
                    }
                }
            }
        }
        __syncthreads();
    }

#pragma unroll
    for (int mt = 0; mt < 2; mt++) {
#pragma unroll
        for (int nt = 0; nt < 8; nt++) {
            int row = bm + wm * 32 + mt * 16 + (lane >> 2);
            int col = bn + wn * 64 + nt * 8 + (lane & 3) * 2;
            float* cc = acc[mt][nt];
            *(float2*)&C[(size_t)row * N + col]       = make_float2(cc[0], cc[1]);
            *(float2*)&C[(size_t)(row + 8) * N + col] = make_float2(cc[2], cc[3]);
        }
    }
}

// ---------------- RoPE + bf16 split + cache scatter ----------------
__global__ __launch_bounds__(256) void rope_scatter_bf16(
    const float* __restrict__ Qr, const float* __restrict__ Kr, const float* __restrict__ Vr,
    const float* __restrict__ cosp, const float* __restrict__ sinp,
    const int* __restrict__ ctx_ptrs,
    __nv_bfloat16* __restrict__ qh, __nv_bfloat16* __restrict__ ql,
    __nv_bfloat16* __restrict__ kh, __nv_bfloat16* __restrict__ kl,
    __nv_bfloat16* __restrict__ vh, __nv_bfloat16* __restrict__ vl)
{
    const int row = blockIdx.x;          // 0..2047
    const int b = row >> 10, t = row & 1023;
    const int tid = threadIdx.x;
    const float* crow = cosp + (size_t)t * HD;
    const float* srow = sinp + (size_t)t * HD;

    // Q: rope, scale by ASCALE, split, store [b,h,t,d]
    for (int idx = tid; idx < NH * 64; idx += 256) {
        int h = idx >> 6, d = idx & 63;
        float x0 = Qr[(size_t)row * (NH * HD) + h * HD + d];
        float x1 = Qr[(size_t)row * (NH * HD) + h * HD + d + 64];
        float o0 = (x0 * crow[d]      - x1 * srow[d])      * ASCALE;
        float o1 = (x1 * crow[d + 64] + x0 * srow[d + 64]) * ASCALE;
        size_t base = ((size_t)(b * NH + h) * QL + t) * HD;
        __nv_bfloat16 h0 = __float2bfloat16(o0), h1 = __float2bfloat16(o1);
        qh[base + d]      = h0; ql[base + d]      = __float2bfloat16(o0 - __bfloat162float(h0));
        qh[base + d + 64] = h1; ql[base + d + 64] = __float2bfloat16(o1 - __bfloat162float(h1));
    }

    const int blk  = ctx_ptrs[b * (QL / BLKSZ) + (t >> 4)];
    const int rrow = t & 15;

    // K: rope, split, scatter into bf16 cache
    for (int idx = tid; idx < NKV * 64; idx += 256) {
        int h = idx >> 6, d = idx & 63;
        float x0 = Kr[(size_t)row * (NKV * HD) + h * HD + d];
        float x1 = Kr[(size_t)row * (NKV * HD) + h * HD + d + 64];
        float o0 = x0 * crow[d]      - x1 * srow[d];
        float o1 = x1 * crow[d + 64] + x0 * srow[d + 64];
        size_t base = (((size_t)blk * NKV + h) * BLKSZ + rrow) * HD;
        __nv_bfloat16 h0 = __float2bfloat16(o0), h1 = __float2bfloat16(o1);
        kh[base + d]      = h0; kl[base + d]      = __float2bfloat16(o0 - __bfloat162float(h0));
        kh[base + d + 64] = h1; kl[base + d + 64] = __float2bfloat16(o1 - __bfloat162float(h1));
    }

    // V: split, scatter
    for (int idx = tid; idx < NKV * HD; idx += 256) {
        int h = idx >> 7, d = idx & 127;
        float x = Vr[(size_t)row * (NKV * HD) + h * HD + d];
        size_t base = (((size_t)blk * NKV + h) * BLKSZ + rrow) * HD;
        __nv_bfloat16 h0 = __float2bfloat16(x);
        vh[base + d] = h0; vl[base + d] = __float2bfloat16(x - __bfloat162float(h0));
    }
}

// ---------------- flash attention: split-bf16 HMMA + exp2 online softmax ----------------
// CTA: 128 threads (4 warps), q-tile 64 (16 rows/warp), kv-tile 64.
// smem tiles [64][128] bf16, swizzle: 16B-chunk ^= (row&7).  Q(hi,lo) + KV(hi,lo) = 64KB.
#define ATT_SMEM2 (4 * 64 * 128 * 2)

__global__ __launch_bounds__(128, 3) void attn_mma(
    const __nv_bfloat16* __restrict__ gqh, const __nv_bfloat16* __restrict__ gql,
    const __nv_bfloat16* __restrict__ gkh, const __nv_bfloat16* __restrict__ gkl,
    const __nv_bfloat16* __restrict__ gvh, const __nv_bfloat16* __restrict__ gvl,
    const int* __restrict__ kvlut, const int* __restrict__ prefix_ptr,
    __nv_bfloat16* __restrict__ ohi, __nv_bfloat16* __restrict__ olo)
{
    extern __shared__ __align__(16) char dynsm[];
    __nv_bfloat16* sQh = (__nv_bfloat16*)dynsm;
    __nv_bfloat16* sQl = sQh + 64 * 128;
    __nv_bfloat16* sKh = sQl + 64 * 128;   // reused for Vhi
    __nv_bfloat16* sKl = sKh + 64 * 128;   // reused for Vlo
    const uint32_t bQh = smem_u32(sQh), bQl = smem_u32(sQl);
    const uint32_t bKh = smem_u32(sKh), bKl = smem_u32(sKl);

    const int qtile = blockIdx.x, h = blockIdx.y, b = blockIdx.z;
    const int kvh = h >> 2;
    const int prefix = prefix_ptr ? *prefix_ptr : 3072;
    const int tid = threadIdx.x;
    const int warp = tid >> 5, lane = tid & 31;
    const int qr = warp * 16;
    const int q0 = qtile * 64;
    const int* lut = kvlut + b * (SEQ / BLKSZ);

    // load Q tile (hi, lo), swizzled
    {
        const __nv_bfloat16* srch = gqh + ((size_t)(b * NH + h) * QL + q0) * HD;
        const __nv_bfloat16* srcl = gql + ((size_t)(b * NH + h) * QL + q0) * HD;
        for (int i = tid; i < 64 * 16; i += 128) {
            int row = i >> 4, c = i & 15;
            int phys = (c ^ (row & 7)) << 3;
            *(uint4*)&sQh[row * 128 + phys] = *(const uint4*)(srch + (size_t)row * HD + c * 8);
            *(uint4*)&sQl[row * 128 + phys] = *(const uint4*)(srcl + (size_t)row * HD + c * 8);
        }
    }

    float O[16][4];
#pragma unroll
    for (int i = 0; i < 16; i++)
#pragma unroll
        for (int e = 0; e < 4; e++) O[i][e] = 0.f;
    float m0 = -1e30f, m1 = -1e30f, l0 = 0.f, l1 = 0.f;

    const int plim = prefix + q0;
    const int kv_end = plim + 64;
    const int qa0 = plim + qr + (lane >> 2);
    const int qa1 = qa0 + 8;

    for (int s0 = 0; s0 < kv_end; s0 += 64) {
        __syncthreads();   // prior V readers done before overwrite
        // load K tile (hi, lo) via LUT gather
        for (int i = tid; i < 64 * 16; i += 128) {
            int row = i >> 4, c = i & 15;
            int s = s0 + row;
            int blk = lut[s >> 4];
            size_t base = (((size_t)blk * NKV + kvh) * BLKSZ + (s & 15)) * HD + c * 8;
            int phys = (c ^ (row & 7)) << 3;
            *(uint4*)&sKh[row * 128 + phys] = *(const uint4*)(gkh + base);
            *(uint4*)&sKl[row * 128 + phys] = *(const uint4*)(gkl + base);
        }
        __syncthreads();

        // ---- S = Q K^T, 3-term split ----
        float S[8][4];
#pragma unroll
        for (int i = 0; i < 8; i++)
#pragma unroll
            for (int e = 0; e < 4; e++) S[i][e] = 0.f;

#pragma unroll
        for (int ks = 0; ks < 8; ks++) {
            uint32_t ah[4], al[4];
            {
                int arow = qr + (lane & 15);
                int ac = ks * 2 + (lane >> 4);
                uint32_t aoff = (uint32_t)(arow * 128 + ((ac ^ (arow & 7)) << 3)) * 2;
                ldsm4(ah, bQh + aoff);
                ldsm4(al, bQl + aoff);
            }
            int brow_b = (lane & 7) + ((lane >> 4) << 3);
            int bc = ks * 2 + ((lane >> 3) & 1);
#pragma unroll
            for (int ng = 0; ng < 4; ng++) {
                int brow = ng * 16 + brow_b;
                uint32_t boff = (uint32_t)(brow * 128 + ((bc ^ (brow & 7)) << 3)) * 2;
                uint32_t kh[4], kl[4];
                ldsm4(kh, bKh + boff);
                ldsm4(kl, bKl + boff);
                mma_bf16(S[2 * ng],     ah, kh[0], kh[1]);
                mma_bf16(S[2 * ng],     ah, kl[0], kl[1]);
                mma_bf16(S[2 * ng],     al, kh[0], kh[1]);
                mma_bf16(S[2 * ng + 1], ah, kh[2], kh[3]);
                mma_bf16(S[2 * ng + 1], ah, kl[2], kl[3]);
                mma_bf16(S[2 * ng + 1], al, kh[2], kh[3]);
            }
        }

        // ---- causal mask (last tile only) ----
        if (s0 + 63 > plim) {
#pragma unroll
            for (int nt = 0; nt < 8; nt++) {
                int colb = s0 + nt * 8 + ((lane & 3) << 1);
                if (colb     > qa0) S[nt][0] = -1e30f;
                if (colb + 1 > qa0) S[nt][1] = -1e30f;
                if (colb     > qa1) S[nt][2] = -1e30f;
                if (colb + 1 > qa1) S[nt][3] = -1e30f;
            }
        }

        // ---- online softmax (base-2 domain) ----
        float mx0 = -1e30f, mx1 = -1e30f;
#pragma unroll
        for (int nt = 0; nt < 8; nt++) {
            mx0 = fmaxf(mx0, fmaxf(S[nt][0], S[nt][1]));
            mx1 = fmaxf(mx1, fmaxf(S[nt][2], S[nt][3]));
        }
        mx0 = fmaxf(mx0, __shfl_xor_sync(0xffffffffu, mx0, 1));
        mx0 = fmaxf(mx0, __shfl_xor_sync(0xffffffffu, mx0, 2));
        mx1 = fmaxf(mx1, __shfl_xor_sync(0xffffffffu, mx1, 1));
        mx1 = fmaxf(mx1, __shfl_xor_sync(0xffffffffu, mx1, 2));
        float mn0 = fmaxf(m0, mx0), mn1 = fmaxf(m1, mx1);
        float f0 = ex2f(m0 - mn0), f1 = ex2f(m1 - mn1);
        m0 = mn0; m1 = mn1;

        float rs0 = 0.f, rs1 = 0.f;
#pragma unroll
        for (int nt = 0; nt < 8; nt++) {
            S[nt][0] = ex2f(S[nt][0] - mn0); rs0 += S[nt][0];
            S[nt][1] = ex2f(S[nt][1] - mn0); rs0 += S[nt][1];
            S[nt][2] = ex2f(S[nt][2] - mn1); rs1 += S[nt][2];
            S[nt][3] = ex2f(S[nt][3] - mn1); rs1 += S[nt][3];
        }
        rs0 += __shfl_xor_sync(0xffffffffu, rs0, 1);
        rs0 += __shfl_xor_sync(0xffffffffu, rs0, 2);
        rs1 += __shfl_xor_sync(0xffffffffu, rs1, 1);
        rs1 += __shfl_xor_sync(0xffffffffu, rs1, 2);
        l0 = l0 * f0 + rs0;
        l1 = l1 * f1 + rs1;

#pragma unroll
        for (int nt = 0; nt < 16; nt++) {
            O[nt][0] *= f0; O[nt][1] *= f0; O[nt][2] *= f1; O[nt][3] *= f1;
        }

        // ---- split P into bf16 hi/lo A-fragments ----
        uint32_t PH[4][4], PL[4][4];
#pragma unroll
        for (int kt = 0; kt < 4; kt++) {
            int e = 2 * kt, o = 2 * kt + 1;
            float h00 = __bfloat162float(__float2bfloat16(S[e][0]));
            float h01 = __bfloat162float(__float2bfloat16(S[e][1]));
            float h02 = __bfloat162float(__float2bfloat16(S[e][2]));
            float h03 = __bfloat162float(__float2bfloat16(S[e][3]));
            float h10 = __bfloat162float(__float2bfloat16(S[o][0]));
            float h11 = __bfloat162float(__float2bfloat16(S[o][1]));
            float h12 = __bfloat162float(__float2bfloat16(S[o][2]));
            float h13 = __bfloat162float(__float2bfloat16(S[o][3]));
            PH[kt][0] = packbf2(h00, h01);
            PH[kt][1] = packbf2(h02, h03);
            PH[kt][2] = packbf2(h10, h11);
            PH[kt][3] = packbf2(h12, h13);
            PL[kt][0] = packbf2(S[e][0] - h00, S[e][1] - h01);
            PL[kt][1] = packbf2(S[e][2] - h02, S[e][3] - h03);
            PL[kt][2] = packbf2(S[o][0] - h10, S[o][1] - h11);
            PL[kt][3] = packbf2(S[o][2] - h12, S[o][3] - h13);
        }

        __syncthreads();   // all warps done reading K smem
        // load V tile (hi, lo) into same smem
        for (int i = tid; i < 64 * 16; i += 128) {
            int row = i >> 4, c = i & 15;
            int s = s0 + row;
            int blk = lut[s >> 4];
            size_t base = (((size_t)blk * NKV + kvh) * BLKSZ + (s & 15)) * HD + c * 8;
            int phys = (c ^ (row & 7)) << 3;
            *(uint4*)&sKh[row * 128 + phys] = *(const uint4*)(gvh + base);
            *(uint4*)&sKl[row * 128 + phys] = *(const uint4*)(gvl + base);
        }
        __syncthreads();

        // ---- O += P V, 3-term split ----
#pragma unroll
        for (int kt = 0; kt < 4; kt++) {
            int vrow = kt * 16 + (((lane >> 3) & 1) << 3) + (lane & 7);
            int vc0 = lane >> 4;
#pragma unroll
            for (int vg = 0; vg < 8; vg++) {
                int c = vg * 2 + vc0;
                uint32_t off = (uint32_t)(vrow * 128 + ((c ^ (vrow & 7)) << 3)) * 2;
                uint32_t vh[4], vl[4];
                ldsm4t(vh, bKh + off);
                ldsm4t(vl, bKl + off);
                mma_bf16(O[2 * vg],     PH[kt], vh[0], vh[1]);
                mma_bf16(O[2 * vg],     PH[kt], vl[0], vl[1]);
                mma_bf16(O[2 * vg],     PL[kt], vh[0], vh[1]);
                mma_bf16(O[2 * vg + 1], PH[kt], vh[2], vh[3]);
                mma_bf16(O[2 * vg + 1], PH[kt], vl[2], vl[3]);
                mma_bf16(O[2 * vg + 1], PL[kt], vh[2], vh[3]);
            }
        }
    }

    // ---- epilogue: normalize, split hi/lo, write [b,t,h*128+d] ----
    float inv0 = 1.f / l0, inv1 = 1.f / l1;
    int r0 = q0 + qr + (lane >> 2);
    int r1 = r0 + 8;
#pragma unroll
    for (int nt = 0; nt < 16; nt++) {
        int d = h * HD + nt * 8 + ((lane & 3) << 1);
        {
            float a = O[nt][0] * inv0, bb = O[nt][1] * inv0;
            float ha = __bfloat162float(__float2bfloat16(a));
            float hb = __bfloat162float(__float2bfloat16(bb));
            size_t base = (size_t)(b * QL + r0) * HID + d;
            *(uint32_t*)(ohi + base) = packbf2(a, bb);
            *(uint32_t*)(olo + base) = packbf2(a - ha, bb - hb);
        }
        {
            float a = O[nt][2] * inv1, bb = O[nt][3] * inv1;
            float ha = __bfloat162float(__float2bfloat16(a));
            float hb = __bfloat162float(__float2bfloat16(bb));
            size_t base = (size_t)(b * QL + r1) * HID + d;
            *(uint32_t*)(ohi + base) = packbf2(a, bb);
            *(uint32_t*)(olo + base) = packbf2(a - ha, bb - hb);
        }
    }
}

// ---------------- launcher ----------------
extern "C" void kernel_launch(void* const* d_in, const int* in_sizes, int n_in,
                              void* d_out, int out_size)
{
    const float* hidden = (const float*)d_in[0];
    const float* Wq     = (const float*)d_in[1];
    const float* Wk     = (const float*)d_in[2];
    const float* Wv     = (const float*)d_in[3];
    const float* Wo     = (const float*)d_in[4];
    const float* cosp   = (const float*)d_in[5];
    const float* sinp   = (const float*)d_in[6];
    const float* kstore = (const float*)d_in[7];
    const float* vstore = (const float*)d_in[8];
    const int*   kvlut  = (const int*)d_in[9];
    const int*   ctxptr = (const int*)d_in[10];
    const int*   prefix = (n_in >= 12) ? (const int*)d_in[11] : nullptr;
    float* out = (float*)d_out;

    float *qraw, *kraw, *vraw;
    __nv_bfloat16 *xhi, *xlo, *whi, *wlo, *qhi, *qlo, *khi, *klo, *vhi, *vlo;
    cudaGetSymbolAddress((void**)&qraw, g_qraw);
    cudaGetSymbolAddress((void**)&kraw, g_kraw);
    cudaGetSymbolAddress((void**)&vraw, g_vraw);
    cudaGetSymbolAddress((void**)&xhi,  g_xhi);
    cudaGetSymbolAddress((void**)&xlo,  g_xlo);
    cudaGetSymbolAddress((void**)&whi,  g_whi);
    cudaGetSymbolAddress((void**)&wlo,  g_wlo);
    cudaGetSymbolAddress((void**)&qhi,  g_qhi);
    cudaGetSymbolAddress((void**)&qlo,  g_qlo);
    cudaGetSymbolAddress((void**)&khi,  g_khi);
    cudaGetSymbolAddress((void**)&klo,  g_klo);
    cudaGetSymbolAddress((void**)&vhi,  g_vhi);
    cudaGetSymbolAddress((void**)&vlo,  g_vlo);

    cudaFuncSetAttribute(attn_mma, cudaFuncAttributeMaxDynamicSharedMemorySize, ATT_SMEM2);

    // hi/lo splits: activations + weights
    {
        int n4;
        n4 = MROWS * HID / 4;
        split2<<<(n4 + 255) / 256, 256>>>(hidden, xhi, xlo, n4);
        n4 = (NH * HD) * HID / 4;
        split2<<<(n4 + 255) / 256, 256>>>(Wq, whi + WOFF_Q, wlo + WOFF_Q, n4);
        n4 = (NKV * HD) * HID / 4;
        split2<<<(n4 + 255) / 256, 256>>>(Wk, whi + WOFF_K, wlo + WOFF_K, n4);
        split2<<<(n4 + 255) / 256, 256>>>(Wv, whi + WOFF_V, wlo + WOFF_V, n4);
        n4 = HID * HID / 4;
        split2<<<(n4 + 255) / 256, 256>>>(Wo, whi + WOFF_O, wlo + WOFF_O, n4);
    }
    // KV storage -> split bf16 caches (before scatter overwrites ctx blocks)
    {
        int n4 = (int)((size_t)NBLK * NKV * BLKSZ * HD / 4);
        split2<<<(n4 + 255) / 256, 256>>>(kstore, khi, klo, n4);
        split2<<<(n4 + 255) / 256, 256>>>(vstore, vhi, vlo, n4);
    }

    // projections via mma.sync bf16-split
    gemm_mma_split<<<dim3((NH * HD) / 128,  MROWS / 128), 256>>>(
        xhi, xlo, whi + WOFF_Q, wlo + WOFF_Q, qraw, MROWS, NH * HD, HID);
    gemm_mma_split<<<dim3((NKV * HD) / 128, MROWS / 128), 256>>>(
        xhi, xlo, whi + WOFF_K, wlo + WOFF_K, kraw, MROWS, NKV * HD, HID);
    gemm_mma_split<<<dim3((NKV * HD) / 128, MROWS / 128), 256>>>(
        xhi, xlo, whi + WOFF_V, wlo + WOFF_V, vraw, MROWS, NKV * HD, HID);

    // RoPE + split + scatter
    rope_scatter_bf16<<<MROWS, 256>>>(qraw, kraw, vraw, cosp, sinp, ctxptr,
                                      qhi, qlo, khi, klo, vhi, vlo);

    // attention (writes split output directly into xhi/xlo)
    attn_mma<<<dim3(QL / 64, NH, BSZ), 128, ATT_SMEM2>>>(
        qhi, qlo, khi, klo, vhi, vlo, kvlut, prefix, xhi, xlo);

    // O projection
    gemm_mma_split<<<dim3(HID / 128, MROWS / 128), 256>>>(
        xhi, xlo, whi + WOFF_O, wlo + WOFF_O, out, MROWS, HID, HID);
}

// round 6
// speedup vs baseline: 2.7095x; 1.0137x over previous
#include <cuda_runtime.h>
#include <cuda_bf16.h>
#include <cstdint>

// ---------------- problem dims ----------------
#define BSZ   2
#define QL    1024
#define HID   4096
#define NH    32
#define NKV   8
#define HD    128
#define NBLK  512
#define BLKSZ 16
#define SEQ   4096
#define MROWS (BSZ*QL)                 // 2048
#define QKVN  (NH*HD + 2*NKV*HD)       // 6144
#define WROWS (QKVN + HID)             // 10240
#define WOFF_Q 0
#define WOFF_K ((size_t)(NH*HD) * HID)
#define WOFF_V ((size_t)(NH*HD + NKV*HD) * HID)
#define WOFF_O ((size_t)QKVN * HID)

// q pre-scale: (1/sqrt(128)) * log2(e)  -> softmax in exp2 domain
#define ASCALE ((float)(0.08838834764831845 * 1.4426950408889634))

// ---------------- device scratch ----------------
__device__ float g_qkv [(size_t)MROWS * QKVN];   // fused QKV projection output
__device__ __nv_bfloat16 g_xhi[(size_t)MROWS * HID];
__device__ __nv_bfloat16 g_xlo[(size_t)MROWS * HID];
__device__ __nv_bfloat16 g_whi[(size_t)WROWS * HID];
__device__ __nv_bfloat16 g_wlo[(size_t)WROWS * HID];
__device__ __nv_bfloat16 g_qhi[(size_t)BSZ * NH * QL * HD];
__device__ __nv_bfloat16 g_qlo[(size_t)BSZ * NH * QL * HD];
__device__ __nv_bfloat16 g_khi[(size_t)NBLK * NKV * BLKSZ * HD];
__device__ __nv_bfloat16 g_klo[(size_t)NBLK * NKV * BLKSZ * HD];
__device__ __nv_bfloat16 g_vhi[(size_t)NBLK * NKV * BLKSZ * HD];
__device__ __nv_bfloat16 g_vlo[(size_t)NBLK * NKV * BLKSZ * HD];

// ---------------- helpers ----------------
__device__ __forceinline__ uint32_t smem_u32(const void* p) {
    uint32_t a;
    asm("{ .reg .u64 t; cvta.to.shared.u64 t, %1; cvt.u32.u64 %0, t; }" : "=r"(a) : "l"(p));
    return a;
}
__device__ __forceinline__ void ldsm4(uint32_t* r, uint32_t addr) {
    asm volatile("ldmatrix.sync.aligned.m8n8.x4.shared.b16 {%0,%1,%2,%3}, [%4];"
                 : "=r"(r[0]), "=r"(r[1]), "=r"(r[2]), "=r"(r[3]) : "r"(addr));
}
__device__ __forceinline__ void ldsm4t(uint32_t* r, uint32_t addr) {
    asm volatile("ldmatrix.sync.aligned.m8n8.x4.trans.shared.b16 {%0,%1,%2,%3}, [%4];"
                 : "=r"(r[0]), "=r"(r[1]), "=r"(r[2]), "=r"(r[3]) : "r"(addr));
}
__device__ __forceinline__ void mma_bf16(float* c, const uint32_t* a, uint32_t b0, uint32_t b1) {
    asm volatile("mma.sync.aligned.m16n8k16.row.col.f32.bf16.bf16.f32 "
                 "{%0,%1,%2,%3}, {%4,%5,%6,%7}, {%8,%9}, {%0,%1,%2,%3};"
                 : "+f"(c[0]), "+f"(c[1]), "+f"(c[2]), "+f"(c[3])
                 : "r"(a[0]), "r"(a[1]), "r"(a[2]), "r"(a[3]), "r"(b0), "r"(b1));
}
__device__ __forceinline__ float ex2f(float x) {
    float y; asm("ex2.approx.ftz.f32 %0, %1;" : "=f"(y) : "f"(x)); return y;
}
__device__ __forceinline__ uint32_t packbf2(float a, float b) {
    __nv_bfloat162 t = __floats2bfloat162_rn(a, b);
    return *(uint32_t*)&t;
}
__device__ __forceinline__ void cpasync16(uint32_t dst, const void* src) {
    asm volatile("cp.async.cg.shared.global [%0], [%1], 16;" :: "r"(dst), "l"(src));
}
#define CP_COMMIT() asm volatile("cp.async.commit_group;" ::: "memory")
#define CP_WAIT1()  asm volatile("cp.async.wait_group 1;" ::: "memory")
#define CP_WAIT0()  asm volatile("cp.async.wait_group 0;" ::: "memory")

// ---------------- fp32 -> bf16 hi/lo split ----------------
__global__ __launch_bounds__(256) void split2(const float* __restrict__ x,
                                              __nv_bfloat16* __restrict__ hi,
                                              __nv_bfloat16* __restrict__ lo, int n4)
{
    int i = blockIdx.x * 256 + threadIdx.x;
    if (i >= n4) return;
    float4 v = *(const float4*)(x + (size_t)i * 4);
    __nv_bfloat16 h0 = __float2bfloat16(v.x), h1 = __float2bfloat16(v.y);
    __nv_bfloat16 h2 = __float2bfloat16(v.z), h3 = __float2bfloat16(v.w);
    __nv_bfloat16 l0 = __float2bfloat16(v.x - __bfloat162float(h0));
    __nv_bfloat16 l1 = __float2bfloat16(v.y - __bfloat162float(h1));
    __nv_bfloat16 l2 = __float2bfloat16(v.z - __bfloat162float(h2));
    __nv_bfloat16 l3 = __float2bfloat16(v.w - __bfloat162float(h3));
    __nv_bfloat162* hp = (__nv_bfloat162*)(hi + (size_t)i * 4);
    __nv_bfloat162* lp = (__nv_bfloat162*)(lo + (size_t)i * 4);
    hp[0] = __nv_bfloat162(h0, h1); hp[1] = __nv_bfloat162(h2, h3);
    lp[0] = __nv_bfloat162(l0, l1); lp[1] = __nv_bfloat162(l2, l3);
}

// ---------------- pipelined mma.sync bf16 3-term split GEMM ----------------
// C[M,N] = A[M,K]*B[N,K]^T, fp32 acc. Tile 128x128x32, 8 warps (4M x 2N).
// Double-buffered smem via cp.async.cg; swizzle: 16B chunk ^= (row>>1)&3.
#define TBYTES 8192                 // one 128x32 bf16 tile
#define BUFBYTES (4 * TBYTES)       // Ah, Al, Bh, Bl

__global__ __launch_bounds__(256) void gemm_mma_split(
    const __nv_bfloat16* __restrict__ Ahi, const __nv_bfloat16* __restrict__ Alo,
    const __nv_bfloat16* __restrict__ Bhi, const __nv_bfloat16* __restrict__ Blo,
    float* __restrict__ C, int M, int N, int K)
{
    __shared__ __nv_bfloat16 smem[2][4][128 * 32];   // 64KB

    const int tid  = threadIdx.x;
    const int warp = tid >> 5, lane = tid & 31;
    const int wm = warp & 3, wn = warp >> 2;
    const int bm = blockIdx.y * 128, bn = blockIdx.x * 128;
    const uint32_t sb = smem_u32(smem);

    float acc[2][8][4];
#pragma unroll
    for (int i = 0; i < 2; i++)
#pragma unroll
        for (int j = 0; j < 8; j++)
#pragma unroll
            for (int e = 0; e < 4; e++) acc[i][j][e] = 0.f;

    const __nv_bfloat16* g0 = Ahi + (size_t)bm * K;
    const __nv_bfloat16* g1 = Alo + (size_t)bm * K;
    const __nv_bfloat16* g2 = Bhi + (size_t)bn * K;
    const __nv_bfloat16* g3 = Blo + (size_t)bn * K;

    // per-thread load geometry (2 positions x 4 tensors, 16B each)
    int rowA = tid >> 2, kcA = tid & 3;
    int rowB = (tid + 256) >> 2, kcB = (tid + 256) & 3;
    uint32_t soffA = (uint32_t)(rowA * 32 + (((kcA + (rowA >> 1)) & 3) * 8)) * 2;
    uint32_t soffB = (uint32_t)(rowB * 32 + (((kcB + (rowB >> 1)) & 3) * 8)) * 2;

    const int nch = K / 32;

#define ISSUE_LOAD(buf, k0)                                                    \
    do {                                                                       \
        size_t gA = (size_t)rowA * K + (k0) + kcA * 8;                         \
        size_t gB = (size_t)rowB * K + (k0) + kcB * 8;                         \
        uint32_t base = sb + (buf) * BUFBYTES;                                 \
        cpasync16(base + 0 * TBYTES + soffA, g0 + gA);                         \
        cpasync16(base + 1 * TBYTES + soffA, g1 + gA);                         \
        cpasync16(base + 2 * TBYTES + soffA, g2 + gA);                         \
        cpasync16(base + 3 * TBYTES + soffA, g3 + gA);                         \
        cpasync16(base + 0 * TBYTES + soffB, g0 + gB);                         \
        cpasync16(base + 1 * TBYTES + soffB, g1 + gB);                         \
        cpasync16(base + 2 * TBYTES + soffB, g2 + gB);                         \
        cpasync16(base + 3 * TBYTES + soffB, g3 + gB);                         \
        CP_COMMIT();                                                           \
    } while (0)

    ISSUE_LOAD(0, 0);

    for (int ch = 0; ch < nch; ch++) {
        const int buf = ch & 1;
        if (ch + 1 < nch) {
            ISSUE_LOAD(buf ^ 1, (ch + 1) * 32);
            CP_WAIT1();
        } else {
            CP_WAIT0();
        }
        __syncthreads();

        const uint32_t aHi = sb + buf * BUFBYTES;
        const uint32_t aLo = aHi + TBYTES;
        const uint32_t bHi = aHi + 2 * TBYTES;
        const uint32_t bLo = aHi + 3 * TBYTES;

#pragma unroll
        for (int ks = 0; ks < 2; ks++) {
            uint32_t ah[2][4], al[2][4];
            {
                int r  = wm * 32 + (lane & 15);
                int cd = ks * 2 + (lane >> 4);
#pragma unroll
                for (int mt = 0; mt < 2; mt++) {
                    int row  = r + mt * 16;
                    int phys = (cd + (row >> 1)) & 3;
                    uint32_t off = (uint32_t)(row * 32 + phys * 8) * 2;
                    ldsm4(ah[mt], aHi + off);
                    ldsm4(al[mt], aLo + off);
                }
            }
#pragma unroll
            for (int nt4 = 0; nt4 < 4; nt4++) {
                int n    = wn * 64 + nt4 * 16 + (lane & 7) + ((lane >> 4) << 3);
                int cd   = ks * 2 + ((lane >> 3) & 1);
                int phys = (cd + (n >> 1)) & 3;
                uint32_t off = (uint32_t)(n * 32 + phys * 8) * 2;
                uint32_t bh[4], bl[4];
                ldsm4(bh, bHi + off);
                ldsm4(bl, bLo + off);
#pragma unroll
                for (int mt = 0; mt < 2; mt++) {
#pragma unroll
                    for (int p = 0; p < 2; p++) {
                        float* cc = acc[mt][nt4 * 2 + p];
                        mma_bf16(cc, ah[mt], bh[2 * p], bh[2 * p + 1]);
                        mma_bf16(cc, ah[mt], bl[2 * p], bl[2 * p + 1]);
                        mma_bf16(cc, al[mt], bh[2 * p], bh[2 * p + 1]);
                    }
                }
            }
        }
        __syncthreads();
    }
#undef ISSUE_LOAD

#pragma unroll
    for (int mt = 0; mt < 2; mt++) {
#pragma unroll
        for (int nt = 0; nt < 8; nt++) {
            int row = bm + wm * 32 + mt * 16 + (lane >> 2);
            int col = bn + wn * 64 + nt * 8 + (lane & 3) * 2;
            float* cc = acc[mt][nt];
            *(float2*)&C[(size_t)row * N + col]       = make_float2(cc[0], cc[1]);
            *(float2*)&C[(size_t)(row + 8) * N + col] = make_float2(cc[2], cc[3]);
        }
    }
}

// ---------------- RoPE + bf16 split + cache scatter (fused-QKV input) ----------------
__global__ __launch_bounds__(256) void rope_scatter_bf16(
    const float* __restrict__ QKV,
    const float* __restrict__ cosp, const float* __restrict__ sinp,
    const int* __restrict__ ctx_ptrs,
    __nv_bfloat16* __restrict__ qh, __nv_bfloat16* __restrict__ ql,
    __nv_bfloat16* __restrict__ kh, __nv_bfloat16* __restrict__ kl,
    __nv_bfloat16* __restrict__ vh, __nv_bfloat16* __restrict__ vl)
{
    const int row = blockIdx.x;          // 0..2047
    const int b = row >> 10, t = row & 1023;
    const int tid = threadIdx.x;
    const float* crow = cosp + (size_t)t * HD;
    const float* srow = sinp + (size_t)t * HD;
    const float* Qr = QKV + (size_t)row * QKVN;
    const float* Kr = Qr + NH * HD;
    const float* Vr = Kr + NKV * HD;

    // Q: rope, scale, split, store [b,h,t,d]
    for (int idx = tid; idx < NH * 64; idx += 256) {
        int h = idx >> 6, d = idx & 63;
        float x0 = Qr[h * HD + d];
        float x1 = Qr[h * HD + d + 64];
        float o0 = (x0 * crow[d]      - x1 * srow[d])      * ASCALE;
        float o1 = (x1 * crow[d + 64] + x0 * srow[d + 64]) * ASCALE;
        size_t base = ((size_t)(b * NH + h) * QL + t) * HD;
        __nv_bfloat16 h0 = __float2bfloat16(o0), h1 = __float2bfloat16(o1);
        qh[base + d]      = h0; ql[base + d]      = __float2bfloat16(o0 - __bfloat162float(h0));
        qh[base + d + 64] = h1; ql[base + d + 64] = __float2bfloat16(o1 - __bfloat162float(h1));
    }

    const int blk  = ctx_ptrs[b * (QL / BLKSZ) + (t >> 4)];
    const int rrow = t & 15;

    // K: rope, split, scatter
    for (int idx = tid; idx < NKV * 64; idx += 256) {
        int h = idx >> 6, d = idx & 63;
        float x0 = Kr[h * HD + d];
        float x1 = Kr[h * HD + d + 64];
        float o0 = x0 * crow[d]      - x1 * srow[d];
        float o1 = x1 * crow[d + 64] + x0 * srow[d + 64];
        size_t base = (((size_t)blk * NKV + h) * BLKSZ + rrow) * HD;
        __nv_bfloat16 h0 = __float2bfloat16(o0), h1 = __float2bfloat16(o1);
        kh[base + d]      = h0; kl[base + d]      = __float2bfloat16(o0 - __bfloat162float(h0));
        kh[base + d + 64] = h1; kl[base + d + 64] = __float2bfloat16(o1 - __bfloat162float(h1));
    }

    // V: split, scatter
    for (int idx = tid; idx < NKV * HD; idx += 256) {
        int h = idx >> 7, d = idx & 127;
        float x = Vr[h * HD + d];
        size_t base = (((size_t)blk * NKV + h) * BLKSZ + rrow) * HD;
        __nv_bfloat16 h0 = __float2bfloat16(x);
        vh[base + d] = h0; vl[base + d] = __float2bfloat16(x - __bfloat162float(h0));
    }
}

// ---------------- flash attention: split-bf16 HMMA + exp2 online softmax ----------------
#define ATT_SMEM2 (4 * 64 * 128 * 2)

__global__ __launch_bounds__(128, 3) void attn_mma(
    const __nv_bfloat16* __restrict__ gqh, const __nv_bfloat16* __restrict__ gql,
    const __nv_bfloat16* __restrict__ gkh, const __nv_bfloat16* __restrict__ gkl,
    const __nv_bfloat16* __restrict__ gvh, const __nv_bfloat16* __restrict__ gvl,
    const int* __restrict__ kvlut, const int* __restrict__ prefix_ptr,
    __nv_bfloat16* __restrict__ ohi, __nv_bfloat16* __restrict__ olo)
{
    extern __shared__ __align__(16) char dynsm[];
    __nv_bfloat16* sQh = (__nv_bfloat16*)dynsm;
    __nv_bfloat16* sQl = sQh + 64 * 128;
    __nv_bfloat16* sKh = sQl + 64 * 128;
    __nv_bfloat16* sKl = sKh + 64 * 128;
    const uint32_t bQh = smem_u32(sQh), bQl = smem_u32(sQl);
    const uint32_t bKh = smem_u32(sKh), bKl = smem_u32(sKl);

    const int qtile = blockIdx.x, h = blockIdx.y, b = blockIdx.z;
    const int kvh = h >> 2;
    const int prefix = prefix_ptr ? *prefix_ptr : 3072;
    const int tid = threadIdx.x;
    const int warp = tid >> 5, lane = tid & 31;
    const int qr = warp * 16;
    const int q0 = qtile * 64;
    const int* lut = kvlut + b * (SEQ / BLKSZ);

    {
        const __nv_bfloat16* srch = gqh + ((size_t)(b * NH + h) * QL + q0) * HD;
        const __nv_bfloat16* srcl = gql + ((size_t)(b * NH + h) * QL + q0) * HD;
        for (int i = tid; i < 64 * 16; i += 128) {
            int row = i >> 4, c = i & 15;
            int phys = (c ^ (row & 7)) << 3;
            *(uint4*)&sQh[row * 128 + phys] = *(const uint4*)(srch + (size_t)row * HD + c * 8);
            *(uint4*)&sQl[row * 128 + phys] = *(const uint4*)(srcl + (size_t)row * HD + c * 8);
        }
    }

    float O[16][4];
#pragma unroll
    for (int i = 0; i < 16; i++)
#pragma unroll
        for (int e = 0; e < 4; e++) O[i][e] = 0.f;
    float m0 = -1e30f, m1 = -1e30f, l0 = 0.f, l1 = 0.f;

    const int plim = prefix + q0;
    const int kv_end = plim + 64;
    const int qa0 = plim + qr + (lane >> 2);
    const int qa1 = qa0 + 8;

    for (int s0 = 0; s0 < kv_end; s0 += 64) {
        __syncthreads();
        for (int i = tid; i < 64 * 16; i += 128) {
            int row = i >> 4, c = i & 15;
            int s = s0 + row;
            int blk = lut[s >> 4];
            size_t base = (((size_t)blk * NKV + kvh) * BLKSZ + (s & 15)) * HD + c * 8;
            int phys = (c ^ (row & 7)) << 3;
            *(uint4*)&sKh[row * 128 + phys] = *(const uint4*)(gkh + base);
            *(uint4*)&sKl[row * 128 + phys] = *(const uint4*)(gkl + base);
        }
        __syncthreads();

        float S[8][4];
#pragma unroll
        for (int i = 0; i < 8; i++)
#pragma unroll
            for (int e = 0; e < 4; e++) S[i][e] = 0.f;

#pragma unroll
        for (int ks = 0; ks < 8; ks++) {
            uint32_t ah[4], al[4];
            {
                int arow = qr + (lane & 15);
                int ac = ks * 2 + (lane >> 4);
                uint32_t aoff = (uint32_t)(arow * 128 + ((ac ^ (arow & 7)) << 3)) * 2;
                ldsm4(ah, bQh + aoff);
                ldsm4(al, bQl + aoff);
            }
            int brow_b = (lane & 7) + ((lane >> 4) << 3);
            int bc = ks * 2 + ((lane >> 3) & 1);
#pragma unroll
            for (int ng = 0; ng < 4; ng++) {
                int brow = ng * 16 + brow_b;
                uint32_t boff = (uint32_t)(brow * 128 + ((bc ^ (brow & 7)) << 3)) * 2;
                uint32_t kh[4], kl[4];
                ldsm4(kh, bKh + boff);
                ldsm4(kl, bKl + boff);
                mma_bf16(S[2 * ng],     ah, kh[0], kh[1]);
                mma_bf16(S[2 * ng],     ah, kl[0], kl[1]);
                mma_bf16(S[2 * ng],     al, kh[0], kh[1]);
                mma_bf16(S[2 * ng + 1], ah, kh[2], kh[3]);
                mma_bf16(S[2 * ng + 1], ah, kl[2], kl[3]);
                mma_bf16(S[2 * ng + 1], al, kh[2], kh[3]);
            }
        }

        if (s0 + 63 > plim) {
#pragma unroll
            for (int nt = 0; nt < 8; nt++) {
                int colb = s0 + nt * 8 + ((lane & 3) << 1);
                if (colb     > qa0) S[nt][0] = -1e30f;
                if (colb + 1 > qa0) S[nt][1] = -1e30f;
                if (colb     > qa1) S[nt][2] = -1e30f;
                if (colb + 1 > qa1) S[nt][3] = -1e30f;
            }
        }

        float mx0 = -1e30f, mx1 = -1e30f;
#pragma unroll
        for (int nt = 0; nt < 8; nt++) {
            mx0 = fmaxf(mx0, fmaxf(S[nt][0], S[nt][1]));
            mx1 = fmaxf(mx1, fmaxf(S[nt][2], S[nt][3]));
        }
        mx0 = fmaxf(mx0, __shfl_xor_sync(0xffffffffu, mx0, 1));
        mx0 = fmaxf(mx0, __shfl_xor_sync(0xffffffffu, mx0, 2));
        mx1 = fmaxf(mx1, __shfl_xor_sync(0xffffffffu, mx1, 1));
        mx1 = fmaxf(mx1, __shfl_xor_sync(0xffffffffu, mx1, 2));
        float mn0 = fmaxf(m0, mx0), mn1 = fmaxf(m1, mx1);
        float f0 = ex2f(m0 - mn0), f1 = ex2f(m1 - mn1);
        m0 = mn0; m1 = mn1;

        float rs0 = 0.f, rs1 = 0.f;
#pragma unroll
        for (int nt = 0; nt < 8; nt++) {
            S[nt][0] = ex2f(S[nt][0] - mn0); rs0 += S[nt][0];
            S[nt][1] = ex2f(S[nt][1] - mn0); rs0 += S[nt][1];
            S[nt][2] = ex2f(S[nt][2] - mn1); rs1 += S[nt][2];
            S[nt][3] = ex2f(S[nt][3] - mn1); rs1 += S[nt][3];
        }
        rs0 += __shfl_xor_sync(0xffffffffu, rs0, 1);
        rs0 += __shfl_xor_sync(0xffffffffu, rs0, 2);
        rs1 += __shfl_xor_sync(0xffffffffu, rs1, 1);
        rs1 += __shfl_xor_sync(0xffffffffu, rs1, 2);
        l0 = l0 * f0 + rs0;
        l1 = l1 * f1 + rs1;

#pragma unroll
        for (int nt = 0; nt < 16; nt++) {
            O[nt][0] *= f0; O[nt][1] *= f0; O[nt][2] *= f1; O[nt][3] *= f1;
        }

        uint32_t PH[4][4], PL[4][4];
#pragma unroll
        for (int kt = 0; kt < 4; kt++) {
            int e = 2 * kt, o = 2 * kt + 1;
            float h00 = __bfloat162float(__float2bfloat16(S[e][0]));
            float h01 = __bfloat162float(__float2bfloat16(S[e][1]));
            float h02 = __bfloat162float(__float2bfloat16(S[e][2]));
            float h03 = __bfloat162float(__float2bfloat16(S[e][3]));
            float h10 = __bfloat162float(__float2bfloat16(S[o][0]));
            float h11 = __bfloat162float(__float2bfloat16(S[o][1]));
            float h12 = __bfloat162float(__float2bfloat16(S[o][2]));
            float h13 = __bfloat162float(__float2bfloat16(S[o][3]));
            PH[kt][0] = packbf2(h00, h01);
            PH[kt][1] = packbf2(h02, h03);
            PH[kt][2] = packbf2(h10, h11);
            PH[kt][3] = packbf2(h12, h13);
            PL[kt][0] = packbf2(S[e][0] - h00, S[e][1] - h01);
            PL[kt][1] = packbf2(S[e][2] - h02, S[e][3] - h03);
            PL[kt][2] = packbf2(S[o][0] - h10, S[o][1] - h11);
            PL[kt][3] = packbf2(S[o][2] - h12, S[o][3] - h13);
        }

        __syncthreads();
        for (int i = tid; i < 64 * 16; i += 128) {
            int row = i >> 4, c = i & 15;
            int s = s0 + row;
            int blk = lut[s >> 4];
            size_t base = (((size_t)blk * NKV + kvh) * BLKSZ + (s & 15)) * HD + c * 8;
            int phys = (c ^ (row & 7)) << 3;
            *(uint4*)&sKh[row * 128 + phys] = *(const uint4*)(gvh + base);
            *(uint4*)&sKl[row * 128 + phys] = *(const uint4*)(gvl + base);
        }
        __syncthreads();

#pragma unroll
        for (int kt = 0; kt < 4; kt++) {
            int vrow = kt * 16 + (((lane >> 3) & 1) << 3) + (lane & 7);
            int vc0 = lane >> 4;
#pragma unroll
            for (int vg = 0; vg < 8; vg++) {
                int c = vg * 2 + vc0;
                uint32_t off = (uint32_t)(vrow * 128 + ((c ^ (vrow & 7)) << 3)) * 2;
                uint32_t vh[4], vl[4];
                ldsm4t(vh, bKh + off);
                ldsm4t(vl, bKl + off);
                mma_bf16(O[2 * vg],     PH[kt], vh[0], vh[1]);
                mma_bf16(O[2 * vg],     PH[kt], vl[0], vl[1]);
                mma_bf16(O[2 * vg],     PL[kt], vh[0], vh[1]);
                mma_bf16(O[2 * vg + 1], PH[kt], vh[2], vh[3]);
                mma_bf16(O[2 * vg + 1], PH[kt], vl[2], vl[3]);
                mma_bf16(O[2 * vg + 1], PL[kt], vh[2], vh[3]);
            }
        }
    }

    float inv0 = 1.f / l0, inv1 = 1.f / l1;
    int r0 = q0 + qr + (lane >> 2);
    int r1 = r0 + 8;
#pragma unroll
    for (int nt = 0; nt < 16; nt++) {
        int d = h * HD + nt * 8 + ((lane & 3) << 1);
        {
            float a = O[nt][0] * inv0, bb = O[nt][1] * inv0;
            float ha = __bfloat162float(__float2bfloat16(a));
            float hb = __bfloat162float(__float2bfloat16(bb));
            size_t base = (size_t)(b * QL + r0) * HID + d;
            *(uint32_t*)(ohi + base) = packbf2(a, bb);
            *(uint32_t*)(olo + base) = packbf2(a - ha, bb - hb);
        }
        {
            float a = O[nt][2] * inv1, bb = O[nt][3] * inv1;
            float ha = __bfloat162float(__float2bfloat16(a));
            float hb = __bfloat162float(__float2bfloat16(bb));
            size_t base = (size_t)(b * QL + r1) * HID + d;
            *(uint32_t*)(ohi + base) = packbf2(a, bb);
            *(uint32_t*)(olo + base) = packbf2(a - ha, bb - hb);
        }
    }
}

// ---------------- launcher ----------------
extern "C" void kernel_launch(void* const* d_in, const int* in_sizes, int n_in,
                              void* d_out, int out_size)
{
    const float* hidden = (const float*)d_in[0];
    const float* Wq     = (const float*)d_in[1];
    const float* Wk     = (const float*)d_in[2];
    const float* Wv     = (const float*)d_in[3];
    const float* Wo     = (const float*)d_in[4];
    const float* cosp   = (const float*)d_in[5];
    const float* sinp   = (const float*)d_in[6];
    const float* kstore = (const float*)d_in[7];
    const float* vstore = (const float*)d_in[8];
    const int*   kvlut  = (const int*)d_in[9];
    const int*   ctxptr = (const int*)d_in[10];
    const int*   prefix = (n_in >= 12) ? (const int*)d_in[11] : nullptr;
    float* out = (float*)d_out;

    float *qkv;
    __nv_bfloat16 *xhi, *xlo, *whi, *wlo, *qhi, *qlo, *khi, *klo, *vhi, *vlo;
    cudaGetSymbolAddress((void**)&qkv, g_qkv);
    cudaGetSymbolAddress((void**)&xhi, g_xhi);
    cudaGetSymbolAddress((void**)&xlo, g_xlo);
    cudaGetSymbolAddress((void**)&whi, g_whi);
    cudaGetSymbolAddress((void**)&wlo, g_wlo);
    cudaGetSymbolAddress((void**)&qhi, g_qhi);
    cudaGetSymbolAddress((void**)&qlo, g_qlo);
    cudaGetSymbolAddress((void**)&khi, g_khi);
    cudaGetSymbolAddress((void**)&klo, g_klo);
    cudaGetSymbolAddress((void**)&vhi, g_vhi);
    cudaGetSymbolAddress((void**)&vlo, g_vlo);

    cudaFuncSetAttribute(attn_mma, cudaFuncAttributeMaxDynamicSharedMemorySize, ATT_SMEM2);

    // hi/lo splits
    {
        int n4;
        n4 = MROWS * HID / 4;
        split2<<<(n4 + 255) / 256, 256>>>(hidden, xhi, xlo, n4);
        n4 = (NH * HD) * HID / 4;
        split2<<<(n4 + 255) / 256, 256>>>(Wq, whi + WOFF_Q, wlo + WOFF_Q, n4);
        n4 = (NKV * HD) * HID / 4;
        split2<<<(n4 + 255) / 256, 256>>>(Wk, whi + WOFF_K, wlo + WOFF_K, n4);
        split2<<<(n4 + 255) / 256, 256>>>(Wv, whi + WOFF_V, wlo + WOFF_V, n4);
        n4 = HID * HID / 4;
        split2<<<(n4 + 255) / 256, 256>>>(Wo, whi + WOFF_O, wlo + WOFF_O, n4);
    }
    // KV storage -> split bf16 caches
    {
        int n4 = (int)((size_t)NBLK * NKV * BLKSZ * HD / 4);
        split2<<<(n4 + 255) / 256, 256>>>(kstore, khi, klo, n4);
        split2<<<(n4 + 255) / 256, 256>>>(vstore, vhi, vlo, n4);
    }

    // fused QKV projection (weights contiguous in g_whi)
    gemm_mma_split<<<dim3(QKVN / 128, MROWS / 128), 256>>>(
        xhi, xlo, whi, wlo, qkv, MROWS, QKVN, HID);

    // RoPE + split + scatter
    rope_scatter_bf16<<<MROWS, 256>>>(qkv, cosp, sinp, ctxptr,
                                      qhi, qlo, khi, klo, vhi, vlo);

    // attention (writes split output directly into xhi/xlo)
    attn_mma<<<dim3(QL / 64, NH, BSZ), 128, ATT_SMEM2>>>(
        qhi, qlo, khi, klo, vhi, vlo, kvlut, prefix, xhi, xlo);

    // O projection
    gemm_mma_split<<<dim3(HID / 128, MROWS / 128), 256>>>(
        xhi, xlo, whi + WOFF_O, wlo + WOFF_O, out, MROWS, HID, HID);
}

// round 7
// speedup vs baseline: 3.6252x; 1.3379x over previous
#include <cuda_runtime.h>
#include <cuda_bf16.h>
#include <cuda_fp16.h>
#include <cstdint>

// ---------------- problem dims ----------------
#define BSZ   2
#define QL    1024
#define HID   4096
#define NH    32
#define NKV   8
#define HD    128
#define NBLK  512
#define BLKSZ 16
#define SEQ   4096
#define MROWS (BSZ*QL)                 // 2048
#define QKVN  (NH*HD + 2*NKV*HD)       // 6144
#define WROWS (QKVN + HID)             // 10240
#define WOFF_O ((size_t)QKVN * HID)

// q pre-scale: (1/sqrt(128)) * log2(e)  -> softmax in exp2 domain
#define ASCALE ((float)(0.08838834764831845 * 1.4426950408889634))

// ---------------- device scratch ----------------
__device__ float g_qkv [(size_t)MROWS * QKVN];   // fused QKV projection output
__device__ __half g_xh [(size_t)MROWS * HID];    // activation fp16 hi (reused for attn out)
__device__ __half g_xl [(size_t)MROWS * HID];    // activation fp16 lo
__device__ __half g_wf [(size_t)WROWS * HID];    // all weights, single fp16
__device__ __nv_bfloat16 g_qhi[(size_t)BSZ * NH * QL * HD];
__device__ __nv_bfloat16 g_qlo[(size_t)BSZ * NH * QL * HD];
__device__ __nv_bfloat16 g_khi[(size_t)NBLK * NKV * BLKSZ * HD];
__device__ __nv_bfloat16 g_klo[(size_t)NBLK * NKV * BLKSZ * HD];
__device__ __nv_bfloat16 g_vhi[(size_t)NBLK * NKV * BLKSZ * HD];
__device__ __nv_bfloat16 g_vlo[(size_t)NBLK * NKV * BLKSZ * HD];

// ---------------- helpers ----------------
__device__ __forceinline__ uint32_t smem_u32(const void* p) {
    uint32_t a;
    asm("{ .reg .u64 t; cvta.to.shared.u64 t, %1; cvt.u32.u64 %0, t; }" : "=r"(a) : "l"(p));
    return a;
}
__device__ __forceinline__ void ldsm4(uint32_t* r, uint32_t addr) {
    asm volatile("ldmatrix.sync.aligned.m8n8.x4.shared.b16 {%0,%1,%2,%3}, [%4];"
                 : "=r"(r[0]), "=r"(r[1]), "=r"(r[2]), "=r"(r[3]) : "r"(addr));
}
__device__ __forceinline__ void ldsm4t(uint32_t* r, uint32_t addr) {
    asm volatile("ldmatrix.sync.aligned.m8n8.x4.trans.shared.b16 {%0,%1,%2,%3}, [%4];"
                 : "=r"(r[0]), "=r"(r[1]), "=r"(r[2]), "=r"(r[3]) : "r"(addr));
}
__device__ __forceinline__ void mma_bf16(float* c, const uint32_t* a, uint32_t b0, uint32_t b1) {
    asm volatile("mma.sync.aligned.m16n8k16.row.col.f32.bf16.bf16.f32 "
                 "{%0,%1,%2,%3}, {%4,%5,%6,%7}, {%8,%9}, {%0,%1,%2,%3};"
                 : "+f"(c[0]), "+f"(c[1]), "+f"(c[2]), "+f"(c[3])
                 : "r"(a[0]), "r"(a[1]), "r"(a[2]), "r"(a[3]), "r"(b0), "r"(b1));
}
__device__ __forceinline__ void mma_f16(float* c, const uint32_t* a, uint32_t b0, uint32_t b1) {
    asm volatile("mma.sync.aligned.m16n8k16.row.col.f32.f16.f16.f32 "
                 "{%0,%1,%2,%3}, {%4,%5,%6,%7}, {%8,%9}, {%0,%1,%2,%3};"
                 : "+f"(c[0]), "+f"(c[1]), "+f"(c[2]), "+f"(c[3])
                 : "r"(a[0]), "r"(a[1]), "r"(a[2]), "r"(a[3]), "r"(b0), "r"(b1));
}
__device__ __forceinline__ float ex2f(float x) {
    float y; asm("ex2.approx.ftz.f32 %0, %1;" : "=f"(y) : "f"(x)); return y;
}
__device__ __forceinline__ uint32_t packbf2(float a, float b) {
    __nv_bfloat162 t = __floats2bfloat162_rn(a, b);
    return *(uint32_t*)&t;
}
__device__ __forceinline__ uint32_t packh2(float a, float b) {
    __half2 t = __floats2half2_rn(a, b);
    return *(uint32_t*)&t;
}
__device__ __forceinline__ void cpasync16(uint32_t dst, const void* src) {
    asm volatile("cp.async.cg.shared.global [%0], [%1], 16;" :: "r"(dst), "l"(src));
}
#define CP_COMMIT() asm volatile("cp.async.commit_group;" ::: "memory")
#define CP_WAIT1()  asm volatile("cp.async.wait_group 1;" ::: "memory")
#define CP_WAIT0()  asm volatile("cp.async.wait_group 0;" ::: "memory")

// ---------------- fp32 -> fp16 hi/lo split ----------------
__global__ __launch_bounds__(256) void split2h(const float* __restrict__ x,
                                               __half* __restrict__ hi,
                                               __half* __restrict__ lo, int n4)
{
    int i = blockIdx.x * 256 + threadIdx.x;
    if (i >= n4) return;
    float4 v = *(const float4*)(x + (size_t)i * 4);
    __half h0 = __float2half_rn(v.x), h1 = __float2half_rn(v.y);
    __half h2 = __float2half_rn(v.z), h3 = __float2half_rn(v.w);
    __half l0 = __float2half_rn(v.x - __half2float(h0));
    __half l1 = __float2half_rn(v.y - __half2float(h1));
    __half l2 = __float2half_rn(v.z - __half2float(h2));
    __half l3 = __float2half_rn(v.w - __half2float(h3));
    __half2* hp = (__half2*)(hi + (size_t)i * 4);
    __half2* lp = (__half2*)(lo + (size_t)i * 4);
    hp[0] = __half2(h0, h1); hp[1] = __half2(h2, h3);
    lp[0] = __half2(l0, l1); lp[1] = __half2(l2, l3);
}

// ---------------- fp32 -> fp16 round (weights) ----------------
__global__ __launch_bounds__(256) void roundh(const float* __restrict__ x,
                                              __half* __restrict__ y, int n4)
{
    int i = blockIdx.x * 256 + threadIdx.x;
    if (i >= n4) return;
    float4 v = *(const float4*)(x + (size_t)i * 4);
    __half2* yp = (__half2*)(y + (size_t)i * 4);
    yp[0] = __floats2half2_rn(v.x, v.y);
    yp[1] = __floats2half2_rn(v.z, v.w);
}

// ---------------- fp32 -> bf16 hi/lo split (KV caches) ----------------
__global__ __launch_bounds__(256) void split2(const float* __restrict__ x,
                                              __nv_bfloat16* __restrict__ hi,
                                              __nv_bfloat16* __restrict__ lo, int n4)
{
    int i = blockIdx.x * 256 + threadIdx.x;
    if (i >= n4) return;
    float4 v = *(const float4*)(x + (size_t)i * 4);
    __nv_bfloat16 h0 = __float2bfloat16(v.x), h1 = __float2bfloat16(v.y);
    __nv_bfloat16 h2 = __float2bfloat16(v.z), h3 = __float2bfloat16(v.w);
    __nv_bfloat16 l0 = __float2bfloat16(v.x - __bfloat162float(h0));
    __nv_bfloat16 l1 = __float2bfloat16(v.y - __bfloat162float(h1));
    __nv_bfloat16 l2 = __float2bfloat16(v.z - __bfloat162float(h2));
    __nv_bfloat16 l3 = __float2bfloat16(v.w - __bfloat162float(h3));
    __nv_bfloat162* hp = (__nv_bfloat162*)(hi + (size_t)i * 4);
    __nv_bfloat162* lp = (__nv_bfloat162*)(lo + (size_t)i * 4);
    hp[0] = __nv_bfloat162(h0, h1); hp[1] = __nv_bfloat162(h2, h3);
    lp[0] = __nv_bfloat162(l0, l1); lp[1] = __nv_bfloat162(l2, l3);
}

// ---------------- pipelined fp16 2-product GEMM ----------------
// C[M,N] = (Ah+Al)[M,K] * B[N,K]^T, fp32 acc. A split fp16, B single fp16.
// Tile 128x128x32, 8 warps (4M x 2N). Double-buffered cp.async.
#define TB2 8192                    // one 128x32 fp16 tile
#define BUF2 (3 * TB2)              // Ah, Al, B

__global__ __launch_bounds__(256) void gemm_f16_2p(
    const __half* __restrict__ Ahi, const __half* __restrict__ Alo,
    const __half* __restrict__ Bw,
    float* __restrict__ C, int M, int N, int K)
{
    __shared__ __half smem[2][3][128 * 32];   // 48KB

    const int tid  = threadIdx.x;
    const int warp = tid >> 5, lane = tid & 31;
    const int wm = warp & 3, wn = warp >> 2;
    const int bm = blockIdx.y * 128, bn = blockIdx.x * 128;
    const uint32_t sb = smem_u32(smem);

    float acc[2][8][4];
#pragma unroll
    for (int i = 0; i < 2; i++)
#pragma unroll
        for (int j = 0; j < 8; j++)
#pragma unroll
            for (int e = 0; e < 4; e++) acc[i][j][e] = 0.f;

    const __half* g0 = Ahi + (size_t)bm * K;
    const __half* g1 = Alo + (size_t)bm * K;
    const __half* g2 = Bw  + (size_t)bn * K;

    int rowA = tid >> 2, kcA = tid & 3;
    int rowB = (tid + 256) >> 2, kcB = (tid + 256) & 3;
    uint32_t soffA = (uint32_t)(rowA * 32 + (((kcA + (rowA >> 1)) & 3) * 8)) * 2;
    uint32_t soffB = (uint32_t)(rowB * 32 + (((kcB + (rowB >> 1)) & 3) * 8)) * 2;

    const int nch = K / 32;

#define ISSUE_LOAD(buf, k0)                                                    \
    do {                                                                       \
        size_t gA = (size_t)rowA * K + (k0) + kcA * 8;                         \
        size_t gB = (size_t)rowB * K + (k0) + kcB * 8;                         \
        uint32_t base = sb + (buf) * BUF2;                                     \
        cpasync16(base + 0 * TB2 + soffA, g0 + gA);                            \
        cpasync16(base + 1 * TB2 + soffA, g1 + gA);                            \
        cpasync16(base + 2 * TB2 + soffA, g2 + gA);                            \
        cpasync16(base + 0 * TB2 + soffB, g0 + gB);                            \
        cpasync16(base + 1 * TB2 + soffB, g1 + gB);                            \
        cpasync16(base + 2 * TB2 + soffB, g2 + gB);                            \
        CP_COMMIT();                                                           \
    } while (0)

    ISSUE_LOAD(0, 0);

    for (int ch = 0; ch < nch; ch++) {
        const int buf = ch & 1;
        if (ch + 1 < nch) {
            ISSUE_LOAD(buf ^ 1, (ch + 1) * 32);
            CP_WAIT1();
        } else {
            CP_WAIT0();
        }
        __syncthreads();

        const uint32_t aHi = sb + buf * BUF2;
        const uint32_t aLo = aHi + TB2;
        const uint32_t bBs = aHi + 2 * TB2;

#pragma unroll
        for (int ks = 0; ks < 2; ks++) {
            uint32_t ah[2][4], al[2][4];
            {
                int r  = wm * 32 + (lane & 15);
                int cd = ks * 2 + (lane >> 4);
#pragma unroll
                for (int mt = 0; mt < 2; mt++) {
                    int row  = r + mt * 16;
                    int phys = (cd + (row >> 1)) & 3;
                    uint32_t off = (uint32_t)(row * 32 + phys * 8) * 2;
                    ldsm4(ah[mt], aHi + off);
                    ldsm4(al[mt], aLo + off);
                }
            }
#pragma unroll
            for (int nt4 = 0; nt4 < 4; nt4++) {
                int n    = wn * 64 + nt4 * 16 + (lane & 7) + ((lane >> 4) << 3);
                int cd   = ks * 2 + ((lane >> 3) & 1);
                int phys = (cd + (n >> 1)) & 3;
                uint32_t off = (uint32_t)(n * 32 + phys * 8) * 2;
                uint32_t bw[4];
                ldsm4(bw, bBs + off);
#pragma unroll
                for (int mt = 0; mt < 2; mt++) {
#pragma unroll
                    for (int p = 0; p < 2; p++) {
                        float* cc = acc[mt][nt4 * 2 + p];
                        mma_f16(cc, ah[mt], bw[2 * p], bw[2 * p + 1]);
                        mma_f16(cc, al[mt], bw[2 * p], bw[2 * p + 1]);
                    }
                }
            }
        }
        __syncthreads();
    }
#undef ISSUE_LOAD

#pragma unroll
    for (int mt = 0; mt < 2; mt++) {
#pragma unroll
        for (int nt = 0; nt < 8; nt++) {
            int row = bm + wm * 32 + mt * 16 + (lane >> 2);
            int col = bn + wn * 64 + nt * 8 + (lane & 3) * 2;
            float* cc = acc[mt][nt];
            *(float2*)&C[(size_t)row * N + col]       = make_float2(cc[0], cc[1]);
            *(float2*)&C[(size_t)(row + 8) * N + col] = make_float2(cc[2], cc[3]);
        }
    }
}

// ---------------- RoPE + bf16 split + cache scatter (fused-QKV input) ----------------
__global__ __launch_bounds__(256) void rope_scatter_bf16(
    const float* __restrict__ QKV,
    const float* __restrict__ cosp, const float* __restrict__ sinp,
    const int* __restrict__ ctx_ptrs,
    __nv_bfloat16* __restrict__ qh, __nv_bfloat16* __restrict__ ql,
    __nv_bfloat16* __restrict__ kh, __nv_bfloat16* __restrict__ kl,
    __nv_bfloat16* __restrict__ vh, __nv_bfloat16* __restrict__ vl)
{
    const int row = blockIdx.x;          // 0..2047
    const int b = row >> 10, t = row & 1023;
    const int tid = threadIdx.x;
    const float* crow = cosp + (size_t)t * HD;
    const float* srow = sinp + (size_t)t * HD;
    const float* Qr = QKV + (size_t)row * QKVN;
    const float* Kr = Qr + NH * HD;
    const float* Vr = Kr + NKV * HD;

    for (int idx = tid; idx < NH * 64; idx += 256) {
        int h = idx >> 6, d = idx & 63;
        float x0 = Qr[h * HD + d];
        float x1 = Qr[h * HD + d + 64];
        float o0 = (x0 * crow[d]      - x1 * srow[d])      * ASCALE;
        float o1 = (x1 * crow[d + 64] + x0 * srow[d + 64]) * ASCALE;
        size_t base = ((size_t)(b * NH + h) * QL + t) * HD;
        __nv_bfloat16 h0 = __float2bfloat16(o0), h1 = __float2bfloat16(o1);
        qh[base + d]      = h0; ql[base + d]      = __float2bfloat16(o0 - __bfloat162float(h0));
        qh[base + d + 64] = h1; ql[base + d + 64] = __float2bfloat16(o1 - __bfloat162float(h1));
    }

    const int blk  = ctx_ptrs[b * (QL / BLKSZ) + (t >> 4)];
    const int rrow = t & 15;

    for (int idx = tid; idx < NKV * 64; idx += 256) {
        int h = idx >> 6, d = idx & 63;
        float x0 = Kr[h * HD + d];
        float x1 = Kr[h * HD + d + 64];
        float o0 = x0 * crow[d]      - x1 * srow[d];
        float o1 = x1 * crow[d + 64] + x0 * srow[d + 64];
        size_t base = (((size_t)blk * NKV + h) * BLKSZ + rrow) * HD;
        __nv_bfloat16 h0 = __float2bfloat16(o0), h1 = __float2bfloat16(o1);
        kh[base + d]      = h0; kl[base + d]      = __float2bfloat16(o0 - __bfloat162float(h0));
        kh[base + d + 64] = h1; kl[base + d + 64] = __float2bfloat16(o1 - __bfloat162float(h1));
    }

    for (int idx = tid; idx < NKV * HD; idx += 256) {
        int h = idx >> 7, d = idx & 127;
        float x = Vr[h * HD + d];
        size_t base = (((size_t)blk * NKV + h) * BLKSZ + rrow) * HD;
        __nv_bfloat16 h0 = __float2bfloat16(x);
        vh[base + d] = h0; vl[base + d] = __float2bfloat16(x - __bfloat162float(h0));
    }
}

// ---------------- flash attention: split-bf16 HMMA + exp2 online softmax ----------------
#define ATT_SMEM2 (4 * 64 * 128 * 2)

__global__ __launch_bounds__(128, 3) void attn_mma(
    const __nv_bfloat16* __restrict__ gqh, const __nv_bfloat16* __restrict__ gql,
    const __nv_bfloat16* __restrict__ gkh, const __nv_bfloat16* __restrict__ gkl,
    const __nv_bfloat16* __restrict__ gvh, const __nv_bfloat16* __restrict__ gvl,
    const int* __restrict__ kvlut, const int* __restrict__ prefix_ptr,
    __half* __restrict__ ohi, __half* __restrict__ olo)
{
    extern __shared__ __align__(16) char dynsm[];
    __nv_bfloat16* sQh = (__nv_bfloat16*)dynsm;
    __nv_bfloat16* sQl = sQh + 64 * 128;
    __nv_bfloat16* sKh = sQl + 64 * 128;
    __nv_bfloat16* sKl = sKh + 64 * 128;
    const uint32_t bQh = smem_u32(sQh), bQl = smem_u32(sQl);
    const uint32_t bKh = smem_u32(sKh), bKl = smem_u32(sKl);

    const int qtile = blockIdx.x, h = blockIdx.y, b = blockIdx.z;
    const int kvh = h >> 2;
    const int prefix = prefix_ptr ? *prefix_ptr : 3072;
    const int tid = threadIdx.x;
    const int warp = tid >> 5, lane = tid & 31;
    const int qr = warp * 16;
    const int q0 = qtile * 64;
    const int* lut = kvlut + b * (SEQ / BLKSZ);

    {
        const __nv_bfloat16* srch = gqh + ((size_t)(b * NH + h) * QL + q0) * HD;
        const __nv_bfloat16* srcl = gql + ((size_t)(b * NH + h) * QL + q0) * HD;
        for (int i = tid; i < 64 * 16; i += 128) {
            int row = i >> 4, c = i & 15;
            int phys = (c ^ (row & 7)) << 3;
            *(uint4*)&sQh[row * 128 + phys] = *(const uint4*)(srch + (size_t)row * HD + c * 8);
            *(uint4*)&sQl[row * 128 + phys] = *(const uint4*)(srcl + (size_t)row * HD + c * 8);
        }
    }

    float O[16][4];
#pragma unroll
    for (int i = 0; i < 16; i++)
#pragma unroll
        for (int e = 0; e < 4; e++) O[i][e] = 0.f;
    float m0 = -1e30f, m1 = -1e30f, l0 = 0.f, l1 = 0.f;

    const int plim = prefix + q0;
    const int kv_end = plim + 64;
    const int qa0 = plim + qr + (lane >> 2);
    const int qa1 = qa0 + 8;

    for (int s0 = 0; s0 < kv_end; s0 += 64) {
        __syncthreads();
        for (int i = tid; i < 64 * 16; i += 128) {
            int row = i >> 4, c = i & 15;
            int s = s0 + row;
            int blk = lut[s >> 4];
            size_t base = (((size_t)blk * NKV + kvh) * BLKSZ + (s & 15)) * HD + c * 8;
            int phys = (c ^ (row & 7)) << 3;
            *(uint4*)&sKh[row * 128 + phys] = *(const uint4*)(gkh + base);
            *(uint4*)&sKl[row * 128 + phys] = *(const uint4*)(gkl + base);
        }
        __syncthreads();

        float S[8][4];
#pragma unroll
        for (int i = 0; i < 8; i++)
#pragma unroll
            for (int e = 0; e < 4; e++) S[i][e] = 0.f;

#pragma unroll
        for (int ks = 0; ks < 8; ks++) {
            uint32_t ah[4], al[4];
            {
                int arow = qr + (lane & 15);
                int ac = ks * 2 + (lane >> 4);
                uint32_t aoff = (uint32_t)(arow * 128 + ((ac ^ (arow & 7)) << 3)) * 2;
                ldsm4(ah, bQh + aoff);
                ldsm4(al, bQl + aoff);
            }
            int brow_b = (lane & 7) + ((lane >> 4) << 3);
            int bc = ks * 2 + ((lane >> 3) & 1);
#pragma unroll
            for (int ng = 0; ng < 4; ng++) {
                int brow = ng * 16 + brow_b;
                uint32_t boff = (uint32_t)(brow * 128 + ((bc ^ (brow & 7)) << 3)) * 2;
                uint32_t kh[4], kl[4];
                ldsm4(kh, bKh + boff);
                ldsm4(kl, bKl + boff);
                mma_bf16(S[2 * ng],     ah, kh[0], kh[1]);
                mma_bf16(S[2 * ng],     ah, kl[0], kl[1]);
                mma_bf16(S[2 * ng],     al, kh[0], kh[1]);
                mma_bf16(S[2 * ng + 1], ah, kh[2], kh[3]);
                mma_bf16(S[2 * ng + 1], ah, kl[2], kl[3]);
                mma_bf16(S[2 * ng + 1], al, kh[2], kh[3]);
            }
        }

        if (s0 + 63 > plim) {
#pragma unroll
            for (int nt = 0; nt < 8; nt++) {
                int colb = s0 + nt * 8 + ((lane & 3) << 1);
                if (colb     > qa0) S[nt][0] = -1e30f;
                if (colb + 1 > qa0) S[nt][1] = -1e30f;
                if (colb     > qa1) S[nt][2] = -1e30f;
                if (colb + 1 > qa1) S[nt][3] = -1e30f;
            }
        }

        float mx0 = -1e30f, mx1 = -1e30f;
#pragma unroll
        for (int nt = 0; nt < 8; nt++) {
            mx0 = fmaxf(mx0, fmaxf(S[nt][0], S[nt][1]));
            mx1 = fmaxf(mx1, fmaxf(S[nt][2], S[nt][3]));
        }
        mx0 = fmaxf(mx0, __shfl_xor_sync(0xffffffffu, mx0, 1));
        mx0 = fmaxf(mx0, __shfl_xor_sync(0xffffffffu, mx0, 2));
        mx1 = fmaxf(mx1, __shfl_xor_sync(0xffffffffu, mx1, 1));
        mx1 = fmaxf(mx1, __shfl_xor_sync(0xffffffffu, mx1, 2));
        float mn0 = fmaxf(m0, mx0), mn1 = fmaxf(m1, mx1);
        float f0 = ex2f(m0 - mn0), f1 = ex2f(m1 - mn1);
        m0 = mn0; m1 = mn1;

        float rs0 = 0.f, rs1 = 0.f;
#pragma unroll
        for (int nt = 0; nt < 8; nt++) {
            S[nt][0] = ex2f(S[nt][0] - mn0); rs0 += S[nt][0];
            S[nt][1] = ex2f(S[nt][1] - mn0); rs0 += S[nt][1];
            S[nt][2] = ex2f(S[nt][2] - mn1); rs1 += S[nt][2];
            S[nt][3] = ex2f(S[nt][3] - mn1); rs1 += S[nt][3];
        }
        rs0 += __shfl_xor_sync(0xffffffffu, rs0, 1);
        rs0 += __shfl_xor_sync(0xffffffffu, rs0, 2);
        rs1 += __shfl_xor_sync(0xffffffffu, rs1, 1);
        rs1 += __shfl_xor_sync(0xffffffffu, rs1, 2);
        l0 = l0 * f0 + rs0;
        l1 = l1 * f1 + rs1;

#pragma unroll
        for (int nt = 0; nt < 16; nt++) {
            O[nt][0] *= f0; O[nt][1] *= f0; O[nt][2] *= f1; O[nt][3] *= f1;
        }

        uint32_t PH[4][4], PL[4][4];
#pragma unroll
        for (int kt = 0; kt < 4; kt++) {
            int e = 2 * kt, o = 2 * kt + 1;
            float h00 = __bfloat162float(__float2bfloat16(S[e][0]));
            float h01 = __bfloat162float(__float2bfloat16(S[e][1]));
            float h02 = __bfloat162float(__float2bfloat16(S[e][2]));
            float h03 = __bfloat162float(__float2bfloat16(S[e][3]));
            float h10 = __bfloat162float(__float2bfloat16(S[o][0]));
            float h11 = __bfloat162float(__float2bfloat16(S[o][1]));
            float h12 = __bfloat162float(__float2bfloat16(S[o][2]));
            float h13 = __bfloat162float(__float2bfloat16(S[o][3]));
            PH[kt][0] = packbf2(h00, h01);
            PH[kt][1] = packbf2(h02, h03);
            PH[kt][2] = packbf2(h10, h11);
            PH[kt][3] = packbf2(h12, h13);
            PL[kt][0] = packbf2(S[e][0] - h00, S[e][1] - h01);
            PL[kt][1] = packbf2(S[e][2] - h02, S[e][3] - h03);
            PL[kt][2] = packbf2(S[o][0] - h10, S[o][1] - h11);
            PL[kt][3] = packbf2(S[o][2] - h12, S[o][3] - h13);
        }

        __syncthreads();
        for (int i = tid; i < 64 * 16; i += 128) {
            int row = i >> 4, c = i & 15;
            int s = s0 + row;
            int blk = lut[s >> 4];
            size_t base = (((size_t)blk * NKV + kvh) * BLKSZ + (s & 15)) * HD + c * 8;
            int phys = (c ^ (row & 7)) << 3;
            *(uint4*)&sKh[row * 128 + phys] = *(const uint4*)(gvh + base);
            *(uint4*)&sKl[row * 128 + phys] = *(const uint4*)(gvl + base);
        }
        __syncthreads();

#pragma unroll
        for (int kt = 0; kt < 4; kt++) {
            int vrow = kt * 16 + (((lane >> 3) & 1) << 3) + (lane & 7);
            int vc0 = lane >> 4;
#pragma unroll
            for (int vg = 0; vg < 8; vg++) {
                int c = vg * 2 + vc0;
                uint32_t off = (uint32_t)(vrow * 128 + ((c ^ (vrow & 7)) << 3)) * 2;
                uint32_t vh[4], vl[4];
                ldsm4t(vh, bKh + off);
                ldsm4t(vl, bKl + off);
                mma_bf16(O[2 * vg],     PH[kt], vh[0], vh[1]);
                mma_bf16(O[2 * vg],     PH[kt], vl[0], vl[1]);
                mma_bf16(O[2 * vg],     PL[kt], vh[0], vh[1]);
                mma_bf16(O[2 * vg + 1], PH[kt], vh[2], vh[3]);
                mma_bf16(O[2 * vg + 1], PH[kt], vl[2], vl[3]);
                mma_bf16(O[2 * vg + 1], PL[kt], vh[2], vh[3]);
            }
        }
    }

    // epilogue: normalize, fp16 hi/lo split, write [b,t,h*128+d]
    float inv0 = 1.f / l0, inv1 = 1.f / l1;
    int r0 = q0 + qr + (lane >> 2);
    int r1 = r0 + 8;
#pragma unroll
    for (int nt = 0; nt < 16; nt++) {
        int d = h * HD + nt * 8 + ((lane & 3) << 1);
        {
            float a = O[nt][0] * inv0, bb = O[nt][1] * inv0;
            float ha = __half2float(__float2half_rn(a));
            float hb = __half2float(__float2half_rn(bb));
            size_t base = (size_t)(b * QL + r0) * HID + d;
            *(uint32_t*)(ohi + base) = packh2(a, bb);
            *(uint32_t*)(olo + base) = packh2(a - ha, bb - hb);
        }
        {
            float a = O[nt][2] * inv1, bb = O[nt][3] * inv1;
            float ha = __half2float(__float2half_rn(a));
            float hb = __half2float(__float2half_rn(bb));
            size_t base = (size_t)(b * QL + r1) * HID + d;
            *(uint32_t*)(ohi + base) = packh2(a, bb);
            *(uint32_t*)(olo + base) = packh2(a - ha, bb - hb);
        }
    }
}

// ---------------- launcher ----------------
extern "C" void kernel_launch(void* const* d_in, const int* in_sizes, int n_in,
                              void* d_out, int out_size)
{
    const float* hidden = (const float*)d_in[0];
    const float* Wq     = (const float*)d_in[1];
    const float* Wk     = (const float*)d_in[2];
    const float* Wv     = (const float*)d_in[3];
    const float* Wo     = (const float*)d_in[4];
    const float* cosp   = (const float*)d_in[5];
    const float* sinp   = (const float*)d_in[6];
    const float* kstore = (const float*)d_in[7];
    const float* vstore = (const float*)d_in[8];
    const int*   kvlut  = (const int*)d_in[9];
    const int*   ctxptr = (const int*)d_in[10];
    const int*   prefix = (n_in >= 12) ? (const int*)d_in[11] : nullptr;
    float* out = (float*)d_out;

    float *qkv;
    __half *xh, *xl, *wf;
    __nv_bfloat16 *qhi, *qlo, *khi, *klo, *vhi, *vlo;
    cudaGetSymbolAddress((void**)&qkv, g_qkv);
    cudaGetSymbolAddress((void**)&xh,  g_xh);
    cudaGetSymbolAddress((void**)&xl,  g_xl);
    cudaGetSymbolAddress((void**)&wf,  g_wf);
    cudaGetSymbolAddress((void**)&qhi, g_qhi);
    cudaGetSymbolAddress((void**)&qlo, g_qlo);
    cudaGetSymbolAddress((void**)&khi, g_khi);
    cudaGetSymbolAddress((void**)&klo, g_klo);
    cudaGetSymbolAddress((void**)&vhi, g_vhi);
    cudaGetSymbolAddress((void**)&vlo, g_vlo);

    cudaFuncSetAttribute(attn_mma, cudaFuncAttributeMaxDynamicSharedMemorySize, ATT_SMEM2);

    // activation split + weight rounding
    {
        int n4 = MROWS * HID / 4;
        split2h<<<(n4 + 255) / 256, 256>>>(hidden, xh, xl, n4);
        n4 = (NH * HD) * HID / 4;
        roundh<<<(n4 + 255) / 256, 256>>>(Wq, wf, n4);
        n4 = (NKV * HD) * HID / 4;
        roundh<<<(n4 + 255) / 256, 256>>>(Wk, wf + (size_t)(NH * HD) * HID, n4);
        roundh<<<(n4 + 255) / 256, 256>>>(Wv, wf + (size_t)(NH * HD + NKV * HD) * HID, n4);
        n4 = HID * HID / 4;
        roundh<<<(n4 + 255) / 256, 256>>>(Wo, wf + WOFF_O, n4);
    }
    // KV storage -> split bf16 caches
    {
        int n4 = (int)((size_t)NBLK * NKV * BLKSZ * HD / 4);
        split2<<<(n4 + 255) / 256, 256>>>(kstore, khi, klo, n4);
        split2<<<(n4 + 255) / 256, 256>>>(vstore, vhi, vlo, n4);
    }

    // fused QKV projection (fp16 2-product)
    gemm_f16_2p<<<dim3(QKVN / 128, MROWS / 128), 256>>>(
        xh, xl, wf, qkv, MROWS, QKVN, HID);

    // RoPE + split + scatter
    rope_scatter_bf16<<<MROWS, 256>>>(qkv, cosp, sinp, ctxptr,
                                      qhi, qlo, khi, klo, vhi, vlo);

    // attention (bf16 3-term; writes fp16 split output into xh/xl)
    attn_mma<<<dim3(QL / 64, NH, BSZ), 128, ATT_SMEM2>>>(
        qhi, qlo, khi, klo, vhi, vlo, kvlut, prefix, xh, xl);

    // O projection (fp16 2-product)
    gemm_f16_2p<<<dim3(HID / 128, MROWS / 128), 256>>>(
        xh, xl, wf + WOFF_O, out, MROWS, HID, HID);
}

// round 8
// speedup vs baseline: 4.4994x; 1.2411x over previous
#include <cuda_runtime.h>
#include <cuda_bf16.h>
#include <cuda_fp16.h>
#include <cstdint>

// ---------------- problem dims ----------------
#define BSZ   2
#define QL    1024
#define HID   4096
#define NH    32
#define NKV   8
#define HD    128
#define NBLK  512
#define BLKSZ 16
#define SEQ   4096
#define MROWS (BSZ*QL)                 // 2048
#define QKVN  (NH*HD + 2*NKV*HD)       // 6144
#define WROWS (QKVN + HID)             // 10240
#define WOFF_O ((size_t)QKVN * HID)

// q pre-scale: (1/sqrt(128)) * log2(e)  -> softmax in exp2 domain
#define ASCALE ((float)(0.08838834764831845 * 1.4426950408889634))

// ---------------- device scratch ----------------
__device__ float g_qkv [(size_t)MROWS * QKVN];   // fused QKV projection output
__device__ __half g_xh [(size_t)MROWS * HID];    // activation fp16 hi (reused for attn out)
__device__ __half g_xl [(size_t)MROWS * HID];    // activation fp16 lo
__device__ __half g_wf [(size_t)WROWS * HID];    // all weights, single fp16
__device__ __half g_qh [(size_t)BSZ * NH * QL * HD];   // Q hi (fp16, pre-scaled)
__device__ __half g_ql [(size_t)BSZ * NH * QL * HD];   // Q lo
__device__ __half g_kf [(size_t)NBLK * NKV * BLKSZ * HD];  // K cache, single fp16
__device__ __half g_vf [(size_t)NBLK * NKV * BLKSZ * HD];  // V cache, single fp16

// ---------------- helpers ----------------
__device__ __forceinline__ uint32_t smem_u32(const void* p) {
    uint32_t a;
    asm("{ .reg .u64 t; cvta.to.shared.u64 t, %1; cvt.u32.u64 %0, t; }" : "=r"(a) : "l"(p));
    return a;
}
__device__ __forceinline__ void ldsm4(uint32_t* r, uint32_t addr) {
    asm volatile("ldmatrix.sync.aligned.m8n8.x4.shared.b16 {%0,%1,%2,%3}, [%4];"
                 : "=r"(r[0]), "=r"(r[1]), "=r"(r[2]), "=r"(r[3]) : "r"(addr));
}
__device__ __forceinline__ void ldsm4t(uint32_t* r, uint32_t addr) {
    asm volatile("ldmatrix.sync.aligned.m8n8.x4.trans.shared.b16 {%0,%1,%2,%3}, [%4];"
                 : "=r"(r[0]), "=r"(r[1]), "=r"(r[2]), "=r"(r[3]) : "r"(addr));
}
__device__ __forceinline__ void mma_f16(float* c, const uint32_t* a, uint32_t b0, uint32_t b1) {
    asm volatile("mma.sync.aligned.m16n8k16.row.col.f32.f16.f16.f32 "
                 "{%0,%1,%2,%3}, {%4,%5,%6,%7}, {%8,%9}, {%0,%1,%2,%3};"
                 : "+f"(c[0]), "+f"(c[1]), "+f"(c[2]), "+f"(c[3])
                 : "r"(a[0]), "r"(a[1]), "r"(a[2]), "r"(a[3]), "r"(b0), "r"(b1));
}
__device__ __forceinline__ float ex2f(float x) {
    float y; asm("ex2.approx.ftz.f32 %0, %1;" : "=f"(y) : "f"(x)); return y;
}
__device__ __forceinline__ uint32_t packh2(float a, float b) {
    __half2 t = __floats2half2_rn(a, b);
    return *(uint32_t*)&t;
}
__device__ __forceinline__ void cpasync16(uint32_t dst, const void* src) {
    asm volatile("cp.async.cg.shared.global [%0], [%1], 16;" :: "r"(dst), "l"(src));
}
#define CP_COMMIT() asm volatile("cp.async.commit_group;" ::: "memory")
#define CP_WAIT1()  asm volatile("cp.async.wait_group 1;" ::: "memory")
#define CP_WAIT0()  asm volatile("cp.async.wait_group 0;" ::: "memory")

// ---------------- fp32 -> fp16 hi/lo split ----------------
__global__ __launch_bounds__(256) void split2h(const float* __restrict__ x,
                                               __half* __restrict__ hi,
                                               __half* __restrict__ lo, int n4)
{
    int i = blockIdx.x * 256 + threadIdx.x;
    if (i >= n4) return;
    float4 v = *(const float4*)(x + (size_t)i * 4);
    __half h0 = __float2half_rn(v.x), h1 = __float2half_rn(v.y);
    __half h2 = __float2half_rn(v.z), h3 = __float2half_rn(v.w);
    __half l0 = __float2half_rn(v.x - __half2float(h0));
    __half l1 = __float2half_rn(v.y - __half2float(h1));
    __half l2 = __float2half_rn(v.z - __half2float(h2));
    __half l3 = __float2half_rn(v.w - __half2float(h3));
    __half2* hp = (__half2*)(hi + (size_t)i * 4);
    __half2* lp = (__half2*)(lo + (size_t)i * 4);
    hp[0] = __half2(h0, h1); hp[1] = __half2(h2, h3);
    lp[0] = __half2(l0, l1); lp[1] = __half2(l2, l3);
}

// ---------------- fp32 -> fp16 round ----------------
__global__ __launch_bounds__(256) void roundh(const float* __restrict__ x,
                                              __half* __restrict__ y, int n4)
{
    int i = blockIdx.x * 256 + threadIdx.x;
    if (i >= n4) return;
    float4 v = *(const float4*)(x + (size_t)i * 4);
    __half2* yp = (__half2*)(y + (size_t)i * 4);
    yp[0] = __floats2half2_rn(v.x, v.y);
    yp[1] = __floats2half2_rn(v.z, v.w);
}

// ---------------- pipelined fp16 2-product GEMM (unchanged from R7) ----------------
#define TB2 8192                    // one 128x32 fp16 tile
#define BUF2 (3 * TB2)              // Ah, Al, B

__global__ __launch_bounds__(256) void gemm_f16_2p(
    const __half* __restrict__ Ahi, const __half* __restrict__ Alo,
    const __half* __restrict__ Bw,
    float* __restrict__ C, int M, int N, int K)
{
    __shared__ __half smem[2][3][128 * 32];   // 48KB

    const int tid  = threadIdx.x;
    const int warp = tid >> 5, lane = tid & 31;
    const int wm = warp & 3, wn = warp >> 2;
    const int bm = blockIdx.y * 128, bn = blockIdx.x * 128;
    const uint32_t sb = smem_u32(smem);

    float acc[2][8][4];
#pragma unroll
    for (int i = 0; i < 2; i++)
#pragma unroll
        for (int j = 0; j < 8; j++)
#pragma unroll
            for (int e = 0; e < 4; e++) acc[i][j][e] = 0.f;

    const __half* g0 = Ahi + (size_t)bm * K;
    const __half* g1 = Alo + (size_t)bm * K;
    const __half* g2 = Bw  + (size_t)bn * K;

    int rowA = tid >> 2, kcA = tid & 3;
    int rowB = (tid + 256) >> 2, kcB = (tid + 256) & 3;
    uint32_t soffA = (uint32_t)(rowA * 32 + (((kcA + (rowA >> 1)) & 3) * 8)) * 2;
    uint32_t soffB = (uint32_t)(rowB * 32 + (((kcB + (rowB >> 1)) & 3) * 8)) * 2;

    const int nch = K / 32;

#define ISSUE_LOAD(buf, k0)                                                    \
    do {                                                                       \
        size_t gA = (size_t)rowA * K + (k0) + kcA * 8;                         \
        size_t gB = (size_t)rowB * K + (k0) + kcB * 8;                         \
        uint32_t base = sb + (buf) * BUF2;                                     \
        cpasync16(base + 0 * TB2 + soffA, g0 + gA);                            \
        cpasync16(base + 1 * TB2 + soffA, g1 + gA);                            \
        cpasync16(base + 2 * TB2 + soffA, g2 + gA);                            \
        cpasync16(base + 0 * TB2 + soffB, g0 + gB);                            \
        cpasync16(base + 1 * TB2 + soffB, g1 + gB);                            \
        cpasync16(base + 2 * TB2 + soffB, g2 + gB);                            \
        CP_COMMIT();                                                           \
    } while (0)

    ISSUE_LOAD(0, 0);

    for (int ch = 0; ch < nch; ch++) {
        const int buf = ch & 1;
        if (ch + 1 < nch) {
            ISSUE_LOAD(buf ^ 1, (ch + 1) * 32);
            CP_WAIT1();
        } else {
            CP_WAIT0();
        }
        __syncthreads();

        const uint32_t aHi = sb + buf * BUF2;
        const uint32_t aLo = aHi + TB2;
        const uint32_t bBs = aHi + 2 * TB2;

#pragma unroll
        for (int ks = 0; ks < 2; ks++) {
            uint32_t ah[2][4], al[2][4];
            {
                int r  = wm * 32 + (lane & 15);
                int cd = ks * 2 + (lane >> 4);
#pragma unroll
                for (int mt = 0; mt < 2; mt++) {
                    int row  = r + mt * 16;
                    int phys = (cd + (row >> 1)) & 3;
                    uint32_t off = (uint32_t)(row * 32 + phys * 8) * 2;
                    ldsm4(ah[mt], aHi + off);
                    ldsm4(al[mt], aLo + off);
                }
            }
#pragma unroll
            for (int nt4 = 0; nt4 < 4; nt4++) {
                int n    = wn * 64 + nt4 * 16 + (lane & 7) + ((lane >> 4) << 3);
                int cd   = ks * 2 + ((lane >> 3) & 1);
                int phys = (cd + (n >> 1)) & 3;
                uint32_t off = (uint32_t)(n * 32 + phys * 8) * 2;
                uint32_t bw[4];
                ldsm4(bw, bBs + off);
#pragma unroll
                for (int mt = 0; mt < 2; mt++) {
#pragma unroll
                    for (int p = 0; p < 2; p++) {
                        float* cc = acc[mt][nt4 * 2 + p];
                        mma_f16(cc, ah[mt], bw[2 * p], bw[2 * p + 1]);
                        mma_f16(cc, al[mt], bw[2 * p], bw[2 * p + 1]);
                    }
                }
            }
        }
        __syncthreads();
    }
#undef ISSUE_LOAD

#pragma unroll
    for (int mt = 0; mt < 2; mt++) {
#pragma unroll
        for (int nt = 0; nt < 8; nt++) {
            int row = bm + wm * 32 + mt * 16 + (lane >> 2);
            int col = bn + wn * 64 + nt * 8 + (lane & 3) * 2;
            float* cc = acc[mt][nt];
            *(float2*)&C[(size_t)row * N + col]       = make_float2(cc[0], cc[1]);
            *(float2*)&C[(size_t)(row + 8) * N + col] = make_float2(cc[2], cc[3]);
        }
    }
}

// ---------------- RoPE + fp16 split/round + cache scatter ----------------
__global__ __launch_bounds__(256) void rope_scatter_h(
    const float* __restrict__ QKV,
    const float* __restrict__ cosp, const float* __restrict__ sinp,
    const int* __restrict__ ctx_ptrs,
    __half* __restrict__ qh, __half* __restrict__ ql,
    __half* __restrict__ kf, __half* __restrict__ vf)
{
    const int row = blockIdx.x;          // 0..2047
    const int b = row >> 10, t = row & 1023;
    const int tid = threadIdx.x;
    const float* crow = cosp + (size_t)t * HD;
    const float* srow = sinp + (size_t)t * HD;
    const float* Qr = QKV + (size_t)row * QKVN;
    const float* Kr = Qr + NH * HD;
    const float* Vr = Kr + NKV * HD;

    // Q: rope, scale, fp16 split, store [b,h,t,d]
    for (int idx = tid; idx < NH * 64; idx += 256) {
        int h = idx >> 6, d = idx & 63;
        float x0 = Qr[h * HD + d];
        float x1 = Qr[h * HD + d + 64];
        float o0 = (x0 * crow[d]      - x1 * srow[d])      * ASCALE;
        float o1 = (x1 * crow[d + 64] + x0 * srow[d + 64]) * ASCALE;
        size_t base = ((size_t)(b * NH + h) * QL + t) * HD;
        __half h0 = __float2half_rn(o0), h1 = __float2half_rn(o1);
        qh[base + d]      = h0; ql[base + d]      = __float2half_rn(o0 - __half2float(h0));
        qh[base + d + 64] = h1; ql[base + d + 64] = __float2half_rn(o1 - __half2float(h1));
    }

    const int blk  = ctx_ptrs[b * (QL / BLKSZ) + (t >> 4)];
    const int rrow = t & 15;

    // K: rope, fp16 round, scatter
    for (int idx = tid; idx < NKV * 64; idx += 256) {
        int h = idx >> 6, d = idx & 63;
        float x0 = Kr[h * HD + d];
        float x1 = Kr[h * HD + d + 64];
        float o0 = x0 * crow[d]      - x1 * srow[d];
        float o1 = x1 * crow[d + 64] + x0 * srow[d + 64];
        size_t base = (((size_t)blk * NKV + h) * BLKSZ + rrow) * HD;
        kf[base + d]      = __float2half_rn(o0);
        kf[base + d + 64] = __float2half_rn(o1);
    }

    // V: fp16 round, scatter
    for (int idx = tid; idx < NKV * HD; idx += 256) {
        int h = idx >> 7, d = idx & 127;
        vf[(((size_t)blk * NKV + h) * BLKSZ + rrow) * HD + d] =
            __float2half_rn(Vr[h * HD + d]);
    }
}

// ---------------- flash attention: fp16 2-product HMMA + exp2 online softmax ----------------
// CTA: 128 threads (4 warps), q-tile 64, kv-tile 64.
// smem: Qh, Ql, KV (single) tiles [64][128] fp16, swizzle 16B-chunk ^= (row&7). 48KB.
#define ATT_SMEM2 (3 * 64 * 128 * 2)

__global__ __launch_bounds__(128, 3) void attn_mma(
    const __half* __restrict__ gqh, const __half* __restrict__ gql,
    const __half* __restrict__ gkf, const __half* __restrict__ gvf,
    const int* __restrict__ kvlut, const int* __restrict__ prefix_ptr,
    __half* __restrict__ ohi, __half* __restrict__ olo)
{
    extern __shared__ __align__(16) char dynsm[];
    __half* sQh = (__half*)dynsm;
    __half* sQl = sQh + 64 * 128;
    __half* sKV = sQl + 64 * 128;   // K, then reused for V
    const uint32_t bQh = smem_u32(sQh), bQl = smem_u32(sQl);
    const uint32_t bKV = smem_u32(sKV);

    const int qtile = blockIdx.x, h = blockIdx.y, b = blockIdx.z;
    const int kvh = h >> 2;
    const int prefix = prefix_ptr ? *prefix_ptr : 3072;
    const int tid = threadIdx.x;
    const int warp = tid >> 5, lane = tid & 31;
    const int qr = warp * 16;
    const int q0 = qtile * 64;
    const int* lut = kvlut + b * (SEQ / BLKSZ);

    {
        const __half* srch = gqh + ((size_t)(b * NH + h) * QL + q0) * HD;
        const __half* srcl = gql + ((size_t)(b * NH + h) * QL + q0) * HD;
        for (int i = tid; i < 64 * 16; i += 128) {
            int row = i >> 4, c = i & 15;
            int phys = (c ^ (row & 7)) << 3;
            *(uint4*)&sQh[row * 128 + phys] = *(const uint4*)(srch + (size_t)row * HD + c * 8);
            *(uint4*)&sQl[row * 128 + phys] = *(const uint4*)(srcl + (size_t)row * HD + c * 8);
        }
    }

    float O[16][4];
#pragma unroll
    for (int i = 0; i < 16; i++)
#pragma unroll
        for (int e = 0; e < 4; e++) O[i][e] = 0.f;
    float m0 = -1e30f, m1 = -1e30f, l0 = 0.f, l1 = 0.f;

    const int plim = prefix + q0;
    const int kv_end = plim + 64;
    const int qa0 = plim + qr + (lane >> 2);
    const int qa1 = qa0 + 8;

    for (int s0 = 0; s0 < kv_end; s0 += 64) {
        __syncthreads();   // prior V readers done before overwrite
        for (int i = tid; i < 64 * 16; i += 128) {
            int row = i >> 4, c = i & 15;
            int s = s0 + row;
            int blk = lut[s >> 4];
            size_t base = (((size_t)blk * NKV + kvh) * BLKSZ + (s & 15)) * HD + c * 8;
            int phys = (c ^ (row & 7)) << 3;
            *(uint4*)&sKV[row * 128 + phys] = *(const uint4*)(gkf + base);
        }
        __syncthreads();

        // ---- S = Q K^T, 2-product (Qh + Ql) x K ----
        float S[8][4];
#pragma unroll
        for (int i = 0; i < 8; i++)
#pragma unroll
            for (int e = 0; e < 4; e++) S[i][e] = 0.f;

#pragma unroll
        for (int ks = 0; ks < 8; ks++) {
            uint32_t ah[4], al[4];
            {
                int arow = qr + (lane & 15);
                int ac = ks * 2 + (lane >> 4);
                uint32_t aoff = (uint32_t)(arow * 128 + ((ac ^ (arow & 7)) << 3)) * 2;
                ldsm4(ah, bQh + aoff);
                ldsm4(al, bQl + aoff);
            }
            int brow_b = (lane & 7) + ((lane >> 4) << 3);
            int bc = ks * 2 + ((lane >> 3) & 1);
#pragma unroll
            for (int ng = 0; ng < 4; ng++) {
                int brow = ng * 16 + brow_b;
                uint32_t boff = (uint32_t)(brow * 128 + ((bc ^ (brow & 7)) << 3)) * 2;
                uint32_t kw[4];
                ldsm4(kw, bKV + boff);
                mma_f16(S[2 * ng],     ah, kw[0], kw[1]);
                mma_f16(S[2 * ng],     al, kw[0], kw[1]);
                mma_f16(S[2 * ng + 1], ah, kw[2], kw[3]);
                mma_f16(S[2 * ng + 1], al, kw[2], kw[3]);
            }
        }

        if (s0 + 63 > plim) {
#pragma unroll
            for (int nt = 0; nt < 8; nt++) {
                int colb = s0 + nt * 8 + ((lane & 3) << 1);
                if (colb     > qa0) S[nt][0] = -1e30f;
                if (colb + 1 > qa0) S[nt][1] = -1e30f;
                if (colb     > qa1) S[nt][2] = -1e30f;
                if (colb + 1 > qa1) S[nt][3] = -1e30f;
            }
        }

        float mx0 = -1e30f, mx1 = -1e30f;
#pragma unroll
        for (int nt = 0; nt < 8; nt++) {
            mx0 = fmaxf(mx0, fmaxf(S[nt][0], S[nt][1]));
            mx1 = fmaxf(mx1, fmaxf(S[nt][2], S[nt][3]));
        }
        mx0 = fmaxf(mx0, __shfl_xor_sync(0xffffffffu, mx0, 1));
        mx0 = fmaxf(mx0, __shfl_xor_sync(0xffffffffu, mx0, 2));
        mx1 = fmaxf(mx1, __shfl_xor_sync(0xffffffffu, mx1, 1));
        mx1 = fmaxf(mx1, __shfl_xor_sync(0xffffffffu, mx1, 2));
        float mn0 = fmaxf(m0, mx0), mn1 = fmaxf(m1, mx1);
        float f0 = ex2f(m0 - mn0), f1 = ex2f(m1 - mn1);
        m0 = mn0; m1 = mn1;

        float rs0 = 0.f, rs1 = 0.f;
#pragma unroll
        for (int nt = 0; nt < 8; nt++) {
            S[nt][0] = ex2f(S[nt][0] - mn0); rs0 += S[nt][0];
            S[nt][1] = ex2f(S[nt][1] - mn0); rs0 += S[nt][1];
            S[nt][2] = ex2f(S[nt][2] - mn1); rs1 += S[nt][2];
            S[nt][3] = ex2f(S[nt][3] - mn1); rs1 += S[nt][3];
        }
        rs0 += __shfl_xor_sync(0xffffffffu, rs0, 1);
        rs0 += __shfl_xor_sync(0xffffffffu, rs0, 2);
        rs1 += __shfl_xor_sync(0xffffffffu, rs1, 1);
        rs1 += __shfl_xor_sync(0xffffffffu, rs1, 2);
        l0 = l0 * f0 + rs0;
        l1 = l1 * f1 + rs1;

#pragma unroll
        for (int nt = 0; nt < 16; nt++) {
            O[nt][0] *= f0; O[nt][1] *= f0; O[nt][2] *= f1; O[nt][3] *= f1;
        }

        // ---- split P into fp16 hi/lo A-fragments ----
        uint32_t PH[4][4], PL[4][4];
#pragma unroll
        for (int kt = 0; kt < 4; kt++) {
            int e = 2 * kt, o = 2 * kt + 1;
            float h00 = __half2float(__float2half_rn(S[e][0]));
            float h01 = __half2float(__float2half_rn(S[e][1]));
            float h02 = __half2float(__float2half_rn(S[e][2]));
            float h03 = __half2float(__float2half_rn(S[e][3]));
            float h10 = __half2float(__float2half_rn(S[o][0]));
            float h11 = __half2float(__float2half_rn(S[o][1]));
            float h12 = __half2float(__float2half_rn(S[o][2]));
            float h13 = __half2float(__float2half_rn(S[o][3]));
            PH[kt][0] = packh2(h00, h01);
            PH[kt][1] = packh2(h02, h03);
            PH[kt][2] = packh2(h10, h11);
            PH[kt][3] = packh2(h12, h13);
            PL[kt][0] = packh2(S[e][0] - h00, S[e][1] - h01);
            PL[kt][1] = packh2(S[e][2] - h02, S[e][3] - h03);
            PL[kt][2] = packh2(S[o][0] - h10, S[o][1] - h11);
            PL[kt][3] = packh2(S[o][2] - h12, S[o][3] - h13);
        }

        __syncthreads();   // all warps done reading K smem
        for (int i = tid; i < 64 * 16; i += 128) {
            int row = i >> 4, c = i & 15;
            int s = s0 + row;
            int blk = lut[s >> 4];
            size_t base = (((size_t)blk * NKV + kvh) * BLKSZ + (s & 15)) * HD + c * 8;
            int phys = (c ^ (row & 7)) << 3;
            *(uint4*)&sKV[row * 128 + phys] = *(const uint4*)(gvf + base);
        }
        __syncthreads();

        // ---- O += P V, 2-product (Ph + Pl) x V ----
#pragma unroll
        for (int kt = 0; kt < 4; kt++) {
            int vrow = kt * 16 + (((lane >> 3) & 1) << 3) + (lane & 7);
            int vc0 = lane >> 4;
#pragma unroll
            for (int vg = 0; vg < 8; vg++) {
                int c = vg * 2 + vc0;
                uint32_t off = (uint32_t)(vrow * 128 + ((c ^ (vrow & 7)) << 3)) * 2;
                uint32_t vw[4];
                ldsm4t(vw, bKV + off);
                mma_f16(O[2 * vg],     PH[kt], vw[0], vw[1]);
                mma_f16(O[2 * vg],     PL[kt], vw[0], vw[1]);
                mma_f16(O[2 * vg + 1], PH[kt], vw[2], vw[3]);
                mma_f16(O[2 * vg + 1], PL[kt], vw[2], vw[3]);
            }
        }
    }

    // epilogue: normalize, fp16 hi/lo split, write [b,t,h*128+d]
    float inv0 = 1.f / l0, inv1 = 1.f / l1;
    int r0 = q0 + qr + (lane >> 2);
    int r1 = r0 + 8;
#pragma unroll
    for (int nt = 0; nt < 16; nt++) {
        int d = h * HD + nt * 8 + ((lane & 3) << 1);
        {
            float a = O[nt][0] * inv0, bb = O[nt][1] * inv0;
            float ha = __half2float(__float2half_rn(a));
            float hb = __half2float(__float2half_rn(bb));
            size_t base = (size_t)(b * QL + r0) * HID + d;
            *(uint32_t*)(ohi + base) = packh2(a, bb);
            *(uint32_t*)(olo + base) = packh2(a - ha, bb - hb);
        }
        {
            float a = O[nt][2] * inv1, bb = O[nt][3] * inv1;
            float ha = __half2float(__float2half_rn(a));
            float hb = __half2float(__float2half_rn(bb));
            size_t base = (size_t)(b * QL + r1) * HID + d;
            *(uint32_t*)(ohi + base) = packh2(a, bb);
            *(uint32_t*)(olo + base) = packh2(a - ha, bb - hb);
        }
    }
}

// ---------------- launcher ----------------
extern "C" void kernel_launch(void* const* d_in, const int* in_sizes, int n_in,
                              void* d_out, int out_size)
{
    const float* hidden = (const float*)d_in[0];
    const float* Wq     = (const float*)d_in[1];
    const float* Wk     = (const float*)d_in[2];
    const float* Wv     = (const float*)d_in[3];
    const float* Wo     = (const float*)d_in[4];
    const float* cosp   = (const float*)d_in[5];
    const float* sinp   = (const float*)d_in[6];
    const float* kstore = (const float*)d_in[7];
    const float* vstore = (const float*)d_in[8];
    const int*   kvlut  = (const int*)d_in[9];
    const int*   ctxptr = (const int*)d_in[10];
    const int*   prefix = (n_in >= 12) ? (const int*)d_in[11] : nullptr;
    float* out = (float*)d_out;

    float *qkv;
    __half *xh, *xl, *wf, *qh, *ql, *kf, *vf;
    cudaGetSymbolAddress((void**)&qkv, g_qkv);
    cudaGetSymbolAddress((void**)&xh,  g_xh);
    cudaGetSymbolAddress((void**)&xl,  g_xl);
    cudaGetSymbolAddress((void**)&wf,  g_wf);
    cudaGetSymbolAddress((void**)&qh,  g_qh);
    cudaGetSymbolAddress((void**)&ql,  g_ql);
    cudaGetSymbolAddress((void**)&kf,  g_kf);
    cudaGetSymbolAddress((void**)&vf,  g_vf);

    cudaFuncSetAttribute(attn_mma, cudaFuncAttributeMaxDynamicSharedMemorySize, ATT_SMEM2);

    // activation split + weight rounding
    {
        int n4 = MROWS * HID / 4;
        split2h<<<(n4 + 255) / 256, 256>>>(hidden, xh, xl, n4);
        n4 = (NH * HD) * HID / 4;
        roundh<<<(n4 + 255) / 256, 256>>>(Wq, wf, n4);
        n4 = (NKV * HD) * HID / 4;
        roundh<<<(n4 + 255) / 256, 256>>>(Wk, wf + (size_t)(NH * HD) * HID, n4);
        roundh<<<(n4 + 255) / 256, 256>>>(Wv, wf + (size_t)(NH * HD + NKV * HD) * HID, n4);
        n4 = HID * HID / 4;
        roundh<<<(n4 + 255) / 256, 256>>>(Wo, wf + WOFF_O, n4);
    }
    // KV storage -> single fp16 caches
    {
        int n4 = (int)((size_t)NBLK * NKV * BLKSZ * HD / 4);
        roundh<<<(n4 + 255) / 256, 256>>>(kstore, kf, n4);
        roundh<<<(n4 + 255) / 256, 256>>>(vstore, vf, n4);
    }

    // fused QKV projection (fp16 2-product)
    gemm_f16_2p<<<dim3(QKVN / 128, MROWS / 128), 256>>>(
        xh, xl, wf, qkv, MROWS, QKVN, HID);

    // RoPE + split/round + scatter
    rope_scatter_h<<<MROWS, 256>>>(qkv, cosp, sinp, ctxptr, qh, ql, kf, vf);

    // attention (fp16 2-product; writes fp16 split output into xh/xl)
    attn_mma<<<dim3(QL / 64, NH, BSZ), 128, ATT_SMEM2>>>(
        qh, ql, kf, vf, kvlut, prefix, xh, xl);

    // O projection (fp16 2-product)
    gemm_f16_2p<<<dim3(HID / 128, MROWS / 128), 256>>>(
        xh, xl, wf + WOFF_O, out, MROWS, HID, HID);
}

// round 9
// speedup vs baseline: 5.6892x; 1.2644x over previous
#include <cuda_runtime.h>
#include <cuda_bf16.h>
#include <cuda_fp16.h>
#include <cstdint>

// ---------------- problem dims ----------------
#define BSZ   2
#define QL    1024
#define HID   4096
#define NH    32
#define NKV   8
#define HD    128
#define NBLK  512
#define BLKSZ 16
#define SEQ   4096
#define MROWS (BSZ*QL)                 // 2048
#define QKVN  (NH*HD + 2*NKV*HD)       // 6144
#define WROWS (QKVN + HID)             // 10240
#define WOFF_O ((size_t)QKVN * HID)

// q pre-scale: (1/sqrt(128)) * log2(e)  -> softmax in exp2 domain
#define ASCALE ((float)(0.08838834764831845 * 1.4426950408889634))

// ---------------- device scratch ----------------
__device__ float g_qkv [(size_t)MROWS * QKVN];   // fused QKV projection output
__device__ __half g_xh [(size_t)MROWS * HID];    // activations, single fp16 (reused for attn out)
__device__ __half g_wf [(size_t)WROWS * HID];    // all weights, single fp16
__device__ __half g_qh [(size_t)BSZ * NH * QL * HD];   // Q hi (fp16, pre-scaled)
__device__ __half g_ql [(size_t)BSZ * NH * QL * HD];   // Q lo
__device__ __half g_kf [(size_t)NBLK * NKV * BLKSZ * HD];  // K cache, single fp16
__device__ __half g_vf [(size_t)NBLK * NKV * BLKSZ * HD];  // V cache, single fp16

// ---------------- helpers ----------------
__device__ __forceinline__ uint32_t smem_u32(const void* p) {
    uint32_t a;
    asm("{ .reg .u64 t; cvta.to.shared.u64 t, %1; cvt.u32.u64 %0, t; }" : "=r"(a) : "l"(p));
    return a;
}
__device__ __forceinline__ void ldsm4(uint32_t* r, uint32_t addr) {
    asm volatile("ldmatrix.sync.aligned.m8n8.x4.shared.b16 {%0,%1,%2,%3}, [%4];"
                 : "=r"(r[0]), "=r"(r[1]), "=r"(r[2]), "=r"(r[3]) : "r"(addr));
}
__device__ __forceinline__ void ldsm4t(uint32_t* r, uint32_t addr) {
    asm volatile("ldmatrix.sync.aligned.m8n8.x4.trans.shared.b16 {%0,%1,%2,%3}, [%4];"
                 : "=r"(r[0]), "=r"(r[1]), "=r"(r[2]), "=r"(r[3]) : "r"(addr));
}
__device__ __forceinline__ void mma_f16(float* c, const uint32_t* a, uint32_t b0, uint32_t b1) {
    asm volatile("mma.sync.aligned.m16n8k16.row.col.f32.f16.f16.f32 "
                 "{%0,%1,%2,%3}, {%4,%5,%6,%7}, {%8,%9}, {%0,%1,%2,%3};"
                 : "+f"(c[0]), "+f"(c[1]), "+f"(c[2]), "+f"(c[3])
                 : "r"(a[0]), "r"(a[1]), "r"(a[2]), "r"(a[3]), "r"(b0), "r"(b1));
}
__device__ __forceinline__ float ex2f(float x) {
    float y; asm("ex2.approx.ftz.f32 %0, %1;" : "=f"(y) : "f"(x)); return y;
}
__device__ __forceinline__ uint32_t packh2(float a, float b) {
    __half2 t = __floats2half2_rn(a, b);
    return *(uint32_t*)&t;
}
__device__ __forceinline__ void cpasync16(uint32_t dst, const void* src) {
    asm volatile("cp.async.cg.shared.global [%0], [%1], 16;" :: "r"(dst), "l"(src));
}
#define CP_COMMIT() asm volatile("cp.async.commit_group;" ::: "memory")
#define CP_WAIT1()  asm volatile("cp.async.wait_group 1;" ::: "memory")
#define CP_WAIT0()  asm volatile("cp.async.wait_group 0;" ::: "memory")

// ---------------- fp32 -> fp16 round ----------------
__global__ __launch_bounds__(256) void roundh(const float* __restrict__ x,
                                              __half* __restrict__ y, int n4)
{
    int i = blockIdx.x * 256 + threadIdx.x;
    if (i >= n4) return;
    float4 v = *(const float4*)(x + (size_t)i * 4);
    __half2* yp = (__half2*)(y + (size_t)i * 4);
    yp[0] = __floats2half2_rn(v.x, v.y);
    yp[1] = __floats2half2_rn(v.z, v.w);
}

// ---------------- pipelined fp16 single-product GEMM ----------------
// C[M,N] = A[M,K] * B[N,K]^T, fp32 acc, both single fp16.
// Tile 128x128x32, 8 warps (4M x 2N). Double-buffered cp.async. 32KB smem.
#define TB2 8192                    // one 128x32 fp16 tile
#define BUF1 (2 * TB2)              // A, B

__global__ __launch_bounds__(256) void gemm_f16_1p(
    const __half* __restrict__ Aa, const __half* __restrict__ Bw,
    float* __restrict__ C, int M, int N, int K)
{
    __shared__ __half smem[2][2][128 * 32];   // 32KB

    const int tid  = threadIdx.x;
    const int warp = tid >> 5, lane = tid & 31;
    const int wm = warp & 3, wn = warp >> 2;
    const int bm = blockIdx.y * 128, bn = blockIdx.x * 128;
    const uint32_t sb = smem_u32(smem);

    float acc[2][8][4];
#pragma unroll
    for (int i = 0; i < 2; i++)
#pragma unroll
        for (int j = 0; j < 8; j++)
#pragma unroll
            for (int e = 0; e < 4; e++) acc[i][j][e] = 0.f;

    const __half* g0 = Aa + (size_t)bm * K;
    const __half* g1 = Bw + (size_t)bn * K;

    int rowA = tid >> 2, kcA = tid & 3;
    int rowB = (tid + 256) >> 2, kcB = (tid + 256) & 3;
    uint32_t soffA = (uint32_t)(rowA * 32 + (((kcA + (rowA >> 1)) & 3) * 8)) * 2;
    uint32_t soffB = (uint32_t)(rowB * 32 + (((kcB + (rowB >> 1)) & 3) * 8)) * 2;

    const int nch = K / 32;

#define ISSUE_LOAD(buf, k0)                                                    \
    do {                                                                       \
        size_t gA = (size_t)rowA * K + (k0) + kcA * 8;                         \
        size_t gB = (size_t)rowB * K + (k0) + kcB * 8;                         \
        uint32_t base = sb + (buf) * BUF1;                                     \
        cpasync16(base + 0 * TB2 + soffA, g0 + gA);                            \
        cpasync16(base + 1 * TB2 + soffA, g1 + gA);                            \
        cpasync16(base + 0 * TB2 + soffB, g0 + gB);                            \
        cpasync16(base + 1 * TB2 + soffB, g1 + gB);                            \
        CP_COMMIT();                                                           \
    } while (0)

    ISSUE_LOAD(0, 0);

    for (int ch = 0; ch < nch; ch++) {
        const int buf = ch & 1;
        if (ch + 1 < nch) {
            ISSUE_LOAD(buf ^ 1, (ch + 1) * 32);
            CP_WAIT1();
        } else {
            CP_WAIT0();
        }
        __syncthreads();

        const uint32_t aBs = sb + buf * BUF1;
        const uint32_t bBs = aBs + TB2;

#pragma unroll
        for (int ks = 0; ks < 2; ks++) {
            uint32_t ah[2][4];
            {
                int r  = wm * 32 + (lane & 15);
                int cd = ks * 2 + (lane >> 4);
#pragma unroll
                for (int mt = 0; mt < 2; mt++) {
                    int row  = r + mt * 16;
                    int phys = (cd + (row >> 1)) & 3;
                    uint32_t off = (uint32_t)(row * 32 + phys * 8) * 2;
                    ldsm4(ah[mt], aBs + off);
                }
            }
#pragma unroll
            for (int nt4 = 0; nt4 < 4; nt4++) {
                int n    = wn * 64 + nt4 * 16 + (lane & 7) + ((lane >> 4) << 3);
                int cd   = ks * 2 + ((lane >> 3) & 1);
                int phys = (cd + (n >> 1)) & 3;
                uint32_t off = (uint32_t)(n * 32 + phys * 8) * 2;
                uint32_t bw[4];
                ldsm4(bw, bBs + off);
#pragma unroll
                for (int mt = 0; mt < 2; mt++) {
#pragma unroll
                    for (int p = 0; p < 2; p++) {
                        mma_f16(acc[mt][nt4 * 2 + p], ah[mt], bw[2 * p], bw[2 * p + 1]);
                    }
                }
            }
        }
        __syncthreads();
    }
#undef ISSUE_LOAD

#pragma unroll
    for (int mt = 0; mt < 2; mt++) {
#pragma unroll
        for (int nt = 0; nt < 8; nt++) {
            int row = bm + wm * 32 + mt * 16 + (lane >> 2);
            int col = bn + wn * 64 + nt * 8 + (lane & 3) * 2;
            float* cc = acc[mt][nt];
            *(float2*)&C[(size_t)row * N + col]       = make_float2(cc[0], cc[1]);
            *(float2*)&C[(size_t)(row + 8) * N + col] = make_float2(cc[2], cc[3]);
        }
    }
}

// ---------------- RoPE + fp16 split/round + cache scatter ----------------
__global__ __launch_bounds__(256) void rope_scatter_h(
    const float* __restrict__ QKV,
    const float* __restrict__ cosp, const float* __restrict__ sinp,
    const int* __restrict__ ctx_ptrs,
    __half* __restrict__ qh, __half* __restrict__ ql,
    __half* __restrict__ kf, __half* __restrict__ vf)
{
    const int row = blockIdx.x;          // 0..2047
    const int b = row >> 10, t = row & 1023;
    const int tid = threadIdx.x;
    const float* crow = cosp + (size_t)t * HD;
    const float* srow = sinp + (size_t)t * HD;
    const float* Qr = QKV + (size_t)row * QKVN;
    const float* Kr = Qr + NH * HD;
    const float* Vr = Kr + NKV * HD;

    // Q: rope, scale, fp16 split, store [b,h,t,d]
    for (int idx = tid; idx < NH * 64; idx += 256) {
        int h = idx >> 6, d = idx & 63;
        float x0 = Qr[h * HD + d];
        float x1 = Qr[h * HD + d + 64];
        float o0 = (x0 * crow[d]      - x1 * srow[d])      * ASCALE;
        float o1 = (x1 * crow[d + 64] + x0 * srow[d + 64]) * ASCALE;
        size_t base = ((size_t)(b * NH + h) * QL + t) * HD;
        __half h0 = __float2half_rn(o0), h1 = __float2half_rn(o1);
        qh[base + d]      = h0; ql[base + d]      = __float2half_rn(o0 - __half2float(h0));
        qh[base + d + 64] = h1; ql[base + d + 64] = __float2half_rn(o1 - __half2float(h1));
    }

    const int blk  = ctx_ptrs[b * (QL / BLKSZ) + (t >> 4)];
    const int rrow = t & 15;

    // K: rope, fp16 round, scatter
    for (int idx = tid; idx < NKV * 64; idx += 256) {
        int h = idx >> 6, d = idx & 63;
        float x0 = Kr[h * HD + d];
        float x1 = Kr[h * HD + d + 64];
        float o0 = x0 * crow[d]      - x1 * srow[d];
        float o1 = x1 * crow[d + 64] + x0 * srow[d + 64];
        size_t base = (((size_t)blk * NKV + h) * BLKSZ + rrow) * HD;
        kf[base + d]      = __float2half_rn(o0);
        kf[base + d + 64] = __float2half_rn(o1);
    }

    // V: fp16 round, scatter
    for (int idx = tid; idx < NKV * HD; idx += 256) {
        int h = idx >> 7, d = idx & 127;
        vf[(((size_t)blk * NKV + h) * BLKSZ + rrow) * HD + d] =
            __float2half_rn(Vr[h * HD + d]);
    }
}

// ---------------- flash attention: fp16 HMMA + exp2 online softmax ----------------
// QK: 2-product (Qh+Ql)K; PV: 2-product (Ph+Pl)V.
// CTA: 128 threads (4 warps), q-tile 64, kv-tile 64. smem 48KB.
#define ATT_SMEM2 (3 * 64 * 128 * 2)

__global__ __launch_bounds__(128, 3) void attn_mma(
    const __half* __restrict__ gqh, const __half* __restrict__ gql,
    const __half* __restrict__ gkf, const __half* __restrict__ gvf,
    const int* __restrict__ kvlut, const int* __restrict__ prefix_ptr,
    __half* __restrict__ oh)
{
    extern __shared__ __align__(16) char dynsm[];
    __half* sQh = (__half*)dynsm;
    __half* sQl = sQh + 64 * 128;
    __half* sKV = sQl + 64 * 128;   // K, then reused for V
    const uint32_t bQh = smem_u32(sQh), bQl = smem_u32(sQl);
    const uint32_t bKV = smem_u32(sKV);

    const int qtile = blockIdx.x, h = blockIdx.y, b = blockIdx.z;
    const int kvh = h >> 2;
    const int prefix = prefix_ptr ? *prefix_ptr : 3072;
    const int tid = threadIdx.x;
    const int warp = tid >> 5, lane = tid & 31;
    const int qr = warp * 16;
    const int q0 = qtile * 64;
    const int* lut = kvlut + b * (SEQ / BLKSZ);

    {
        const __half* srch = gqh + ((size_t)(b * NH + h) * QL + q0) * HD;
        const __half* srcl = gql + ((size_t)(b * NH + h) * QL + q0) * HD;
        for (int i = tid; i < 64 * 16; i += 128) {
            int row = i >> 4, c = i & 15;
            int phys = (c ^ (row & 7)) << 3;
            *(uint4*)&sQh[row * 128 + phys] = *(const uint4*)(srch + (size_t)row * HD + c * 8);
            *(uint4*)&sQl[row * 128 + phys] = *(const uint4*)(srcl + (size_t)row * HD + c * 8);
        }
    }

    float O[16][4];
#pragma unroll
    for (int i = 0; i < 16; i++)
#pragma unroll
        for (int e = 0; e < 4; e++) O[i][e] = 0.f;
    float m0 = -1e30f, m1 = -1e30f, l0 = 0.f, l1 = 0.f;

    const int plim = prefix + q0;
    const int kv_end = plim + 64;
    const int qa0 = plim + qr + (lane >> 2);
    const int qa1 = qa0 + 8;

    for (int s0 = 0; s0 < kv_end; s0 += 64) {
        __syncthreads();
        for (int i = tid; i < 64 * 16; i += 128) {
            int row = i >> 4, c = i & 15;
            int s = s0 + row;
            int blk = lut[s >> 4];
            size_t base = (((size_t)blk * NKV + kvh) * BLKSZ + (s & 15)) * HD + c * 8;
            int phys = (c ^ (row & 7)) << 3;
            *(uint4*)&sKV[row * 128 + phys] = *(const uint4*)(gkf + base);
        }
        __syncthreads();

        // ---- S = Q K^T, 2-product (Qh + Ql) x K ----
        float S[8][4];
#pragma unroll
        for (int i = 0; i < 8; i++)
#pragma unroll
            for (int e = 0; e < 4; e++) S[i][e] = 0.f;

#pragma unroll
        for (int ks = 0; ks < 8; ks++) {
            uint32_t ah[4], al[4];
            {
                int arow = qr + (lane & 15);
                int ac = ks * 2 + (lane >> 4);
                uint32_t aoff = (uint32_t)(arow * 128 + ((ac ^ (arow & 7)) << 3)) * 2;
                ldsm4(ah, bQh + aoff);
                ldsm4(al, bQl + aoff);
            }
            int brow_b = (lane & 7) + ((lane >> 4) << 3);
            int bc = ks * 2 + ((lane >> 3) & 1);
#pragma unroll
            for (int ng = 0; ng < 4; ng++) {
                int brow = ng * 16 + brow_b;
                uint32_t boff = (uint32_t)(brow * 128 + ((bc ^ (brow & 7)) << 3)) * 2;
                uint32_t kw[4];
                ldsm4(kw, bKV + boff);
                mma_f16(S[2 * ng],     ah, kw[0], kw[1]);
                mma_f16(S[2 * ng],     al, kw[0], kw[1]);
                mma_f16(S[2 * ng + 1], ah, kw[2], kw[3]);
                mma_f16(S[2 * ng + 1], al, kw[2], kw[3]);
            }
        }

        if (s0 + 63 > plim) {
#pragma unroll
            for (int nt = 0; nt < 8; nt++) {
                int colb = s0 + nt * 8 + ((lane & 3) << 1);
                if (colb     > qa0) S[nt][0] = -1e30f;
                if (colb + 1 > qa0) S[nt][1] = -1e30f;
                if (colb     > qa1) S[nt][2] = -1e30f;
                if (colb + 1 > qa1) S[nt][3] = -1e30f;
            }
        }

        float mx0 = -1e30f, mx1 = -1e30f;
#pragma unroll
        for (int nt = 0; nt < 8; nt++) {
            mx0 = fmaxf(mx0, fmaxf(S[nt][0], S[nt][1]));
            mx1 = fmaxf(mx1, fmaxf(S[nt][2], S[nt][3]));
        }
        mx0 = fmaxf(mx0, __shfl_xor_sync(0xffffffffu, mx0, 1));
        mx0 = fmaxf(mx0, __shfl_xor_sync(0xffffffffu, mx0, 2));
        mx1 = fmaxf(mx1, __shfl_xor_sync(0xffffffffu, mx1, 1));
        mx1 = fmaxf(mx1, __shfl_xor_sync(0xffffffffu, mx1, 2));
        float mn0 = fmaxf(m0, mx0), mn1 = fmaxf(m1, mx1);
        float f0 = ex2f(m0 - mn0), f1 = ex2f(m1 - mn1);
        m0 = mn0; m1 = mn1;

        float rs0 = 0.f, rs1 = 0.f;
#pragma unroll
        for (int nt = 0; nt < 8; nt++) {
            S[nt][0] = ex2f(S[nt][0] - mn0); rs0 += S[nt][0];
            S[nt][1] = ex2f(S[nt][1] - mn0); rs0 += S[nt][1];
            S[nt][2] = ex2f(S[nt][2] - mn1); rs1 += S[nt][2];
            S[nt][3] = ex2f(S[nt][3] - mn1); rs1 += S[nt][3];
        }
        rs0 += __shfl_xor_sync(0xffffffffu, rs0, 1);
        rs0 += __shfl_xor_sync(0xffffffffu, rs0, 2);
        rs1 += __shfl_xor_sync(0xffffffffu, rs1, 1);
        rs1 += __shfl_xor_sync(0xffffffffu, rs1, 2);
        l0 = l0 * f0 + rs0;
        l1 = l1 * f1 + rs1;

#pragma unroll
        for (int nt = 0; nt < 16; nt++) {
            O[nt][0] *= f0; O[nt][1] *= f0; O[nt][2] *= f1; O[nt][3] *= f1;
        }

        // ---- split P into fp16 hi/lo A-fragments ----
        uint32_t PH[4][4], PL[4][4];
#pragma unroll
        for (int kt = 0; kt < 4; kt++) {
            int e = 2 * kt, o = 2 * kt + 1;
            float h00 = __half2float(__float2half_rn(S[e][0]));
            float h01 = __half2float(__float2half_rn(S[e][1]));
            float h02 = __half2float(__float2half_rn(S[e][2]));
            float h03 = __half2float(__float2half_rn(S[e][3]));
            float h10 = __half2float(__float2half_rn(S[o][0]));
            float h11 = __half2float(__float2half_rn(S[o][1]));
            float h12 = __half2float(__float2half_rn(S[o][2]));
            float h13 = __half2float(__float2half_rn(S[o][3]));
            PH[kt][0] = packh2(h00, h01);
            PH[kt][1] = packh2(h02, h03);
            PH[kt][2] = packh2(h10, h11);
            PH[kt][3] = packh2(h12, h13);
            PL[kt][0] = packh2(S[e][0] - h00, S[e][1] - h01);
            PL[kt][1] = packh2(S[e][2] - h02, S[e][3] - h03);
            PL[kt][2] = packh2(S[o][0] - h10, S[o][1] - h11);
            PL[kt][3] = packh2(S[o][2] - h12, S[o][3] - h13);
        }

        __syncthreads();
        for (int i = tid; i < 64 * 16; i += 128) {
            int row = i >> 4, c = i & 15;
            int s = s0 + row;
            int blk = lut[s >> 4];
            size_t base = (((size_t)blk * NKV + kvh) * BLKSZ + (s & 15)) * HD + c * 8;
            int phys = (c ^ (row & 7)) << 3;
            *(uint4*)&sKV[row * 128 + phys] = *(const uint4*)(gvf + base);
        }
        __syncthreads();

        // ---- O += P V, 2-product (Ph + Pl) x V ----
#pragma unroll
        for (int kt = 0; kt < 4; kt++) {
            int vrow = kt * 16 + (((lane >> 3) & 1) << 3) + (lane & 7);
            int vc0 = lane >> 4;
#pragma unroll
            for (int vg = 0; vg < 8; vg++) {
                int c = vg * 2 + vc0;
                uint32_t off = (uint32_t)(vrow * 128 + ((c ^ (vrow & 7)) << 3)) * 2;
                uint32_t vw[4];
                ldsm4t(vw, bKV + off);
                mma_f16(O[2 * vg],     PH[kt], vw[0], vw[1]);
                mma_f16(O[2 * vg],     PL[kt], vw[0], vw[1]);
                mma_f16(O[2 * vg + 1], PH[kt], vw[2], vw[3]);
                mma_f16(O[2 * vg + 1], PL[kt], vw[2], vw[3]);
            }
        }
    }

    // epilogue: normalize, round to fp16, write [b,t,h*128+d]
    float inv0 = 1.f / l0, inv1 = 1.f / l1;
    int r0 = q0 + qr + (lane >> 2);
    int r1 = r0 + 8;
#pragma unroll
    for (int nt = 0; nt < 16; nt++) {
        int d = h * HD + nt * 8 + ((lane & 3) << 1);
        *(uint32_t*)(oh + (size_t)(b * QL + r0) * HID + d) =
            packh2(O[nt][0] * inv0, O[nt][1] * inv0);
        *(uint32_t*)(oh + (size_t)(b * QL + r1) * HID + d) =
            packh2(O[nt][2] * inv1, O[nt][3] * inv1);
    }
}

// ---------------- launcher ----------------
extern "C" void kernel_launch(void* const* d_in, const int* in_sizes, int n_in,
                              void* d_out, int out_size)
{
    const float* hidden = (const float*)d_in[0];
    const float* Wq     = (const float*)d_in[1];
    const float* Wk     = (const float*)d_in[2];
    const float* Wv     = (const float*)d_in[3];
    const float* Wo     = (const float*)d_in[4];
    const float* cosp   = (const float*)d_in[5];
    const float* sinp   = (const float*)d_in[6];
    const float* kstore = (const float*)d_in[7];
    const float* vstore = (const float*)d_in[8];
    const int*   kvlut  = (const int*)d_in[9];
    const int*   ctxptr = (const int*)d_in[10];
    const int*   prefix = (n_in >= 12) ? (const int*)d_in[11] : nullptr;
    float* out = (float*)d_out;

    float *qkv;
    __half *xh, *wf, *qh, *ql, *kf, *vf;
    cudaGetSymbolAddress((void**)&qkv, g_qkv);
    cudaGetSymbolAddress((void**)&xh,  g_xh);
    cudaGetSymbolAddress((void**)&wf,  g_wf);
    cudaGetSymbolAddress((void**)&qh,  g_qh);
    cudaGetSymbolAddress((void**)&ql,  g_ql);
    cudaGetSymbolAddress((void**)&kf,  g_kf);
    cudaGetSymbolAddress((void**)&vf,  g_vf);

    cudaFuncSetAttribute(attn_mma, cudaFuncAttributeMaxDynamicSharedMemorySize, ATT_SMEM2);

    // activation + weight rounding to fp16
    {
        int n4 = MROWS * HID / 4;
        roundh<<<(n4 + 255) / 256, 256>>>(hidden, xh, n4);
        n4 = (NH * HD) * HID / 4;
        roundh<<<(n4 + 255) / 256, 256>>>(Wq, wf, n4);
        n4 = (NKV * HD) * HID / 4;
        roundh<<<(n4 + 255) / 256, 256>>>(Wk, wf + (size_t)(NH * HD) * HID, n4);
        roundh<<<(n4 + 255) / 256, 256>>>(Wv, wf + (size_t)(NH * HD + NKV * HD) * HID, n4);
        n4 = HID * HID / 4;
        roundh<<<(n4 + 255) / 256, 256>>>(Wo, wf + WOFF_O, n4);
    }
    // KV storage -> single fp16 caches
    {
        int n4 = (int)((size_t)NBLK * NKV * BLKSZ * HD / 4);
        roundh<<<(n4 + 255) / 256, 256>>>(kstore, kf, n4);
        roundh<<<(n4 + 255) / 256, 256>>>(vstore, vf, n4);
    }

    // fused QKV projection (fp16 single-product)
    gemm_f16_1p<<<dim3(QKVN / 128, MROWS / 128), 256>>>(
        xh, wf, qkv, MROWS, QKVN, HID);

    // RoPE + split/round + scatter
    rope_scatter_h<<<MROWS, 256>>>(qkv, cosp, sinp, ctxptr, qh, ql, kf, vf);

    // attention (writes fp16 output into xh)
    attn_mma<<<dim3(QL / 64, NH, BSZ), 128, ATT_SMEM2>>>(
        qh, ql, kf, vf, kvlut, prefix, xh);

    // O projection (fp16 single-product)
    gemm_f16_1p<<<dim3(HID / 128, MROWS / 128), 256>>>(
        xh, wf + WOFF_O, out, MROWS, HID, HID);
}

// round 11
// speedup vs baseline: 6.2432x; 1.0974x over previous
#include <cuda_runtime.h>
#include <cuda_bf16.h>
#include <cuda_fp16.h>
#include <cstdint>

// ---------------- problem dims ----------------
#define BSZ   2
#define QL    1024
#define HID   4096
#define NH    32
#define NKV   8
#define HD    128
#define NBLK  512
#define BLKSZ 16
#define SEQ   4096
#define MROWS (BSZ*QL)                 // 2048
#define QKVN  (NH*HD + 2*NKV*HD)       // 6144
#define WROWS (QKVN + HID)             // 10240
#define WOFF_O ((size_t)QKVN * HID)

// q pre-scale: (1/sqrt(128)) * log2(e)  -> softmax in exp2 domain
#define ASCALE ((float)(0.08838834764831845 * 1.4426950408889634))

// ---------------- device scratch ----------------
__device__ float g_qkv [(size_t)MROWS * QKVN];   // fused QKV projection output
__device__ __half g_xh [(size_t)MROWS * HID];    // activations fp16 (reused for attn out)
__device__ __half g_wf [(size_t)WROWS * HID];    // all weights fp16
__device__ __half g_qf [(size_t)BSZ * NH * QL * HD];   // Q fp16 (pre-scaled)
__device__ __half g_kf [(size_t)NBLK * NKV * BLKSZ * HD];  // K cache fp16
__device__ __half g_vf [(size_t)NBLK * NKV * BLKSZ * HD];  // V cache fp16

// ---------------- helpers ----------------
__device__ __forceinline__ uint32_t smem_u32(const void* p) {
    uint32_t a;
    asm("{ .reg .u64 t; cvta.to.shared.u64 t, %1; cvt.u32.u64 %0, t; }" : "=r"(a) : "l"(p));
    return a;
}
__device__ __forceinline__ void ldsm4(uint32_t* r, uint32_t addr) {
    asm volatile("ldmatrix.sync.aligned.m8n8.x4.shared.b16 {%0,%1,%2,%3}, [%4];"
                 : "=r"(r[0]), "=r"(r[1]), "=r"(r[2]), "=r"(r[3]) : "r"(addr));
}
__device__ __forceinline__ void ldsm4t(uint32_t* r, uint32_t addr) {
    asm volatile("ldmatrix.sync.aligned.m8n8.x4.trans.shared.b16 {%0,%1,%2,%3}, [%4];"
                 : "=r"(r[0]), "=r"(r[1]), "=r"(r[2]), "=r"(r[3]) : "r"(addr));
}
__device__ __forceinline__ void mma_f16(float* c, const uint32_t* a, uint32_t b0, uint32_t b1) {
    asm volatile("mma.sync.aligned.m16n8k16.row.col.f32.f16.f16.f32 "
                 "{%0,%1,%2,%3}, {%4,%5,%6,%7}, {%8,%9}, {%0,%1,%2,%3};"
                 : "+f"(c[0]), "+f"(c[1]), "+f"(c[2]), "+f"(c[3])
                 : "r"(a[0]), "r"(a[1]), "r"(a[2]), "r"(a[3]), "r"(b0), "r"(b1));
}
__device__ __forceinline__ float ex2f(float x) {
    float y; asm("ex2.approx.ftz.f32 %0, %1;" : "=f"(y) : "f"(x)); return y;
}
__device__ __forceinline__ uint32_t packh2(float a, float b) {
    __half2 t = __floats2half2_rn(a, b);
    return *(uint32_t*)&t;
}
__device__ __forceinline__ void cpasync16(uint32_t dst, const void* src) {
    asm volatile("cp.async.cg.shared.global [%0], [%1], 16;" :: "r"(dst), "l"(src));
}
#define CP_COMMIT() asm volatile("cp.async.commit_group;" ::: "memory")
#define CP_WAIT1()  asm volatile("cp.async.wait_group 1;" ::: "memory")
#define CP_WAIT0()  asm volatile("cp.async.wait_group 0;" ::: "memory")

// ---------------- fp32 -> fp16 round ----------------
__global__ __launch_bounds__(256) void roundh(const float* __restrict__ x,
                                              __half* __restrict__ y, int n4)
{
    int i = blockIdx.x * 256 + threadIdx.x;
    if (i >= n4) return;
    float4 v = *(const float4*)(x + (size_t)i * 4);
    __half2* yp = (__half2*)(y + (size_t)i * 4);
    yp[0] = __floats2half2_rn(v.x, v.y);
    yp[1] = __floats2half2_rn(v.z, v.w);
}

// ---------------- pipelined fp16 single-product GEMM (unchanged from R9) ----------------
#define TB2 8192                    // one 128x32 fp16 tile
#define BUF1 (2 * TB2)              // A, B

__global__ __launch_bounds__(256) void gemm_f16_1p(
    const __half* __restrict__ Aa, const __half* __restrict__ Bw,
    float* __restrict__ C, int M, int N, int K)
{
    __shared__ __half smem[2][2][128 * 32];   // 32KB

    const int tid  = threadIdx.x;
    const int warp = tid >> 5, lane = tid & 31;
    const int wm = warp & 3, wn = warp >> 2;
    const int bm = blockIdx.y * 128, bn = blockIdx.x * 128;
    const uint32_t sb = smem_u32(smem);

    float acc[2][8][4];
#pragma unroll
    for (int i = 0; i < 2; i++)
#pragma unroll
        for (int j = 0; j < 8; j++)
#pragma unroll
            for (int e = 0; e < 4; e++) acc[i][j][e] = 0.f;

    const __half* g0 = Aa + (size_t)bm * K;
    const __half* g1 = Bw + (size_t)bn * K;

    int rowA = tid >> 2, kcA = tid & 3;
    int rowB = (tid + 256) >> 2, kcB = (tid + 256) & 3;
    uint32_t soffA = (uint32_t)(rowA * 32 + (((kcA + (rowA >> 1)) & 3) * 8)) * 2;
    uint32_t soffB = (uint32_t)(rowB * 32 + (((kcB + (rowB >> 1)) & 3) * 8)) * 2;

    const int nch = K / 32;

#define ISSUE_LOAD(buf, k0)                                                    \
    do {                                                                       \
        size_t gA = (size_t)rowA * K + (k0) + kcA * 8;                         \
        size_t gB = (size_t)rowB * K + (k0) + kcB * 8;                         \
        uint32_t base = sb + (buf) * BUF1;                                     \
        cpasync16(base + 0 * TB2 + soffA, g0 + gA);                            \
        cpasync16(base + 1 * TB2 + soffA, g1 + gA);                            \
        cpasync16(base + 0 * TB2 + soffB, g0 + gB);                            \
        cpasync16(base + 1 * TB2 + soffB, g1 + gB);                            \
        CP_COMMIT();                                                           \
    } while (0)

    ISSUE_LOAD(0, 0);

    for (int ch = 0; ch < nch; ch++) {
        const int buf = ch & 1;
        if (ch + 1 < nch) {
            ISSUE_LOAD(buf ^ 1, (ch + 1) * 32);
            CP_WAIT1();
        } else {
            CP_WAIT0();
        }
        __syncthreads();

        const uint32_t aBs = sb + buf * BUF1;
        const uint32_t bBs = aBs + TB2;

#pragma unroll
        for (int ks = 0; ks < 2; ks++) {
            uint32_t ah[2][4];
            {
                int r  = wm * 32 + (lane & 15);
                int cd = ks * 2 + (lane >> 4);
#pragma unroll
                for (int mt = 0; mt < 2; mt++) {
                    int row  = r + mt * 16;
                    int phys = (cd + (row >> 1)) & 3;
                    uint32_t off = (uint32_t)(row * 32 + phys * 8) * 2;
                    ldsm4(ah[mt], aBs + off);
                }
            }
#pragma unroll
            for (int nt4 = 0; nt4 < 4; nt4++) {
                int n    = wn * 64 + nt4 * 16 + (lane & 7) + ((lane >> 4) << 3);
                int cd   = ks * 2 + ((lane >> 3) & 1);
                int phys = (cd + (n >> 1)) & 3;
                uint32_t off = (uint32_t)(n * 32 + phys * 8) * 2;
                uint32_t bw[4];
                ldsm4(bw, bBs + off);
#pragma unroll
                for (int mt = 0; mt < 2; mt++) {
#pragma unroll
                    for (int p = 0; p < 2; p++) {
                        mma_f16(acc[mt][nt4 * 2 + p], ah[mt], bw[2 * p], bw[2 * p + 1]);
                    }
                }
            }
        }
        __syncthreads();
    }
#undef ISSUE_LOAD

#pragma unroll
    for (int mt = 0; mt < 2; mt++) {
#pragma unroll
        for (int nt = 0; nt < 8; nt++) {
            int row = bm + wm * 32 + mt * 16 + (lane >> 2);
            int col = bn + wn * 64 + nt * 8 + (lane & 3) * 2;
            float* cc = acc[mt][nt];
            *(float2*)&C[(size_t)row * N + col]       = make_float2(cc[0], cc[1]);
            *(float2*)&C[(size_t)(row + 8) * N + col] = make_float2(cc[2], cc[3]);
        }
    }
}

// ---------------- RoPE + fp16 round + cache scatter ----------------
__global__ __launch_bounds__(256) void rope_scatter_h(
    const float* __restrict__ QKV,
    const float* __restrict__ cosp, const float* __restrict__ sinp,
    const int* __restrict__ ctx_ptrs,
    __half* __restrict__ qf,
    __half* __restrict__ kf, __half* __restrict__ vf)
{
    const int row = blockIdx.x;          // 0..2047
    const int b = row >> 10, t = row & 1023;
    const int tid = threadIdx.x;
    const float* crow = cosp + (size_t)t * HD;
    const float* srow = sinp + (size_t)t * HD;
    const float* Qr = QKV + (size_t)row * QKVN;
    const float* Kr = Qr + NH * HD;
    const float* Vr = Kr + NKV * HD;

    // Q: rope, scale, fp16 round, store [b,h,t,d]
    for (int idx = tid; idx < NH * 64; idx += 256) {
        int h = idx >> 6, d = idx & 63;
        float x0 = Qr[h * HD + d];
        float x1 = Qr[h * HD + d + 64];
        float o0 = (x0 * crow[d]      - x1 * srow[d])      * ASCALE;
        float o1 = (x1 * crow[d + 64] + x0 * srow[d + 64]) * ASCALE;
        size_t base = ((size_t)(b * NH + h) * QL + t) * HD;
        qf[base + d]      = __float2half_rn(o0);
        qf[base + d + 64] = __float2half_rn(o1);
    }

    const int blk  = ctx_ptrs[b * (QL / BLKSZ) + (t >> 4)];
    const int rrow = t & 15;

    // K: rope, fp16 round, scatter
    for (int idx = tid; idx < NKV * 64; idx += 256) {
        int h = idx >> 6, d = idx & 63;
        float x0 = Kr[h * HD + d];
        float x1 = Kr[h * HD + d + 64];
        float o0 = x0 * crow[d]      - x1 * srow[d];
        float o1 = x1 * crow[d + 64] + x0 * srow[d + 64];
        size_t base = (((size_t)blk * NKV + h) * BLKSZ + rrow) * HD;
        kf[base + d]      = __float2half_rn(o0);
        kf[base + d + 64] = __float2half_rn(o1);
    }

    // V: fp16 round, scatter
    for (int idx = tid; idx < NKV * HD; idx += 256) {
        int h = idx >> 7, d = idx & 127;
        vf[(((size_t)blk * NKV + h) * BLKSZ + rrow) * HD + d] =
            __float2half_rn(Vr[h * HD + d]);
    }
}

// ---------------- flash attention: single-product fp16 HMMA + exp2 softmax ----------------
// CTA: 128 threads (4 warps), q-tile 64, kv-tile 64. smem: Q + KV = 32KB.
#define ATT_SMEM2 (2 * 64 * 128 * 2)

__global__ __launch_bounds__(128, 3) void attn_mma(
    const __half* __restrict__ gqf,
    const __half* __restrict__ gkf, const __half* __restrict__ gvf,
    const int* __restrict__ kvlut, const int* __restrict__ prefix_ptr,
    __half* __restrict__ oh)
{
    extern __shared__ __align__(16) char dynsm[];
    __half* sQ  = (__half*)dynsm;
    __half* sKV = sQ + 64 * 128;    // K, then reused for V
    const uint32_t bQ = smem_u32(sQ), bKV = smem_u32(sKV);

    const int qtile = blockIdx.x, h = blockIdx.y, b = blockIdx.z;
    const int kvh = h >> 2;
    const int prefix = prefix_ptr ? *prefix_ptr : 3072;
    const int tid = threadIdx.x;
    const int warp = tid >> 5, lane = tid & 31;
    const int qr = warp * 16;
    const int q0 = qtile * 64;
    const int* lut = kvlut + b * (SEQ / BLKSZ);

    {
        const __half* src = gqf + ((size_t)(b * NH + h) * QL + q0) * HD;
        for (int i = tid; i < 64 * 16; i += 128) {
            int row = i >> 4, c = i & 15;
            int phys = (c ^ (row & 7)) << 3;
            *(uint4*)&sQ[row * 128 + phys] = *(const uint4*)(src + (size_t)row * HD + c * 8);
        }
    }

    float O[16][4];
#pragma unroll
    for (int i = 0; i < 16; i++)
#pragma unroll
        for (int e = 0; e < 4; e++) O[i][e] = 0.f;
    float m0 = -1e30f, m1 = -1e30f, l0 = 0.f, l1 = 0.f;

    const int plim = prefix + q0;
    const int kv_end = plim + 64;
    const int qa0 = plim + qr + (lane >> 2);
    const int qa1 = qa0 + 8;

    for (int s0 = 0; s0 < kv_end; s0 += 64) {
        __syncthreads();
        for (int i = tid; i < 64 * 16; i += 128) {
            int row = i >> 4, c = i & 15;
            int s = s0 + row;
            int blk = lut[s >> 4];
            size_t base = (((size_t)blk * NKV + kvh) * BLKSZ + (s & 15)) * HD + c * 8;
            int phys = (c ^ (row & 7)) << 3;
            *(uint4*)&sKV[row * 128 + phys] = *(const uint4*)(gkf + base);
        }
        __syncthreads();

        // ---- S = Q K^T (single product) ----
        float S[8][4];
#pragma unroll
        for (int i = 0; i < 8; i++)
#pragma unroll
            for (int e = 0; e < 4; e++) S[i][e] = 0.f;

#pragma unroll
        for (int ks = 0; ks < 8; ks++) {
            uint32_t aq[4];
            {
                int arow = qr + (lane & 15);
                int ac = ks * 2 + (lane >> 4);
                uint32_t aoff = (uint32_t)(arow * 128 + ((ac ^ (arow & 7)) << 3)) * 2;
                ldsm4(aq, bQ + aoff);
            }
            int brow_b = (lane & 7) + ((lane >> 4) << 3);
            int bc = ks * 2 + ((lane >> 3) & 1);
#pragma unroll
            for (int ng = 0; ng < 4; ng++) {
                int brow = ng * 16 + brow_b;
                uint32_t boff = (uint32_t)(brow * 128 + ((bc ^ (brow & 7)) << 3)) * 2;
                uint32_t kw[4];
                ldsm4(kw, bKV + boff);
                mma_f16(S[2 * ng],     aq, kw[0], kw[1]);
                mma_f16(S[2 * ng + 1], aq, kw[2], kw[3]);
            }
        }

        if (s0 + 63 > plim) {
#pragma unroll
            for (int nt = 0; nt < 8; nt++) {
                int colb = s0 + nt * 8 + ((lane & 3) << 1);
                if (colb     > qa0) S[nt][0] = -1e30f;
                if (colb + 1 > qa0) S[nt][1] = -1e30f;
                if (colb     > qa1) S[nt][2] = -1e30f;
                if (colb + 1 > qa1) S[nt][3] = -1e30f;
            }
        }

        float mx0 = -1e30f, mx1 = -1e30f;
#pragma unroll
        for (int nt = 0; nt < 8; nt++) {
            mx0 = fmaxf(mx0, fmaxf(S[nt][0], S[nt][1]));
            mx1 = fmaxf(mx1, fmaxf(S[nt][2], S[nt][3]));
        }
        mx0 = fmaxf(mx0, __shfl_xor_sync(0xffffffffu, mx0, 1));
        mx0 = fmaxf(mx0, __shfl_xor_sync(0xffffffffu, mx0, 2));
        mx1 = fmaxf(mx1, __shfl_xor_sync(0xffffffffu, mx1, 1));
        mx1 = fmaxf(mx1, __shfl_xor_sync(0xffffffffu, mx1, 2));
        float mn0 = fmaxf(m0, mx0), mn1 = fmaxf(m1, mx1);
        float f0 = ex2f(m0 - mn0), f1 = ex2f(m1 - mn1);
        m0 = mn0; m1 = mn1;

        float rs0 = 0.f, rs1 = 0.f;
#pragma unroll
        for (int nt = 0; nt < 8; nt++) {
            S[nt][0] = ex2f(S[nt][0] - mn0); rs0 += S[nt][0];
            S[nt][1] = ex2f(S[nt][1] - mn0); rs0 += S[nt][1];
            S[nt][2] = ex2f(S[nt][2] - mn1); rs1 += S[nt][2];
            S[nt][3] = ex2f(S[nt][3] - mn1); rs1 += S[nt][3];
        }
        rs0 += __shfl_xor_sync(0xffffffffu, rs0, 1);
        rs0 += __shfl_xor_sync(0xffffffffu, rs0, 2);
        rs1 += __shfl_xor_sync(0xffffffffu, rs1, 1);
        rs1 += __shfl_xor_sync(0xffffffffu, rs1, 2);
        l0 = l0 * f0 + rs0;
        l1 = l1 * f1 + rs1;

#pragma unroll
        for (int nt = 0; nt < 16; nt++) {
            O[nt][0] *= f0; O[nt][1] *= f0; O[nt][2] *= f1; O[nt][3] *= f1;
        }

        // ---- pack P (single fp16) ----
        uint32_t PH[4][4];
#pragma unroll
        for (int kt = 0; kt < 4; kt++) {
            int e = 2 * kt, o = 2 * kt + 1;
            PH[kt][0] = packh2(S[e][0], S[e][1]);
            PH[kt][1] = packh2(S[e][2], S[e][3]);
            PH[kt][2] = packh2(S[o][0], S[o][1]);
            PH[kt][3] = packh2(S[o][2], S[o][3]);
        }

        __syncthreads();
        for (int i = tid; i < 64 * 16; i += 128) {
            int row = i >> 4, c = i & 15;
            int s = s0 + row;
            int blk = lut[s >> 4];
            size_t base = (((size_t)blk * NKV + kvh) * BLKSZ + (s & 15)) * HD + c * 8;
            int phys = (c ^ (row & 7)) << 3;
            *(uint4*)&sKV[row * 128 + phys] = *(const uint4*)(gvf + base);
        }
        __syncthreads();

        // ---- O += P V (single product) ----
#pragma unroll
        for (int kt = 0; kt < 4; kt++) {
            int vrow = kt * 16 + (((lane >> 3) & 1) << 3) + (lane & 7);
            int vc0 = lane >> 4;
#pragma unroll
            for (int vg = 0; vg < 8; vg++) {
                int c = vg * 2 + vc0;
                uint32_t off = (uint32_t)(vrow * 128 + ((c ^ (vrow & 7)) << 3)) * 2;
                uint32_t vw[4];
                ldsm4t(vw, bKV + off);
                mma_f16(O[2 * vg],     PH[kt], vw[0], vw[1]);
                mma_f16(O[2 * vg + 1], PH[kt], vw[2], vw[3]);
            }
        }
    }

    // epilogue: normalize, round to fp16, write [b,t,h*128+d]
    float inv0 = 1.f / l0, inv1 = 1.f / l1;
    int r0 = q0 + qr + (lane >> 2);
    int r1 = r0 + 8;
#pragma unroll
    for (int nt = 0; nt < 16; nt++) {
        int d = h * HD + nt * 8 + ((lane & 3) << 1);
        *(uint32_t*)(oh + (size_t)(b * QL + r0) * HID + d) =
            packh2(O[nt][0] * inv0, O[nt][1] * inv0);
        *(uint32_t*)(oh + (size_t)(b * QL + r1) * HID + d) =
            packh2(O[nt][2] * inv1, O[nt][3] * inv1);
    }
}

// ---------------- launcher ----------------
extern "C" void kernel_launch(void* const* d_in, const int* in_sizes, int n_in,
                              void* d_out, int out_size)
{
    const float* hidden = (const float*)d_in[0];
    const float* Wq     = (const float*)d_in[1];
    const float* Wk     = (const float*)d_in[2];
    const float* Wv     = (const float*)d_in[3];
    const float* Wo     = (const float*)d_in[4];
    const float* cosp   = (const float*)d_in[5];
    const float* sinp   = (const float*)d_in[6];
    const float* kstore = (const float*)d_in[7];
    const float* vstore = (const float*)d_in[8];
    const int*   kvlut  = (const int*)d_in[9];
    const int*   ctxptr = (const int*)d_in[10];
    const int*   prefix = (n_in >= 12) ? (const int*)d_in[11] : nullptr;
    float* out = (float*)d_out;

    float *qkv;
    __half *xh, *wf, *qf, *kf, *vf;
    cudaGetSymbolAddress((void**)&qkv, g_qkv);
    cudaGetSymbolAddress((void**)&xh,  g_xh);
    cudaGetSymbolAddress((void**)&wf,  g_wf);
    cudaGetSymbolAddress((void**)&qf,  g_qf);
    cudaGetSymbolAddress((void**)&kf,  g_kf);
    cudaGetSymbolAddress((void**)&vf,  g_vf);

    cudaFuncSetAttribute(attn_mma, cudaFuncAttributeMaxDynamicSharedMemorySize, ATT_SMEM2);

    // activation + weight rounding to fp16
    {
        int n4 = MROWS * HID / 4;
        roundh<<<(n4 + 255) / 256, 256>>>(hidden, xh, n4);
        n4 = (NH * HD) * HID / 4;
        roundh<<<(n4 + 255) / 256, 256>>>(Wq, wf, n4);
        n4 = (NKV * HD) * HID / 4;
        roundh<<<(n4 + 255) / 256, 256>>>(Wk, wf + (size_t)(NH * HD) * HID, n4);
        roundh<<<(n4 + 255) / 256, 256>>>(Wv, wf + (size_t)(NH * HD + NKV * HD) * HID, n4);
        n4 = HID * HID / 4;
        roundh<<<(n4 + 255) / 256, 256>>>(Wo, wf + WOFF_O, n4);
    }
    // KV storage -> fp16 caches
    {
        int n4 = (int)((size_t)NBLK * NKV * BLKSZ * HD / 4);
        roundh<<<(n4 + 255) / 256, 256>>>(kstore, kf, n4);
        roundh<<<(n4 + 255) / 256, 256>>>(vstore, vf, n4);
    }

    // fused QKV projection
    gemm_f16_1p<<<dim3(QKVN / 128, MROWS / 128), 256>>>(
        xh, wf, qkv, MROWS, QKVN, HID);

    // RoPE + round + scatter
    rope_scatter_h<<<MROWS, 256>>>(qkv, cosp, sinp, ctxptr, qf, kf, vf);

    // attention (writes fp16 output into xh)
    attn_mma<<<dim3(QL / 64, NH, BSZ), 128, ATT_SMEM2>>>(
        qf, kf, vf, kvlut, prefix, xh);

    // O projection
    gemm_f16_1p<<<dim3(HID / 128, MROWS / 128), 256>>>(
        xh, wf + WOFF_O, out, MROWS, HID, HID);
}